// round 12
// baseline (speedup 1.0000x reference)
#include <cuda_runtime.h>
#include <cuda_bf16.h>
#include <cstdint>

#define BB 64
#define SS 64
#define DIN 512
#define DATTN 512
#define DMODEL 2048
#define MM 25
#define MP 32
#define HEADS 8
#define HD 64
#define NSYNC 512
#define OUT_N 1000
#define OUT_P 1024
#define TT 50
#define DPRE 2560
#define D2 4096
#define HSPLIT 6

#define PRED_SZ (BB*OUT_N*TT)
#define CERT_OFF (PRED_SZ)
#define SYO_OFF (PRED_SZ + BB*2*TT)

// ---------- scratch ----------
__device__ float g_kv[BB*SS*DATTN];
__device__ float g_Kt[BB*HEADS*HD*SS];
__device__ float g_V [BB*HEADS*SS*HD];
__device__ float g_Wqpq[NSYNC*DATTN];
__device__ float g_WbigTop[DATTN*D2];
__device__ float g_bq2[DATTN];
__device__ float g_bs1c[D2];
__device__ float g_act[BB*DMODEL];
__device__ float g_trace[BB*DMODEL*MP];
__device__ float g_aA[BB*NSYNC], g_bA[BB*NSYNC], g_syA[BB*NSYNC];
__device__ float g_aO[BB*NSYNC], g_bO[BB*NSYNC], g_syO[BB*NSYNC];
__device__ float g_hpart[HSPLIT*BB*D2];
__device__ float g_ppart[4*BB*OUT_P];
// packed bf16 hi/lo
__device__ uint32_t g_xp_h[(BB*SS)*(DIN/2)],  g_xp_l[(BB*SS)*(DIN/2)];
__device__ uint32_t g_Wf_h[(DIN/2)*DATTN],  g_Wf_l[(DIN/2)*DATTN];
__device__ uint32_t g_Wk_h[(DATTN/2)*DATTN], g_Wk_l[(DATTN/2)*DATTN];
__device__ uint32_t g_Wv_h[(DATTN/2)*DATTN], g_Wv_l[(DATTN/2)*DATTN];
__device__ uint32_t g_Wq_h[(DATTN/2)*DATTN], g_Wq_l[(DATTN/2)*DATTN];
__device__ uint32_t g_WqpA_h[NSYNC*(DATTN/2)], g_WqpA_l[NSYNC*(DATTN/2)];
__device__ uint32_t g_WoA_h[DATTN*(DATTN/2)], g_WoA_l[DATTN*(DATTN/2)];
__device__ uint32_t g_Ws1t_h[(DATTN/2)*D2], g_Ws1t_l[(DATTN/2)*D2];
__device__ uint32_t g_Wbig_h[(DPRE/2)*D2], g_Wbig_l[(DPRE/2)*D2];
__device__ uint32_t g_WoutP_h[(NSYNC/2)*OUT_P], g_WoutP_l[(NSYNC/2)*OUT_P];
__device__ uint32_t g_pA_h[BB*(DPRE/2)], g_pA_l[BB*(DPRE/2)];
__device__ uint32_t g_syO_h[BB*(NSYNC/2)], g_syO_l[BB*(NSYNC/2)];

// ---------- helpers ----------
__device__ __forceinline__ uint32_t bfpair(float a, float b){
    __nv_bfloat162 t = __floats2bfloat162_rn(a, b);
    return *reinterpret_cast<uint32_t*>(&t);
}
__device__ __forceinline__ void split2(float v0, float v1, uint32_t& hi, uint32_t& lo){
    float h0 = __bfloat162float(__float2bfloat16(v0));
    float h1 = __bfloat162float(__float2bfloat16(v1));
    hi = bfpair(h0, h1);
    lo = bfpair(v0 - h0, v1 - h1);
}
__device__ __forceinline__ void mma16816(float* c, uint32_t a0, uint32_t a1,
                                         uint32_t a2, uint32_t a3, uint32_t b0, uint32_t b1){
    asm volatile("mma.sync.aligned.m16n8k16.row.col.f32.bf16.bf16.f32 "
        "{%0,%1,%2,%3},{%4,%5,%6,%7},{%8,%9},{%0,%1,%2,%3};"
        : "+f"(c[0]), "+f"(c[1]), "+f"(c[2]), "+f"(c[3])
        : "r"(a0), "r"(a1), "r"(a2), "r"(a3), "r"(b0), "r"(b1));
}
__device__ __forceinline__ float gelu_f(float x){
    float z = 0.7978845608028654f * (x + 0.044715f * x*x*x);
    float ee = __expf(-2.f * fabsf(z));
    float th = copysignf((1.f - ee) / (1.f + ee), z);
    return 0.5f * x * (1.f + th);
}
__device__ __forceinline__ void packA_elem(const float* __restrict__ src,
                                           uint32_t* __restrict__ h, uint32_t* __restrict__ l,
                                           int idx, int K){
    const int Kh = K >> 1;
    const int m = idx / Kh, kp = idx - m * Kh;
    split2(src[(size_t)m*K + 2*kp], src[(size_t)m*K + 2*kp + 1], h[idx], l[idx]);
}
__device__ __forceinline__ void packW_elem(const float* __restrict__ src,
                                           uint32_t* __restrict__ h, uint32_t* __restrict__ l,
                                           int idx, int N){
    const int kp = idx / N, n = idx - kp * N;
    split2(src[(size_t)(2*kp)*N + n], src[(size_t)(2*kp+1)*N + n], h[idx], l[idx]);
}
__device__ __forceinline__ void packWpad_elem(const float* __restrict__ src,
                                              uint32_t* __restrict__ h, uint32_t* __restrict__ l,
                                              int idx, int Ns, int Nd){
    const int kp = idx / Nd, n = idx - kp * Nd;
    const float v0 = (n < Ns) ? src[(size_t)(2*kp)*Ns + n] : 0.f;
    const float v1 = (n < Ns) ? src[(size_t)(2*kp+1)*Ns + n] : 0.f;
    split2(v0, v1, h[idx], l[idx]);
}

// ---------- setup GEMM core ----------
__device__ void gemm_dev(const uint32_t* __restrict__ Ah, const uint32_t* __restrict__ Al,
                         const uint32_t* __restrict__ Wh, const uint32_t* __restrict__ Wl,
                         float* __restrict__ C, const float* __restrict__ bias,
                         int N, int K, int epi, int bx, int by, uint32_t* smem, const float* Af32)
{
    uint32_t* sAh = smem;
    uint32_t* sAl = sAh + 2304;
    uint32_t* sBh = sAl + 2304;
    uint32_t* sBl = sBh + 1152;
    const int tid = threadIdx.x;
    const int nBase = bx * 64, rowBase = by * 64;
    const int Kh = K >> 1;
    const int warp = tid >> 5, lane = tid & 31;
    const int wm = (warp & 3) * 16, wn = (warp >> 2) * 32;
    const int g = lane >> 2, tg = lane & 3;
    float acc[4][4];
#pragma unroll
    for (int t = 0; t < 4; t++){ acc[t][0]=acc[t][1]=acc[t][2]=acc[t][3]=0.f; }

    for (int kk = 0; kk < K; kk += 32){
        const int kpg = kk >> 1;
#pragma unroll
        for (int i = 0; i < 4; i++){
            int idx = tid + i * 256;
            int m = idx >> 4, kp = idx & 15;
            if (Af32){
                const float2 av = *reinterpret_cast<const float2*>(
                    &Af32[(size_t)(rowBase + m) * K + (kpg + kp) * 2]);
                split2(av.x, av.y, sAh[m*36+kp], sAl[m*36+kp]);
            } else {
                sAh[m*36+kp] = Ah[(size_t)(rowBase + m) * Kh + kpg + kp];
                sAl[m*36+kp] = Al[(size_t)(rowBase + m) * Kh + kpg + kp];
            }
            int kb = idx >> 6, n = idx & 63;
            sBh[kb*72+n] = Wh[(size_t)(kpg + kb) * N + nBase + n];
            sBl[kb*72+n] = Wl[(size_t)(kpg + kb) * N + nBase + n];
        }
        __syncthreads();
#pragma unroll
        for (int s = 0; s < 2; s++){
            const int kb = s * 8;
            uint32_t ah0 = sAh[(wm+g)*36+kb+tg],   ah1 = sAh[(wm+8+g)*36+kb+tg];
            uint32_t ah2 = sAh[(wm+g)*36+kb+4+tg], ah3 = sAh[(wm+8+g)*36+kb+4+tg];
            uint32_t al0 = sAl[(wm+g)*36+kb+tg],   al1 = sAl[(wm+8+g)*36+kb+tg];
            uint32_t al2 = sAl[(wm+g)*36+kb+4+tg], al3 = sAl[(wm+8+g)*36+kb+4+tg];
#pragma unroll
            for (int t = 0; t < 4; t++){
                const int n = wn + t * 8 + g;
                uint32_t bh0 = sBh[(kb+tg)*72+n], bh1 = sBh[(kb+4+tg)*72+n];
                uint32_t bl0 = sBl[(kb+tg)*72+n], bl1 = sBl[(kb+4+tg)*72+n];
                mma16816(acc[t], ah0, ah1, ah2, ah3, bh0, bh1);
                mma16816(acc[t], ah0, ah1, ah2, ah3, bl0, bl1);
                mma16816(acc[t], al0, al1, al2, al3, bh0, bh1);
            }
        }
        __syncthreads();
    }
    const int r0 = rowBase + wm + g;
#pragma unroll
    for (int t = 0; t < 4; t++){
        const int c = nBase + wn + t * 8 + tg * 2;
#pragma unroll
        for (int hr = 0; hr < 2; hr++){
            const int r = r0 + hr * 8;
            const float v0 = acc[t][hr*2+0], v1 = acc[t][hr*2+1];
            if (epi == 0){
                C[(size_t)r*N + c]   = v0 + (bias ? bias[c]   : 0.f);
                C[(size_t)r*N + c+1] = v1 + (bias ? bias[c+1] : 0.f);
            } else if (epi == 1){
                const int b = r >> 6, srow = r & 63, h = c >> 6, d = c & 63;
                C[((b*HEADS+h)*HD + d  )*SS + srow] = v0 + bias[c];
                C[((b*HEADS+h)*HD + d+1)*SS + srow] = v1 + bias[c+1];
            } else {
                const int b = r >> 6, srow = r & 63, h = c >> 6, d = c & 63;
                C[((b*HEADS+h)*SS + srow)*HD + d  ] = v0 + bias[c];
                C[((b*HEADS+h)*SS + srow)*HD + d+1] = v1 + bias[c+1];
            }
        }
    }
}

// ---------- setup kernels ----------
__global__ void setup_a(const float* __restrict__ x,  const float* __restrict__ Wf,
                        const float* __restrict__ Wk, const float* __restrict__ Wv,
                        const float* __restrict__ Wq, const float* __restrict__ Wqp,
                        const float* __restrict__ Wo, const float* __restrict__ Ws1,
                        const float* __restrict__ Wout,
                        const float* __restrict__ bqp, const float* __restrict__ bq,
                        const float* __restrict__ bo,  const float* __restrict__ bs1,
                        const float* __restrict__ start_trace, const float* __restrict__ start_state,
                        const int* __restrict__ idx_lo, const int* __restrict__ idx_ro)
{
    int blk = blockIdx.x;
    const int tid = threadIdx.x;
    if (blk < 64){
        const int col = blk*8 + (tid >> 5), lane = tid & 31;
        float acc = 0.f;
#pragma unroll 16
        for (int i = 0; i < 16; i++){
            const int k = lane + i*32;
            acc += bqp[k] * Wq[(size_t)k*DATTN + col];
        }
#pragma unroll
        for (int off = 16; off; off >>= 1) acc += __shfl_xor_sync(0xffffffffu, acc, off);
        if (lane == 0) g_bq2[col] = acc + bq[col];
        return;
    }
    blk -= 64;
    if (blk < 512){
        const int col = blk*8 + (tid >> 5), lane = tid & 31;
        float acc = 0.f;
#pragma unroll 16
        for (int i = 0; i < 16; i++){
            const int k = lane + i*32;
            acc += bo[k] * Ws1[(size_t)k*D2 + col];
        }
#pragma unroll
        for (int off = 16; off; off >>= 1) acc += __shfl_xor_sync(0xffffffffu, acc, off);
        if (lane == 0) g_bs1c[col] = acc + bs1[col];
        return;
    }
    blk -= 512;
    if (blk < 512){
        const int idx = blk*256 + tid;
        const int b = idx / DMODEL, d = idx - b * DMODEL;
        const float s0 = start_state[d];
        g_act[idx] = s0;
        if (!(d & 1)){
            uint32_t h, l; split2(s0, start_state[d+1], h, l);
            const int kp = (DATTN + d) >> 1;
            g_pA_h[b*(DPRE/2) + kp] = h; g_pA_l[b*(DPRE/2) + kp] = l;
        }
#pragma unroll
        for (int m = 0; m < MP; m++)
            g_trace[(size_t)idx * MP + m] = (m < MM) ? start_trace[d*MM + m] : 0.f;
        if (d < NSYNC){
            g_aA[b*NSYNC + d] = 0.f; g_bA[b*NSYNC + d] = 0.f;
            g_aO[b*NSYNC + d] = start_state[idx_lo[d]] * start_state[idx_ro[d]];
            g_bO[b*NSYNC + d] = 1.f;
        }
        return;
    }
    blk -= 512;
    if (blk < 4096){ packA_elem(x, g_xp_h, g_xp_l, blk*256 + tid, DIN); return; }
    blk -= 4096;
    if (blk < 512){ packW_elem(Wf, g_Wf_h, g_Wf_l, blk*256 + tid, DATTN); return; }
    blk -= 512;
    if (blk < 512){ packW_elem(Wk, g_Wk_h, g_Wk_l, blk*256 + tid, DATTN); return; }
    blk -= 512;
    if (blk < 512){ packW_elem(Wv, g_Wv_h, g_Wv_l, blk*256 + tid, DATTN); return; }
    blk -= 512;
    if (blk < 512){ packW_elem(Wq, g_Wq_h, g_Wq_l, blk*256 + tid, DATTN); return; }
    blk -= 512;
    if (blk < 512){ packA_elem(Wqp, g_WqpA_h, g_WqpA_l, blk*256 + tid, DATTN); return; }
    blk -= 512;
    if (blk < 512){ packA_elem(Wo, g_WoA_h, g_WoA_l, blk*256 + tid, DATTN); return; }
    blk -= 512;
    if (blk < 4096){ packW_elem(Ws1, g_Ws1t_h, g_Ws1t_l, blk*256 + tid, D2); return; }
    blk -= 4096;
    packWpad_elem(Wout, g_WoutP_h, g_WoutP_l, blk*256 + tid, OUT_N, OUT_P);
}
__global__ __launch_bounds__(256) void setup_g1(const float* __restrict__ bf)
{
    __shared__ uint32_t smem[6912];
    const int c = blockIdx.x;
    if (c < 512)      gemm_dev(g_xp_h, g_xp_l, g_Wf_h, g_Wf_l, g_kv, bf, DATTN, DIN, 0, c & 7, c >> 3, smem, (const float*)0);
    else if (c < 576){ const int c2 = c - 512;
                      gemm_dev(g_WqpA_h, g_WqpA_l, g_Wq_h, g_Wq_l, g_Wqpq, (const float*)0, DATTN, DATTN, 0, c2 & 7, c2 >> 3, smem, (const float*)0); }
    else             { const int c2 = c - 576;
                      gemm_dev(g_WoA_h, g_WoA_l, g_Ws1t_h, g_Ws1t_l, g_WbigTop, (const float*)0, D2, DATTN, 0, c2 & 63, c2 >> 6, smem, (const float*)0); }
}
__global__ __launch_bounds__(256) void setup_b(const float* __restrict__ bk,
                                               const float* __restrict__ bv,
                                               const float* __restrict__ Ws1)
{
    __shared__ uint32_t smem[6912];
    int c = blockIdx.x;
    if (c < 512){ gemm_dev((const uint32_t*)0, (const uint32_t*)0, g_Wk_h, g_Wk_l, g_Kt, bk, DATTN, DATTN, 1, c & 7, c >> 3, smem, g_kv); return; }
    c -= 512;
    if (c < 512){ gemm_dev((const uint32_t*)0, (const uint32_t*)0, g_Wv_h, g_Wv_l, g_V, bv, DATTN, DATTN, 2, c & 7, c >> 3, smem, g_kv); return; }
    c -= 512;
    {   const int idx = c*256 + threadIdx.x;
        const int kp = idx / D2, n = idx - kp*D2;
        float v0, v1;
        if (kp < DATTN/2){ v0 = g_WbigTop[(size_t)(2*kp)*D2 + n]; v1 = g_WbigTop[(size_t)(2*kp+1)*D2 + n]; }
        else             { v0 = Ws1[(size_t)(2*kp)*D2 + n];       v1 = Ws1[(size_t)(2*kp+1)*D2 + n]; }
        split2(v0, v1, g_Wbig_h[idx], g_Wbig_l[idx]); }
}

// ---------- entropy ----------
__device__ void dev_entropy(int b, int tid, float* sm, const float* __restrict__ bout,
                            float* __restrict__ out, int tw)
{
    float* pbuf = sm;
    float* r0 = pbuf + 1000;
    float* r1 = r0 + 8;
    float* bc = r1 + 8;
    float mx = -1e30f;
    for (int o = tid; o < OUT_N; o += 256){
        float p = bout[o];
#pragma unroll
        for (int z = 0; z < 4; z++) p += g_ppart[(z*BB + b)*OUT_P + o];
        pbuf[o] = p;
        out[((size_t)(b*OUT_N + o))*TT + tw] = p;
        mx = fmaxf(mx, p);
    }
#pragma unroll
    for (int off = 16; off; off >>= 1) mx = fmaxf(mx, __shfl_xor_sync(0xffffffffu, mx, off));
    if ((tid & 31) == 0) r0[tid >> 5] = mx;
    __syncthreads();
    if (tid == 0){
        float m = r0[0];
        for (int w = 1; w < 8; w++) m = fmaxf(m, r0[w]);
        bc[0] = m;
    }
    __syncthreads();
    mx = bc[0];
    float s0 = 0.f, s1 = 0.f;
    for (int o = tid; o < OUT_N; o += 256){
        const float u = pbuf[o] - mx;
        const float e = __expf(u);
        s0 += e; s1 += u * e;
    }
#pragma unroll
    for (int off = 16; off; off >>= 1){
        s0 += __shfl_xor_sync(0xffffffffu, s0, off);
        s1 += __shfl_xor_sync(0xffffffffu, s1, off);
    }
    if ((tid & 31) == 0){ r0[tid>>5] = s0; r1[tid>>5] = s1; }
    __syncthreads();
    if (tid == 0){
        float t0 = 0.f, t1 = 0.f;
        for (int w = 0; w < 8; w++){ t0 += r0[w]; t1 += r1[w]; }
        const float ne = -(t1 / t0 - logf(t0)) / logf((float)OUT_N);
        out[CERT_OFF + (size_t)(b*2 + 0)*TT + tw] = ne;
        out[CERT_OFF + (size_t)(b*2 + 1)*TT + tw] = 1.f - ne;
    }
}

// ---------- pred (split-K MMA over syO) ----------
__device__ void dev_pred(int nx, int z, uint32_t* smem)
{
    uint32_t* sAh = smem;
    uint32_t* sAl = sAh + 2304;
    uint32_t* sBh = sAl + 2304;
    uint32_t* sBl = sBh + 1152;
    const int tid = threadIdx.x;
    const int nBase = nx * 64;
    const int warp = tid >> 5, lane = tid & 31;
    const int wm = (warp & 3) * 16, wn = (warp >> 2) * 32;
    const int g = lane >> 2, tg = lane & 3;
    float acc[4][4];
#pragma unroll
    for (int t = 0; t < 4; t++){ acc[t][0]=acc[t][1]=acc[t][2]=acc[t][3]=0.f; }

    for (int kk = 0; kk < 128; kk += 32){
        const int kpg = z * 64 + (kk >> 1);
#pragma unroll
        for (int i = 0; i < 4; i++){
            int idx = tid + i * 256;
            int m = idx >> 4, kp = idx & 15;
            sAh[m*36+kp] = g_syO_h[m*(NSYNC/2) + kpg + kp];
            sAl[m*36+kp] = g_syO_l[m*(NSYNC/2) + kpg + kp];
            int kb = idx >> 6, n = idx & 63;
            sBh[kb*72+n] = g_WoutP_h[(size_t)(kpg + kb) * OUT_P + nBase + n];
            sBl[kb*72+n] = g_WoutP_l[(size_t)(kpg + kb) * OUT_P + nBase + n];
        }
        __syncthreads();
#pragma unroll
        for (int s = 0; s < 2; s++){
            const int kb = s * 8;
            uint32_t ah0 = sAh[(wm+g)*36+kb+tg],   ah1 = sAh[(wm+8+g)*36+kb+tg];
            uint32_t ah2 = sAh[(wm+g)*36+kb+4+tg], ah3 = sAh[(wm+8+g)*36+kb+4+tg];
            uint32_t al0 = sAl[(wm+g)*36+kb+tg],   al1 = sAl[(wm+8+g)*36+kb+tg];
            uint32_t al2 = sAl[(wm+g)*36+kb+4+tg], al3 = sAl[(wm+8+g)*36+kb+4+tg];
#pragma unroll
            for (int t = 0; t < 4; t++){
                const int n = wn + t * 8 + g;
                uint32_t bh0 = sBh[(kb+tg)*72+n], bh1 = sBh[(kb+4+tg)*72+n];
                uint32_t bl0 = sBl[(kb+tg)*72+n], bl1 = sBl[(kb+4+tg)*72+n];
                mma16816(acc[t], ah0, ah1, ah2, ah3, bh0, bh1);
                mma16816(acc[t], ah0, ah1, ah2, ah3, bl0, bl1);
                mma16816(acc[t], al0, al1, al2, al3, bh0, bh1);
            }
        }
        __syncthreads();
    }
    const int r0 = wm + g;
#pragma unroll
    for (int t = 0; t < 4; t++){
        const int c = nBase + wn + t * 8 + tg * 2;
#pragma unroll
        for (int hr = 0; hr < 2; hr++){
            const int r = r0 + hr * 8;
            float* p = &g_ppart[((size_t)(z*BB + r)) * OUT_P + c];
            p[0] = acc[t][hr*2+0]; p[1] = acc[t][hr*2+1];
        }
    }
}

// ---------- big GEMM slice: N-tile nx (128 wide), k-pairs [kp0, kp0+nst*16), out slice zout ----------
__device__ void dev_big(int nx, int zout, int kp0, int nst, uint32_t* sm)
{
    uint32_t* sAh = sm;
    uint32_t* sAl = sAh + 1280;
    uint32_t* sBh = sAl + 1280;
    uint32_t* sBl = sBh + 2112;
    const int tid = threadIdx.x;
    const int nBase = nx * 128;
    const int warp = tid >> 5, lane = tid & 31;
    const int wm = (warp & 3) * 16, wn = (warp >> 2) * 64;
    const int g = lane >> 2, tg = lane & 3;
    const int arow = tid >> 2, apg = (tid & 3) << 2;
    const int brow = tid >> 5, bc = lane << 2;

    float acc[8][4];
#pragma unroll
    for (int t = 0; t < 8; t++){ acc[t][0]=acc[t][1]=acc[t][2]=acc[t][3]=0.f; }

    uint4 pAh, pAl, pBh0, pBl0, pBh1, pBl1;
    {
        const int kpg = kp0;
        pAh = *reinterpret_cast<const uint4*>(&g_pA_h[arow*(DPRE/2) + kpg + apg]);
        pAl = *reinterpret_cast<const uint4*>(&g_pA_l[arow*(DPRE/2) + kpg + apg]);
        pBh0 = __ldcg(reinterpret_cast<const uint4*>(&g_Wbig_h[(size_t)(kpg+brow  )*D2 + nBase + bc]));
        pBl0 = __ldcg(reinterpret_cast<const uint4*>(&g_Wbig_l[(size_t)(kpg+brow  )*D2 + nBase + bc]));
        pBh1 = __ldcg(reinterpret_cast<const uint4*>(&g_Wbig_h[(size_t)(kpg+brow+8)*D2 + nBase + bc]));
        pBl1 = __ldcg(reinterpret_cast<const uint4*>(&g_Wbig_l[(size_t)(kpg+brow+8)*D2 + nBase + bc]));
    }
    *reinterpret_cast<uint4*>(&sAh[arow*20 + apg]) = pAh;
    *reinterpret_cast<uint4*>(&sAl[arow*20 + apg]) = pAl;
    *reinterpret_cast<uint4*>(&sBh[brow*132 + bc]) = pBh0;
    *reinterpret_cast<uint4*>(&sBl[brow*132 + bc]) = pBl0;
    *reinterpret_cast<uint4*>(&sBh[(brow+8)*132 + bc]) = pBh1;
    *reinterpret_cast<uint4*>(&sBl[(brow+8)*132 + bc]) = pBl1;
    __syncthreads();

    for (int st = 0; st < nst; st++){
        if (st + 1 < nst){
            const int kpg = kp0 + (st+1) * 16;
            pAh = *reinterpret_cast<const uint4*>(&g_pA_h[arow*(DPRE/2) + kpg + apg]);
            pAl = *reinterpret_cast<const uint4*>(&g_pA_l[arow*(DPRE/2) + kpg + apg]);
            pBh0 = __ldcg(reinterpret_cast<const uint4*>(&g_Wbig_h[(size_t)(kpg+brow  )*D2 + nBase + bc]));
            pBl0 = __ldcg(reinterpret_cast<const uint4*>(&g_Wbig_l[(size_t)(kpg+brow  )*D2 + nBase + bc]));
            pBh1 = __ldcg(reinterpret_cast<const uint4*>(&g_Wbig_h[(size_t)(kpg+brow+8)*D2 + nBase + bc]));
            pBl1 = __ldcg(reinterpret_cast<const uint4*>(&g_Wbig_l[(size_t)(kpg+brow+8)*D2 + nBase + bc]));
        }
#pragma unroll
        for (int s = 0; s < 2; s++){
            const int kb = s * 8;
            const uint32_t ah0 = sAh[(wm+g)*20 + kb+tg],   ah1 = sAh[(wm+8+g)*20 + kb+tg];
            const uint32_t ah2 = sAh[(wm+g)*20 + kb+4+tg], ah3 = sAh[(wm+8+g)*20 + kb+4+tg];
            const uint32_t al0 = sAl[(wm+g)*20 + kb+tg],   al1 = sAl[(wm+8+g)*20 + kb+tg];
            const uint32_t al2 = sAl[(wm+g)*20 + kb+4+tg], al3 = sAl[(wm+8+g)*20 + kb+4+tg];
#pragma unroll
            for (int t = 0; t < 8; t++){
                const int n = wn + t * 8 + g;
                const uint32_t bh0 = sBh[(kb+tg)*132 + n], bh1 = sBh[(kb+4+tg)*132 + n];
                const uint32_t bl0 = sBl[(kb+tg)*132 + n], bl1 = sBl[(kb+4+tg)*132 + n];
                mma16816(acc[t], ah0, ah1, ah2, ah3, bh0, bh1);
                mma16816(acc[t], ah0, ah1, ah2, ah3, bl0, bl1);
                mma16816(acc[t], al0, al1, al2, al3, bh0, bh1);
            }
        }
        if (st + 1 < nst){
            __syncthreads();
            *reinterpret_cast<uint4*>(&sAh[arow*20 + apg]) = pAh;
            *reinterpret_cast<uint4*>(&sAl[arow*20 + apg]) = pAl;
            *reinterpret_cast<uint4*>(&sBh[brow*132 + bc]) = pBh0;
            *reinterpret_cast<uint4*>(&sBl[brow*132 + bc]) = pBl0;
            *reinterpret_cast<uint4*>(&sBh[(brow+8)*132 + bc]) = pBh1;
            *reinterpret_cast<uint4*>(&sBl[(brow+8)*132 + bc]) = pBl1;
            __syncthreads();
        }
    }
    const int r0 = wm + g;
#pragma unroll
    for (int t = 0; t < 8; t++){
        const int c = nBase + wn + t * 8 + tg * 2;
#pragma unroll
        for (int hr = 0; hr < 2; hr++){
            const int r = r0 + hr * 8;
            float* p = &g_hpart[((size_t)(zout*64 + r)) * D2 + c];
            p[0] = acc[t][hr*2+0]; p[1] = acc[t][hr*2+1];
        }
    }
}

// ---------- K1: q+attn(t) | pred(t-1) | bigB(t) (k>=512, depends on nlm(t-1)) ----------
// blocks [0,128): attnq ; [128,192): pred ; [192,320): bigB (nx=r&31, z=r>>5)
__global__ __launch_bounds__(256) void k1_kernel(int tick)
{
    __shared__ __align__(16) uint32_t SMu[6928];
    const int tid = threadIdx.x;
    if (blockIdx.x >= 192){
        const int r = blockIdx.x - 192;
        dev_big(r & 31, r >> 5, 256 + (r >> 5) * 256, 16, SMu);
        return;
    }
    if (blockIdx.x >= 128){
        if (tick > 0){
            const int r = blockIdx.x - 128;
            dev_pred(r & 15, r >> 4, SMu);
        }
        return;
    }
    float* SM = (float*)SMu;
    float* sA  = SM;
    float* sW  = SM + 2048;
    float* qs  = SM + 6400;
    float* ws  = qs + 256;
    float* red = ws + 256;
    const int h = blockIdx.x >> 4, bg = blockIdx.x & 15;
    const int grp = tid >> 6, t = tid & 63;
    const int b = bg * 4 + grp;

#pragma unroll
    for (int i = 0; i < 8; i++){
        const int idx = tid + i * 256;
        sA[idx] = g_syA[(bg*4 + (idx >> 9)) * NSYNC + (idx & 511)];
    }

    const int col = h * HD + t;
    float a0 = 0.f, a1 = 0.f, a2 = 0.f, a3 = 0.f;
    for (int ch = 0; ch < 8; ch++){
        const int k0 = ch * 64;
        __syncthreads();
#pragma unroll
        for (int i = 0; i < 16; i++){
            const int idx = tid + i * 256;
            const int r = idx >> 6, c = idx & 63;
            sW[c*68 + r] = g_Wqpq[(size_t)(k0 + r) * DATTN + h * HD + c];
        }
        __syncthreads();
        const float* ap = sA + grp * 512 + k0;
        const float4* wp = reinterpret_cast<const float4*>(sW + t * 68);
#pragma unroll
        for (int k = 0; k < 64; k += 4){
            const float4 w = wp[k >> 2];
            a0 += ap[k+0] * w.x;
            a1 += ap[k+1] * w.y;
            a2 += ap[k+2] * w.z;
            a3 += ap[k+3] * w.w;
        }
    }
    qs[grp*64 + t] = (a0 + a1) + (a2 + a3) + g_bq2[col];
    __syncthreads();

    const float* ktp = &g_Kt[((b*HEADS + h)*HD) * SS + t];
    float sc = 0.f;
#pragma unroll
    for (int d = 0; d < HD; d++) sc += qs[grp*64 + d] * ktp[d*SS];
    sc *= 0.125f;

    float mx = sc;
#pragma unroll
    for (int off = 16; off; off >>= 1) mx = fmaxf(mx, __shfl_xor_sync(0xffffffffu, mx, off));
    if ((t & 31) == 0) red[grp*4 + (t >> 5)] = mx;
    __syncthreads();
    mx = fmaxf(red[grp*4 + 0], red[grp*4 + 1]);
    const float e = __expf(sc - mx);
    float smv = e;
#pragma unroll
    for (int off = 16; off; off >>= 1) smv += __shfl_xor_sync(0xffffffffu, smv, off);
    if ((t & 31) == 0) red[grp*4 + 2 + (t >> 5)] = smv;
    __syncthreads();
    smv = red[grp*4 + 2] + red[grp*4 + 3];
    ws[grp*64 + t] = e / smv;
    __syncthreads();

    const float* vp = &g_V[((b*HEADS + h)*SS) * HD + t];
    float ao = 0.f;
#pragma unroll
    for (int s = 0; s < SS; s++) ao += ws[grp*64 + s] * vp[s*HD];

    const float an = __shfl_down_sync(0xffffffffu, ao, 1);
    if (!(t & 1)){
        uint32_t hi, lo; split2(ao, an, hi, lo);
        const int kp = (h*HD + t) >> 1;
        g_pA_h[b*(DPRE/2) + kp] = hi; g_pA_l[b*(DPRE/2) + kp] = lo;
    }
}

// ---------- K2: bigA(t) (k<512, needs attnq) | entropy(t-1) ----------
// blocks [0,64): bigA (nx=blk&31, z2=blk>>5: pairs z2*128..+128, out slice 4+z2)
// blocks [64,128): entropy(t-1)
__global__ __launch_bounds__(256) void k2_kernel(const float* __restrict__ bout,
                                                 float* __restrict__ out, int tick)
{
    __shared__ __align__(16) uint32_t sm[6784];
    const int tid = threadIdx.x;
    if (blockIdx.x >= 64){
        if (tick > 0) dev_entropy(blockIdx.x - 64, tid, (float*)sm, bout, out, tick - 1);
        return;
    }
    const int nx = blockIdx.x & 31, z2 = blockIdx.x >> 5;
    dev_big(nx, 4 + z2, z2 * 128, 8, sm);
}

__global__ __launch_bounds__(256) void glu_kernel(const float* __restrict__ ln_g,
                                                  const float* __restrict__ ln_b, int tick)
{
    __shared__ float gbuf[DMODEL];
    __shared__ float rs[16];
    __shared__ float ms[2];
    const int b = blockIdx.x, tid = threadIdx.x;
    float s = 0.f, s2 = 0.f;
    for (int j = tid; j < DMODEL; j += 256){
        float h1 = g_bs1c[j], h2 = g_bs1c[j + DMODEL];
#pragma unroll
        for (int z = 0; z < HSPLIT; z++){
            h1 += g_hpart[(size_t)(z*64 + b)*D2 + j];
            h2 += g_hpart[(size_t)(z*64 + b)*D2 + j + DMODEL];
        }
        const float gv = h1 / (1.f + __expf(-h2));
        gbuf[j] = gv; s += gv; s2 += gv*gv;
    }
#pragma unroll
    for (int off = 16; off; off >>= 1){
        s  += __shfl_xor_sync(0xffffffffu, s,  off);
        s2 += __shfl_xor_sync(0xffffffffu, s2, off);
    }
    if ((tid & 31) == 0){ rs[tid>>5] = s; rs[8 + (tid>>5)] = s2; }
    __syncthreads();
    if (tid == 0){
        float ts = 0.f, ts2 = 0.f;
        for (int w = 0; w < 8; w++){ ts += rs[w]; ts2 += rs[8+w]; }
        const float mu = ts / (float)DMODEL;
        ms[0] = mu; ms[1] = rsqrtf(ts2 / (float)DMODEL - mu*mu + 1e-5f);
    }
    __syncthreads();
    const int slot = tick % MM;
    const float mu = ms[0], inv = ms[1];
    for (int j = tid; j < DMODEL; j += 256)
        g_trace[((size_t)(b*DMODEL + j)) * MP + slot] = (gbuf[j] - mu) * inv * ln_g[j] + ln_b[j];
}

__global__ __launch_bounds__(256) void nlm_kernel(const float* __restrict__ nw1,
                                                  const float* __restrict__ nb1,
                                                  const float* __restrict__ nw2,
                                                  const float* __restrict__ nb2, int tick)
{
    __shared__ float w1s[3200], b1s[128], w2s[128], sAct[256];
    const int cta = blockIdx.x, tid = threadIdx.x;
    const int d0 = cta * 16;
    const int b = tid & 63, dsub = tid >> 6;
    const int o = (tick + 1) % MM;

    for (int p = 0; p < 4; p++){
        const int dbase = d0 + p * 4;
        __syncthreads();
        for (int i = tid; i < 3200; i += 256) w1s[i] = nw1[(size_t)dbase*800 + i];
        if (tid < 128){ b1s[tid] = nb1[dbase*32 + tid]; w2s[tid] = nw2[dbase*32 + tid]; }
        __syncthreads();

        const int d = dbase + dsub;
        float tr[MM];
        const float* tp = &g_trace[((size_t)(b*DMODEL + d)) * MP];
#pragma unroll
        for (int m = 0; m < MM; m++){ int s = o + m; if (s >= MM) s -= MM; tr[m] = tp[s]; }

        const float* w1p = w1s + dsub * 800;
        float ov = 0.f;
#pragma unroll
        for (int h = 0; h < 32; h += 4){
            float4 s4 = *reinterpret_cast<const float4*>(&b1s[dsub*32 + h]);
#pragma unroll
            for (int m = 0; m < MM; m++){
                const float4 w = *reinterpret_cast<const float4*>(&w1p[m*32 + h]);
                s4.x += tr[m]*w.x; s4.y += tr[m]*w.y; s4.z += tr[m]*w.z; s4.w += tr[m]*w.w;
            }
            const float4 w2v = *reinterpret_cast<const float4*>(&w2s[dsub*32 + h]);
            ov += gelu_f(s4.x)*w2v.x + gelu_f(s4.y)*w2v.y + gelu_f(s4.z)*w2v.z + gelu_f(s4.w)*w2v.w;
        }
        const float a = ov + nb2[d];
        g_act[b*DMODEL + d] = a;
        sAct[dsub*64 + b] = a;
        __syncthreads();
        if (tid < 128){
            const int pi = tid >> 6, bb = tid & 63;
            const float v0 = sAct[(2*pi)*64 + bb], v1 = sAct[(2*pi+1)*64 + bb];
            uint32_t hi, lo; split2(v0, v1, hi, lo);
            const int kp = (DATTN + dbase + 2*pi) >> 1;
            g_pA_h[bb*(DPRE/2) + kp] = hi; g_pA_l[bb*(DPRE/2) + kp] = lo;
        }
    }
}

__global__ void sync_kernel(const float* __restrict__ decay_a, const float* __restrict__ decay_o,
                            const int* __restrict__ idx_la, const int* __restrict__ idx_ra,
                            const int* __restrict__ idx_lo, const int* __restrict__ idx_ro,
                            int mode)
{
    __shared__ float sAct[DMODEL];
    const int b = blockIdx.x, i = threadIdx.x;
#pragma unroll
    for (int k = 0; k < 4; k++) sAct[i + k*512] = g_act[b*DMODEL + i + k*512];
    __syncthreads();
    if (mode & 2){
        const float pairing = sAct[idx_lo[i]] * sAct[idx_ro[i]];
        const float r = __expf(-fminf(fmaxf(decay_o[i], 0.f), 15.f));
        const float a = r * g_aO[b*NSYNC+i] + pairing;
        const float bt = r * g_bO[b*NSYNC+i] + 1.f;
        g_aO[b*NSYNC+i] = a; g_bO[b*NSYNC+i] = bt;
        const float v = a * rsqrtf(bt);
        g_syO[b*NSYNC+i] = v;
        const float vn = __shfl_down_sync(0xffffffffu, v, 1);
        if (!(i & 1)){
            uint32_t h, l; split2(v, vn, h, l);
            g_syO_h[b*(NSYNC/2) + (i>>1)] = h; g_syO_l[b*(NSYNC/2) + (i>>1)] = l;
        }
    }
    if (mode & 1){
        const float pairing = sAct[idx_la[i]] * sAct[idx_ra[i]];
        const float r = __expf(-fminf(fmaxf(decay_a[i], 0.f), 15.f));
        const float a = r * g_aA[b*NSYNC+i] + pairing;
        const float bt = r * g_bA[b*NSYNC+i] + 1.f;
        g_aA[b*NSYNC+i] = a; g_bA[b*NSYNC+i] = bt;
        g_syA[b*NSYNC+i] = a * rsqrtf(bt);
    }
}

// tail: pred(49)
__global__ __launch_bounds__(256) void predtail_kernel()
{
    __shared__ __align__(16) uint32_t smem[6912];
    dev_pred((int)blockIdx.x, (int)blockIdx.y, smem);
}
// tail: entropy(49) + syO copy
__global__ __launch_bounds__(256) void fin_kernel(const float* __restrict__ bout,
                                                  float* __restrict__ out)
{
    __shared__ float SM[1024];
    const int blk = blockIdx.x, tid = threadIdx.x;
    if (blk < 64){ dev_entropy(blk, tid, SM, bout, out, TT - 1); return; }
    const int i = (blk - 64) * 256 + tid;
    out[SYO_OFF + i] = g_syO[i];
}

// ---------- launch ----------
extern "C" void kernel_launch(void* const* d_in, const int* in_sizes, int n_in,
                              void* d_out, int out_size)
{
    const float* x   = (const float*)d_in[0];
    const float* Wf  = (const float*)d_in[1];
    const float* bf  = (const float*)d_in[2];
    const float* start_trace = (const float*)d_in[3];
    const float* start_state = (const float*)d_in[4];
    const float* decay_a = (const float*)d_in[5];
    const float* decay_o = (const float*)d_in[6];
    const float* Wqp = (const float*)d_in[7];
    const float* bqp = (const float*)d_in[8];
    const float* Wq  = (const float*)d_in[9];
    const float* bq  = (const float*)d_in[10];
    const float* Wk  = (const float*)d_in[11];
    const float* bk  = (const float*)d_in[12];
    const float* Wv  = (const float*)d_in[13];
    const float* bv  = (const float*)d_in[14];
    const float* Wo  = (const float*)d_in[15];
    const float* bo  = (const float*)d_in[16];
    const float* Ws1 = (const float*)d_in[17];
    const float* bs1 = (const float*)d_in[18];
    const float* ln_g = (const float*)d_in[19];
    const float* ln_b = (const float*)d_in[20];
    const float* nw1 = (const float*)d_in[21];
    const float* nb1 = (const float*)d_in[22];
    const float* nw2 = (const float*)d_in[23];
    const float* nb2 = (const float*)d_in[24];
    const float* Wout = (const float*)d_in[25];
    const float* bout = (const float*)d_in[26];
    const int* idx_la = (const int*)d_in[27];
    const int* idx_ra = (const int*)d_in[28];
    const int* idx_lo = (const int*)d_in[29];
    const int* idx_ro = (const int*)d_in[30];
    float* out = (float*)d_out;

    setup_a<<<13376, 256>>>(x, Wf, Wk, Wv, Wq, Wqp, Wo, Ws1, Wout,
                            bqp, bq, bo, bs1, start_trace, start_state, idx_lo, idx_ro);
    setup_g1<<<1088, 256>>>(bf);
    setup_b<<<21504, 256>>>(bk, bv, Ws1);

    sync_kernel<<<64, 512>>>(decay_a, decay_o, idx_la, idx_ra, idx_lo, idx_ro, 1);

    for (int t = 0; t < TT; t++){
        k1_kernel<<<320, 256>>>(t);                    // q+attn(t) | pred(t-1) | bigB(t)
        k2_kernel<<<128, 256>>>(bout, out, t);         // bigA(t) | entropy(t-1)
        glu_kernel<<<64, 256>>>(ln_g, ln_b, t);
        nlm_kernel<<<128, 256>>>(nw1, nb1, nw2, nb2, t);
        sync_kernel<<<64, 512>>>(decay_a, decay_o, idx_la, idx_ra, idx_lo, idx_ro, 3);
    }
    predtail_kernel<<<dim3(16, 4), 256>>>();
    fin_kernel<<<192, 256>>>(bout, out);
    (void)in_sizes; (void)n_in; (void)out_size;
}

// round 13
// speedup vs baseline: 1.0206x; 1.0206x over previous
#include <cuda_runtime.h>
#include <cuda_bf16.h>
#include <cstdint>

#define BB 64
#define SS 64
#define DIN 512
#define DATTN 512
#define DMODEL 2048
#define MM 25
#define MP 32
#define HEADS 8
#define HD 64
#define NSYNC 512
#define OUT_N 1000
#define OUT_P 1024
#define TT 50
#define DPRE 2560
#define D2 4096
#define KSPLIT 4

#define PRED_SZ (BB*OUT_N*TT)
#define CERT_OFF (PRED_SZ)
#define SYO_OFF (PRED_SZ + BB*2*TT)

// ---------- scratch ----------
__device__ float g_kv[BB*SS*DATTN];
__device__ float g_Kt[BB*HEADS*HD*SS];
__device__ float g_V [BB*HEADS*SS*HD];
__device__ float g_Wqpq[NSYNC*DATTN];
__device__ float g_WbigTop[DATTN*D2];
__device__ float g_bq2[DATTN];
__device__ float g_bs1c[D2];
__device__ float g_act[BB*DMODEL];
__device__ float g_trace[BB*DMODEL*MP];
__device__ float g_aA[2][BB*NSYNC], g_bA[2][BB*NSYNC];
__device__ float g_aO[BB*NSYNC], g_bO[BB*NSYNC], g_syO[BB*NSYNC];
__device__ float g_hpart[KSPLIT*BB*D2];
__device__ float g_ppart[4*BB*OUT_P];
// packed bf16 hi/lo
__device__ uint32_t g_xp_h[(BB*SS)*(DIN/2)],  g_xp_l[(BB*SS)*(DIN/2)];
__device__ uint32_t g_Wf_h[(DIN/2)*DATTN],  g_Wf_l[(DIN/2)*DATTN];
__device__ uint32_t g_Wk_h[(DATTN/2)*DATTN], g_Wk_l[(DATTN/2)*DATTN];
__device__ uint32_t g_Wv_h[(DATTN/2)*DATTN], g_Wv_l[(DATTN/2)*DATTN];
__device__ uint32_t g_Wq_h[(DATTN/2)*DATTN], g_Wq_l[(DATTN/2)*DATTN];
__device__ uint32_t g_WqpA_h[NSYNC*(DATTN/2)], g_WqpA_l[NSYNC*(DATTN/2)];
__device__ uint32_t g_WoA_h[DATTN*(DATTN/2)], g_WoA_l[DATTN*(DATTN/2)];
__device__ uint32_t g_Ws1t_h[(DATTN/2)*D2], g_Ws1t_l[(DATTN/2)*D2];
__device__ uint32_t g_Wbig_h[(DPRE/2)*D2], g_Wbig_l[(DPRE/2)*D2];
__device__ uint32_t g_WoutP_h[(NSYNC/2)*OUT_P], g_WoutP_l[(NSYNC/2)*OUT_P];
__device__ uint32_t g_pA_h[BB*(DPRE/2)], g_pA_l[BB*(DPRE/2)];
__device__ uint32_t g_syO_h[BB*(NSYNC/2)], g_syO_l[BB*(NSYNC/2)];

// ---------- helpers ----------
__device__ __forceinline__ uint32_t bfpair(float a, float b){
    __nv_bfloat162 t = __floats2bfloat162_rn(a, b);
    return *reinterpret_cast<uint32_t*>(&t);
}
__device__ __forceinline__ void split2(float v0, float v1, uint32_t& hi, uint32_t& lo){
    float h0 = __bfloat162float(__float2bfloat16(v0));
    float h1 = __bfloat162float(__float2bfloat16(v1));
    hi = bfpair(h0, h1);
    lo = bfpair(v0 - h0, v1 - h1);
}
__device__ __forceinline__ void mma16816(float* c, uint32_t a0, uint32_t a1,
                                         uint32_t a2, uint32_t a3, uint32_t b0, uint32_t b1){
    asm volatile("mma.sync.aligned.m16n8k16.row.col.f32.bf16.bf16.f32 "
        "{%0,%1,%2,%3},{%4,%5,%6,%7},{%8,%9},{%0,%1,%2,%3};"
        : "+f"(c[0]), "+f"(c[1]), "+f"(c[2]), "+f"(c[3])
        : "r"(a0), "r"(a1), "r"(a2), "r"(a3), "r"(b0), "r"(b1));
}
__device__ __forceinline__ float gelu_f(float x){
    float z = 0.7978845608028654f * (x + 0.044715f * x*x*x);
    float ee = __expf(-2.f * fabsf(z));
    float th = copysignf((1.f - ee) / (1.f + ee), z);
    return 0.5f * x * (1.f + th);
}
__device__ __forceinline__ void packA_elem(const float* __restrict__ src,
                                           uint32_t* __restrict__ h, uint32_t* __restrict__ l,
                                           int idx, int K){
    const int Kh = K >> 1;
    const int m = idx / Kh, kp = idx - m * Kh;
    split2(src[(size_t)m*K + 2*kp], src[(size_t)m*K + 2*kp + 1], h[idx], l[idx]);
}
__device__ __forceinline__ void packW_elem(const float* __restrict__ src,
                                           uint32_t* __restrict__ h, uint32_t* __restrict__ l,
                                           int idx, int N){
    const int kp = idx / N, n = idx - kp * N;
    split2(src[(size_t)(2*kp)*N + n], src[(size_t)(2*kp+1)*N + n], h[idx], l[idx]);
}
__device__ __forceinline__ void packWpad_elem(const float* __restrict__ src,
                                              uint32_t* __restrict__ h, uint32_t* __restrict__ l,
                                              int idx, int Ns, int Nd){
    const int kp = idx / Nd, n = idx - kp * Nd;
    const float v0 = (n < Ns) ? src[(size_t)(2*kp)*Ns + n] : 0.f;
    const float v1 = (n < Ns) ? src[(size_t)(2*kp+1)*Ns + n] : 0.f;
    split2(v0, v1, h[idx], l[idx]);
}

// ---------- setup GEMM core ----------
__device__ void gemm_dev(const uint32_t* __restrict__ Ah, const uint32_t* __restrict__ Al,
                         const uint32_t* __restrict__ Wh, const uint32_t* __restrict__ Wl,
                         float* __restrict__ C, const float* __restrict__ bias,
                         int N, int K, int epi, int bx, int by, uint32_t* smem, const float* Af32)
{
    uint32_t* sAh = smem;
    uint32_t* sAl = sAh + 2304;
    uint32_t* sBh = sAl + 2304;
    uint32_t* sBl = sBh + 1152;
    const int tid = threadIdx.x;
    const int nBase = bx * 64, rowBase = by * 64;
    const int Kh = K >> 1;
    const int warp = tid >> 5, lane = tid & 31;
    const int wm = (warp & 3) * 16, wn = (warp >> 2) * 32;
    const int g = lane >> 2, tg = lane & 3;
    float acc[4][4];
#pragma unroll
    for (int t = 0; t < 4; t++){ acc[t][0]=acc[t][1]=acc[t][2]=acc[t][3]=0.f; }

    for (int kk = 0; kk < K; kk += 32){
        const int kpg = kk >> 1;
#pragma unroll
        for (int i = 0; i < 4; i++){
            int idx = tid + i * 256;
            int m = idx >> 4, kp = idx & 15;
            if (Af32){
                const float2 av = *reinterpret_cast<const float2*>(
                    &Af32[(size_t)(rowBase + m) * K + (kpg + kp) * 2]);
                split2(av.x, av.y, sAh[m*36+kp], sAl[m*36+kp]);
            } else {
                sAh[m*36+kp] = Ah[(size_t)(rowBase + m) * Kh + kpg + kp];
                sAl[m*36+kp] = Al[(size_t)(rowBase + m) * Kh + kpg + kp];
            }
            int kb = idx >> 6, n = idx & 63;
            sBh[kb*72+n] = Wh[(size_t)(kpg + kb) * N + nBase + n];
            sBl[kb*72+n] = Wl[(size_t)(kpg + kb) * N + nBase + n];
        }
        __syncthreads();
#pragma unroll
        for (int s = 0; s < 2; s++){
            const int kb = s * 8;
            uint32_t ah0 = sAh[(wm+g)*36+kb+tg],   ah1 = sAh[(wm+8+g)*36+kb+tg];
            uint32_t ah2 = sAh[(wm+g)*36+kb+4+tg], ah3 = sAh[(wm+8+g)*36+kb+4+tg];
            uint32_t al0 = sAl[(wm+g)*36+kb+tg],   al1 = sAl[(wm+8+g)*36+kb+tg];
            uint32_t al2 = sAl[(wm+g)*36+kb+4+tg], al3 = sAl[(wm+8+g)*36+kb+4+tg];
#pragma unroll
            for (int t = 0; t < 4; t++){
                const int n = wn + t * 8 + g;
                uint32_t bh0 = sBh[(kb+tg)*72+n], bh1 = sBh[(kb+4+tg)*72+n];
                uint32_t bl0 = sBl[(kb+tg)*72+n], bl1 = sBl[(kb+4+tg)*72+n];
                mma16816(acc[t], ah0, ah1, ah2, ah3, bh0, bh1);
                mma16816(acc[t], ah0, ah1, ah2, ah3, bl0, bl1);
                mma16816(acc[t], al0, al1, al2, al3, bh0, bh1);
            }
        }
        __syncthreads();
    }
    const int r0 = rowBase + wm + g;
#pragma unroll
    for (int t = 0; t < 4; t++){
        const int c = nBase + wn + t * 8 + tg * 2;
#pragma unroll
        for (int hr = 0; hr < 2; hr++){
            const int r = r0 + hr * 8;
            const float v0 = acc[t][hr*2+0], v1 = acc[t][hr*2+1];
            if (epi == 0){
                C[(size_t)r*N + c]   = v0 + (bias ? bias[c]   : 0.f);
                C[(size_t)r*N + c+1] = v1 + (bias ? bias[c+1] : 0.f);
            } else if (epi == 1){
                const int b = r >> 6, srow = r & 63, h = c >> 6, d = c & 63;
                C[((b*HEADS+h)*HD + d  )*SS + srow] = v0 + bias[c];
                C[((b*HEADS+h)*HD + d+1)*SS + srow] = v1 + bias[c+1];
            } else {
                const int b = r >> 6, srow = r & 63, h = c >> 6, d = c & 63;
                C[((b*HEADS+h)*SS + srow)*HD + d  ] = v0 + bias[c];
                C[((b*HEADS+h)*SS + srow)*HD + d+1] = v1 + bias[c+1];
            }
        }
    }
}

// ---------- setup kernels ----------
__global__ void setup_a(const float* __restrict__ x,  const float* __restrict__ Wf,
                        const float* __restrict__ Wk, const float* __restrict__ Wv,
                        const float* __restrict__ Wq, const float* __restrict__ Wqp,
                        const float* __restrict__ Wo, const float* __restrict__ Ws1,
                        const float* __restrict__ Wout,
                        const float* __restrict__ bqp, const float* __restrict__ bq,
                        const float* __restrict__ bo,  const float* __restrict__ bs1,
                        const float* __restrict__ start_trace, const float* __restrict__ start_state,
                        const int* __restrict__ idx_lo, const int* __restrict__ idx_ro)
{
    int blk = blockIdx.x;
    const int tid = threadIdx.x;
    if (blk < 64){
        const int col = blk*8 + (tid >> 5), lane = tid & 31;
        float acc = 0.f;
#pragma unroll 16
        for (int i = 0; i < 16; i++){
            const int k = lane + i*32;
            acc += bqp[k] * Wq[(size_t)k*DATTN + col];
        }
#pragma unroll
        for (int off = 16; off; off >>= 1) acc += __shfl_xor_sync(0xffffffffu, acc, off);
        if (lane == 0) g_bq2[col] = acc + bq[col];
        return;
    }
    blk -= 64;
    if (blk < 512){
        const int col = blk*8 + (tid >> 5), lane = tid & 31;
        float acc = 0.f;
#pragma unroll 16
        for (int i = 0; i < 16; i++){
            const int k = lane + i*32;
            acc += bo[k] * Ws1[(size_t)k*D2 + col];
        }
#pragma unroll
        for (int off = 16; off; off >>= 1) acc += __shfl_xor_sync(0xffffffffu, acc, off);
        if (lane == 0) g_bs1c[col] = acc + bs1[col];
        return;
    }
    blk -= 512;
    if (blk < 512){
        const int idx = blk*256 + tid;
        const int b = idx / DMODEL, d = idx - b * DMODEL;
        const float s0 = start_state[d];
        g_act[idx] = s0;
        if (!(d & 1)){
            uint32_t h, l; split2(s0, start_state[d+1], h, l);
            const int kp = (DATTN + d) >> 1;
            g_pA_h[b*(DPRE/2) + kp] = h; g_pA_l[b*(DPRE/2) + kp] = l;
        }
#pragma unroll
        for (int m = 0; m < MP; m++)
            g_trace[(size_t)idx * MP + m] = (m < MM) ? start_trace[d*MM + m] : 0.f;
        if (d < NSYNC){
            g_aA[0][b*NSYNC + d] = 0.f; g_bA[0][b*NSYNC + d] = 0.f;
            g_aO[b*NSYNC + d] = start_state[idx_lo[d]] * start_state[idx_ro[d]];
            g_bO[b*NSYNC + d] = 1.f;
        }
        return;
    }
    blk -= 512;
    if (blk < 4096){ packA_elem(x, g_xp_h, g_xp_l, blk*256 + tid, DIN); return; }
    blk -= 4096;
    if (blk < 512){ packW_elem(Wf, g_Wf_h, g_Wf_l, blk*256 + tid, DATTN); return; }
    blk -= 512;
    if (blk < 512){ packW_elem(Wk, g_Wk_h, g_Wk_l, blk*256 + tid, DATTN); return; }
    blk -= 512;
    if (blk < 512){ packW_elem(Wv, g_Wv_h, g_Wv_l, blk*256 + tid, DATTN); return; }
    blk -= 512;
    if (blk < 512){ packW_elem(Wq, g_Wq_h, g_Wq_l, blk*256 + tid, DATTN); return; }
    blk -= 512;
    if (blk < 512){ packA_elem(Wqp, g_WqpA_h, g_WqpA_l, blk*256 + tid, DATTN); return; }
    blk -= 512;
    if (blk < 512){ packA_elem(Wo, g_WoA_h, g_WoA_l, blk*256 + tid, DATTN); return; }
    blk -= 512;
    if (blk < 4096){ packW_elem(Ws1, g_Ws1t_h, g_Ws1t_l, blk*256 + tid, D2); return; }
    blk -= 4096;
    packWpad_elem(Wout, g_WoutP_h, g_WoutP_l, blk*256 + tid, OUT_N, OUT_P);
}
__global__ __launch_bounds__(256) void setup_g1(const float* __restrict__ bf)
{
    __shared__ uint32_t smem[6912];
    const int c = blockIdx.x;
    if (c < 512)      gemm_dev(g_xp_h, g_xp_l, g_Wf_h, g_Wf_l, g_kv, bf, DATTN, DIN, 0, c & 7, c >> 3, smem, (const float*)0);
    else if (c < 576){ const int c2 = c - 512;
                      gemm_dev(g_WqpA_h, g_WqpA_l, g_Wq_h, g_Wq_l, g_Wqpq, (const float*)0, DATTN, DATTN, 0, c2 & 7, c2 >> 3, smem, (const float*)0); }
    else             { const int c2 = c - 576;
                      gemm_dev(g_WoA_h, g_WoA_l, g_Ws1t_h, g_Ws1t_l, g_WbigTop, (const float*)0, D2, DATTN, 0, c2 & 63, c2 >> 6, smem, (const float*)0); }
}
__global__ __launch_bounds__(256) void setup_b(const float* __restrict__ bk,
                                               const float* __restrict__ bv,
                                               const float* __restrict__ Ws1)
{
    __shared__ uint32_t smem[6912];
    int c = blockIdx.x;
    if (c < 512){ gemm_dev((const uint32_t*)0, (const uint32_t*)0, g_Wk_h, g_Wk_l, g_Kt, bk, DATTN, DATTN, 1, c & 7, c >> 3, smem, g_kv); return; }
    c -= 512;
    if (c < 512){ gemm_dev((const uint32_t*)0, (const uint32_t*)0, g_Wv_h, g_Wv_l, g_V, bv, DATTN, DATTN, 2, c & 7, c >> 3, smem, g_kv); return; }
    c -= 512;
    {   const int idx = c*256 + threadIdx.x;
        const int kp = idx / D2, n = idx - kp*D2;
        float v0, v1;
        if (kp < DATTN/2){ v0 = g_WbigTop[(size_t)(2*kp)*D2 + n]; v1 = g_WbigTop[(size_t)(2*kp+1)*D2 + n]; }
        else             { v0 = Ws1[(size_t)(2*kp)*D2 + n];       v1 = Ws1[(size_t)(2*kp+1)*D2 + n]; }
        split2(v0, v1, g_Wbig_h[idx], g_Wbig_l[idx]); }
}

// ---------- entropy ----------
__device__ void dev_entropy(int b, int tid, float* sm, const float* __restrict__ bout,
                            float* __restrict__ out, int tw)
{
    float* pbuf = sm;
    float* r0 = pbuf + 1000;
    float* r1 = r0 + 8;
    float* bc = r1 + 8;
    float mx = -1e30f;
    for (int o = tid; o < OUT_N; o += 256){
        float p = bout[o];
#pragma unroll
        for (int z = 0; z < 4; z++) p += g_ppart[(z*BB + b)*OUT_P + o];
        pbuf[o] = p;
        out[((size_t)(b*OUT_N + o))*TT + tw] = p;
        mx = fmaxf(mx, p);
    }
#pragma unroll
    for (int off = 16; off; off >>= 1) mx = fmaxf(mx, __shfl_xor_sync(0xffffffffu, mx, off));
    if ((tid & 31) == 0) r0[tid >> 5] = mx;
    __syncthreads();
    if (tid == 0){
        float m = r0[0];
        for (int w = 1; w < 8; w++) m = fmaxf(m, r0[w]);
        bc[0] = m;
    }
    __syncthreads();
    mx = bc[0];
    float s0 = 0.f, s1 = 0.f;
    for (int o = tid; o < OUT_N; o += 256){
        const float u = pbuf[o] - mx;
        const float e = __expf(u);
        s0 += e; s1 += u * e;
    }
#pragma unroll
    for (int off = 16; off; off >>= 1){
        s0 += __shfl_xor_sync(0xffffffffu, s0, off);
        s1 += __shfl_xor_sync(0xffffffffu, s1, off);
    }
    if ((tid & 31) == 0){ r0[tid>>5] = s0; r1[tid>>5] = s1; }
    __syncthreads();
    if (tid == 0){
        float t0 = 0.f, t1 = 0.f;
        for (int w = 0; w < 8; w++){ t0 += r0[w]; t1 += r1[w]; }
        const float ne = -(t1 / t0 - logf(t0)) / logf((float)OUT_N);
        out[CERT_OFF + (size_t)(b*2 + 0)*TT + tw] = ne;
        out[CERT_OFF + (size_t)(b*2 + 1)*TT + tw] = 1.f - ne;
    }
}

// ---------- syncO for one batch (256 threads) ----------
__device__ void dev_syncO(int b, int tid, float* sAct,
                          const float* __restrict__ decay_o,
                          const int* __restrict__ idx_lo, const int* __restrict__ idx_ro)
{
#pragma unroll
    for (int k = 0; k < 8; k++) sAct[tid + k*256] = g_act[b*DMODEL + tid + k*256];
    __syncthreads();
    const int i0 = tid * 2, i1 = i0 + 1;
    float v[2];
#pragma unroll
    for (int j = 0; j < 2; j++){
        const int i = i0 + j;
        const float pairing = sAct[idx_lo[i]] * sAct[idx_ro[i]];
        const float r = __expf(-fminf(fmaxf(decay_o[i], 0.f), 15.f));
        const float a = r * g_aO[b*NSYNC+i] + pairing;
        const float bt = r * g_bO[b*NSYNC+i] + 1.f;
        g_aO[b*NSYNC+i] = a; g_bO[b*NSYNC+i] = bt;
        v[j] = a * rsqrtf(bt);
        g_syO[b*NSYNC+i] = v[j];
    }
    uint32_t h, l; split2(v[0], v[1], h, l);
    g_syO_h[b*(NSYNC/2) + tid] = h;
    g_syO_l[b*(NSYNC/2) + tid] = l;
    (void)i1;
}

// ---------- pred (split-K MMA over syO) ----------
__device__ void dev_pred(int nx, int z, uint32_t* smem)
{
    uint32_t* sAh = smem;
    uint32_t* sAl = sAh + 2304;
    uint32_t* sBh = sAl + 2304;
    uint32_t* sBl = sBh + 1152;
    const int tid = threadIdx.x;
    const int nBase = nx * 64;
    const int warp = tid >> 5, lane = tid & 31;
    const int wm = (warp & 3) * 16, wn = (warp >> 2) * 32;
    const int g = lane >> 2, tg = lane & 3;
    float acc[4][4];
#pragma unroll
    for (int t = 0; t < 4; t++){ acc[t][0]=acc[t][1]=acc[t][2]=acc[t][3]=0.f; }

    for (int kk = 0; kk < 128; kk += 32){
        const int kpg = z * 64 + (kk >> 1);
#pragma unroll
        for (int i = 0; i < 4; i++){
            int idx = tid + i * 256;
            int m = idx >> 4, kp = idx & 15;
            sAh[m*36+kp] = g_syO_h[m*(NSYNC/2) + kpg + kp];
            sAl[m*36+kp] = g_syO_l[m*(NSYNC/2) + kpg + kp];
            int kb = idx >> 6, n = idx & 63;
            sBh[kb*72+n] = g_WoutP_h[(size_t)(kpg + kb) * OUT_P + nBase + n];
            sBl[kb*72+n] = g_WoutP_l[(size_t)(kpg + kb) * OUT_P + nBase + n];
        }
        __syncthreads();
#pragma unroll
        for (int s = 0; s < 2; s++){
            const int kb = s * 8;
            uint32_t ah0 = sAh[(wm+g)*36+kb+tg],   ah1 = sAh[(wm+8+g)*36+kb+tg];
            uint32_t ah2 = sAh[(wm+g)*36+kb+4+tg], ah3 = sAh[(wm+8+g)*36+kb+4+tg];
            uint32_t al0 = sAl[(wm+g)*36+kb+tg],   al1 = sAl[(wm+8+g)*36+kb+tg];
            uint32_t al2 = sAl[(wm+g)*36+kb+4+tg], al3 = sAl[(wm+8+g)*36+kb+4+tg];
#pragma unroll
            for (int t = 0; t < 4; t++){
                const int n = wn + t * 8 + g;
                uint32_t bh0 = sBh[(kb+tg)*72+n], bh1 = sBh[(kb+4+tg)*72+n];
                uint32_t bl0 = sBl[(kb+tg)*72+n], bl1 = sBl[(kb+4+tg)*72+n];
                mma16816(acc[t], ah0, ah1, ah2, ah3, bh0, bh1);
                mma16816(acc[t], ah0, ah1, ah2, ah3, bl0, bl1);
                mma16816(acc[t], al0, al1, al2, al3, bh0, bh1);
            }
        }
        __syncthreads();
    }
    const int r0 = wm + g;
#pragma unroll
    for (int t = 0; t < 4; t++){
        const int c = nBase + wn + t * 8 + tg * 2;
#pragma unroll
        for (int hr = 0; hr < 2; hr++){
            const int r = r0 + hr * 8;
            float* p = &g_ppart[((size_t)(z*BB + r)) * OUT_P + c];
            p[0] = acc[t][hr*2+0]; p[1] = acc[t][hr*2+1];
        }
    }
}

// ---------- big GEMM slice ----------
__device__ void dev_big(int nx, int zout, int kp0, int nst, uint32_t* sm)
{
    uint32_t* sAh = sm;
    uint32_t* sAl = sAh + 1280;
    uint32_t* sBh = sAl + 1280;
    uint32_t* sBl = sBh + 2112;
    const int tid = threadIdx.x;
    const int nBase = nx * 128;
    const int warp = tid >> 5, lane = tid & 31;
    const int wm = (warp & 3) * 16, wn = (warp >> 2) * 64;
    const int g = lane >> 2, tg = lane & 3;
    const int arow = tid >> 2, apg = (tid & 3) << 2;
    const int brow = tid >> 5, bc = lane << 2;

    float acc[8][4];
#pragma unroll
    for (int t = 0; t < 8; t++){ acc[t][0]=acc[t][1]=acc[t][2]=acc[t][3]=0.f; }

    uint4 pAh, pAl, pBh0, pBl0, pBh1, pBl1;
    {
        const int kpg = kp0;
        pAh = *reinterpret_cast<const uint4*>(&g_pA_h[arow*(DPRE/2) + kpg + apg]);
        pAl = *reinterpret_cast<const uint4*>(&g_pA_l[arow*(DPRE/2) + kpg + apg]);
        pBh0 = __ldcg(reinterpret_cast<const uint4*>(&g_Wbig_h[(size_t)(kpg+brow  )*D2 + nBase + bc]));
        pBl0 = __ldcg(reinterpret_cast<const uint4*>(&g_Wbig_l[(size_t)(kpg+brow  )*D2 + nBase + bc]));
        pBh1 = __ldcg(reinterpret_cast<const uint4*>(&g_Wbig_h[(size_t)(kpg+brow+8)*D2 + nBase + bc]));
        pBl1 = __ldcg(reinterpret_cast<const uint4*>(&g_Wbig_l[(size_t)(kpg+brow+8)*D2 + nBase + bc]));
    }
    *reinterpret_cast<uint4*>(&sAh[arow*20 + apg]) = pAh;
    *reinterpret_cast<uint4*>(&sAl[arow*20 + apg]) = pAl;
    *reinterpret_cast<uint4*>(&sBh[brow*132 + bc]) = pBh0;
    *reinterpret_cast<uint4*>(&sBl[brow*132 + bc]) = pBl0;
    *reinterpret_cast<uint4*>(&sBh[(brow+8)*132 + bc]) = pBh1;
    *reinterpret_cast<uint4*>(&sBl[(brow+8)*132 + bc]) = pBl1;
    __syncthreads();

    for (int st = 0; st < nst; st++){
        if (st + 1 < nst){
            const int kpg = kp0 + (st+1) * 16;
            pAh = *reinterpret_cast<const uint4*>(&g_pA_h[arow*(DPRE/2) + kpg + apg]);
            pAl = *reinterpret_cast<const uint4*>(&g_pA_l[arow*(DPRE/2) + kpg + apg]);
            pBh0 = __ldcg(reinterpret_cast<const uint4*>(&g_Wbig_h[(size_t)(kpg+brow  )*D2 + nBase + bc]));
            pBl0 = __ldcg(reinterpret_cast<const uint4*>(&g_Wbig_l[(size_t)(kpg+brow  )*D2 + nBase + bc]));
            pBh1 = __ldcg(reinterpret_cast<const uint4*>(&g_Wbig_h[(size_t)(kpg+brow+8)*D2 + nBase + bc]));
            pBl1 = __ldcg(reinterpret_cast<const uint4*>(&g_Wbig_l[(size_t)(kpg+brow+8)*D2 + nBase + bc]));
        }
#pragma unroll
        for (int s = 0; s < 2; s++){
            const int kb = s * 8;
            const uint32_t ah0 = sAh[(wm+g)*20 + kb+tg],   ah1 = sAh[(wm+8+g)*20 + kb+tg];
            const uint32_t ah2 = sAh[(wm+g)*20 + kb+4+tg], ah3 = sAh[(wm+8+g)*20 + kb+4+tg];
            const uint32_t al0 = sAl[(wm+g)*20 + kb+tg],   al1 = sAl[(wm+8+g)*20 + kb+tg];
            const uint32_t al2 = sAl[(wm+g)*20 + kb+4+tg], al3 = sAl[(wm+8+g)*20 + kb+4+tg];
#pragma unroll
            for (int t = 0; t < 8; t++){
                const int n = wn + t * 8 + g;
                const uint32_t bh0 = sBh[(kb+tg)*132 + n], bh1 = sBh[(kb+4+tg)*132 + n];
                const uint32_t bl0 = sBl[(kb+tg)*132 + n], bl1 = sBl[(kb+4+tg)*132 + n];
                mma16816(acc[t], ah0, ah1, ah2, ah3, bh0, bh1);
                mma16816(acc[t], ah0, ah1, ah2, ah3, bl0, bl1);
                mma16816(acc[t], al0, al1, al2, al3, bh0, bh1);
            }
        }
        if (st + 1 < nst){
            __syncthreads();
            *reinterpret_cast<uint4*>(&sAh[arow*20 + apg]) = pAh;
            *reinterpret_cast<uint4*>(&sAl[arow*20 + apg]) = pAl;
            *reinterpret_cast<uint4*>(&sBh[brow*132 + bc]) = pBh0;
            *reinterpret_cast<uint4*>(&sBl[brow*132 + bc]) = pBl0;
            *reinterpret_cast<uint4*>(&sBh[(brow+8)*132 + bc]) = pBh1;
            *reinterpret_cast<uint4*>(&sBl[(brow+8)*132 + bc]) = pBl1;
            __syncthreads();
        }
    }
    const int r0 = wm + g;
#pragma unroll
    for (int t = 0; t < 8; t++){
        const int c = nBase + wn + t * 8 + tg * 2;
#pragma unroll
        for (int hr = 0; hr < 2; hr++){
            const int r = r0 + hr * 8;
            float* p = &g_hpart[((size_t)(zout*64 + r)) * D2 + c];
            p[0] = acc[t][hr*2+0]; p[1] = acc[t][hr*2+1];
        }
    }
}

// ---------- K1: attnq(t) with in-block syncA | syncO(t-1) ----------
// blocks [0,128): attnq (h=blk>>4, bg=blk&15)
// blocks [128,192): syncO(t-1) for b=blk-128 (skip t==0)
__global__ __launch_bounds__(256) void k1_kernel(const float* __restrict__ decay_a,
                                                 const int* __restrict__ idx_la,
                                                 const int* __restrict__ idx_ra,
                                                 const float* __restrict__ decay_o,
                                                 const int* __restrict__ idx_lo,
                                                 const int* __restrict__ idx_ro,
                                                 int tick)
{
    __shared__ __align__(16) uint32_t SMu[6928];
    const int tid = threadIdx.x;
    if (blockIdx.x >= 128){
        if (tick > 0) dev_syncO(blockIdx.x - 128, tid, (float*)SMu, decay_o, idx_lo, idx_ro);
        return;
    }
    float* SM = (float*)SMu;
    float* sA  = SM;              // 4 x 512
    float* sW  = SM + 2048;       // 64 x 68 transposed
    float* qs  = SM + 6400;
    float* ws  = qs + 256;
    float* red = ws + 256;
    const int h = blockIdx.x >> 4, bg = blockIdx.x & 15;
    const int grp = tid >> 6, t = tid & 63;
    const int b = bg * 4 + grp;
    const int buf = tick & 1, nbuf = buf ^ 1;

    // in-block syncA: compute syA for the 4 batches into sA; h==0 commits state
#pragma unroll
    for (int i = 0; i < 8; i++){
        const int idx = tid + i * 256;
        const int bb = bg*4 + (idx >> 9), ii = idx & 511;
        const float pairing = g_act[bb*DMODEL + idx_la[ii]] * g_act[bb*DMODEL + idx_ra[ii]];
        const float r = __expf(-fminf(fmaxf(decay_a[ii], 0.f), 15.f));
        const float a = r * g_aA[buf][bb*NSYNC+ii] + pairing;
        const float bt = r * g_bA[buf][bb*NSYNC+ii] + 1.f;
        sA[idx] = a * rsqrtf(bt);
        if (h == 0){
            g_aA[nbuf][bb*NSYNC+ii] = a;
            g_bA[nbuf][bb*NSYNC+ii] = bt;
        }
    }

    const int col = h * HD + t;
    float a0 = 0.f, a1 = 0.f, a2 = 0.f, a3 = 0.f;
    for (int ch = 0; ch < 8; ch++){
        const int k0 = ch * 64;
        __syncthreads();
#pragma unroll
        for (int i = 0; i < 16; i++){
            const int idx = tid + i * 256;
            const int r = idx >> 6, c = idx & 63;
            sW[c*68 + r] = g_Wqpq[(size_t)(k0 + r) * DATTN + h * HD + c];
        }
        __syncthreads();
        const float* ap = sA + grp * 512 + k0;
        const float4* wp = reinterpret_cast<const float4*>(sW + t * 68);
#pragma unroll
        for (int k = 0; k < 64; k += 4){
            const float4 w = wp[k >> 2];
            a0 += ap[k+0] * w.x;
            a1 += ap[k+1] * w.y;
            a2 += ap[k+2] * w.z;
            a3 += ap[k+3] * w.w;
        }
    }
    __syncthreads();
    qs[grp*64 + t] = (a0 + a1) + (a2 + a3) + g_bq2[col];
    __syncthreads();

    const float* ktp = &g_Kt[((b*HEADS + h)*HD) * SS + t];
    float sc = 0.f;
#pragma unroll
    for (int d = 0; d < HD; d++) sc += qs[grp*64 + d] * ktp[d*SS];
    sc *= 0.125f;

    float mx = sc;
#pragma unroll
    for (int off = 16; off; off >>= 1) mx = fmaxf(mx, __shfl_xor_sync(0xffffffffu, mx, off));
    if ((t & 31) == 0) red[grp*4 + (t >> 5)] = mx;
    __syncthreads();
    mx = fmaxf(red[grp*4 + 0], red[grp*4 + 1]);
    const float e = __expf(sc - mx);
    float smv = e;
#pragma unroll
    for (int off = 16; off; off >>= 1) smv += __shfl_xor_sync(0xffffffffu, smv, off);
    if ((t & 31) == 0) red[grp*4 + 2 + (t >> 5)] = smv;
    __syncthreads();
    smv = red[grp*4 + 2] + red[grp*4 + 3];
    ws[grp*64 + t] = e / smv;
    __syncthreads();

    const float* vp = &g_V[((b*HEADS + h)*SS) * HD + t];
    float ao = 0.f;
#pragma unroll
    for (int s = 0; s < SS; s++) ao += ws[grp*64 + s] * vp[s*HD];

    const float an = __shfl_down_sync(0xffffffffu, ao, 1);
    if (!(t & 1)){
        uint32_t hi, lo; split2(ao, an, hi, lo);
        const int kp = (h*HD + t) >> 1;
        g_pA_h[b*(DPRE/2) + kp] = hi; g_pA_l[b*(DPRE/2) + kp] = lo;
    }
}

// ---------- K2: big(t) | pred(t-1) ----------
// blocks [0,128): big (nx=blk&31, z=blk>>5, kp0=z*320, 20 stages)
// blocks [128,192): pred(t-1) (skip t==0)
__global__ __launch_bounds__(256) void k2_kernel(int tick)
{
    __shared__ __align__(16) uint32_t sm[6928];
    if (blockIdx.x >= 128){
        if (tick > 0){
            const int r = blockIdx.x - 128;
            dev_pred(r & 15, r >> 4, sm);
        }
        return;
    }
    const int nx = blockIdx.x & 31, z = blockIdx.x >> 5;
    dev_big(nx, z, z * 320, 20, sm);
}

// ---------- K3: glu(t) | entropy(t-1) ----------
__global__ __launch_bounds__(256) void glu_ent_kernel(const float* __restrict__ ln_g,
                                                      const float* __restrict__ ln_b,
                                                      const float* __restrict__ bout,
                                                      float* __restrict__ out, int tick)
{
    __shared__ float SM[2080];
    const int tid = threadIdx.x;
    if (blockIdx.x >= 64){
        if (tick > 0) dev_entropy(blockIdx.x - 64, tid, SM, bout, out, tick - 1);
        return;
    }
    float* gbuf = SM;
    float* rs   = SM + DMODEL;
    float* ms   = rs + 16;
    const int b = blockIdx.x;
    float s = 0.f, s2 = 0.f;
    for (int j = tid; j < DMODEL; j += 256){
        float h1 = g_bs1c[j], h2 = g_bs1c[j + DMODEL];
#pragma unroll
        for (int z = 0; z < KSPLIT; z++){
            h1 += g_hpart[(size_t)(z*64 + b)*D2 + j];
            h2 += g_hpart[(size_t)(z*64 + b)*D2 + j + DMODEL];
        }
        const float gv = h1 / (1.f + __expf(-h2));
        gbuf[j] = gv; s += gv; s2 += gv*gv;
    }
#pragma unroll
    for (int off = 16; off; off >>= 1){
        s  += __shfl_xor_sync(0xffffffffu, s,  off);
        s2 += __shfl_xor_sync(0xffffffffu, s2, off);
    }
    if ((tid & 31) == 0){ rs[tid>>5] = s; rs[8 + (tid>>5)] = s2; }
    __syncthreads();
    if (tid == 0){
        float ts = 0.f, ts2 = 0.f;
        for (int w = 0; w < 8; w++){ ts += rs[w]; ts2 += rs[8+w]; }
        const float mu = ts / (float)DMODEL;
        ms[0] = mu; ms[1] = rsqrtf(ts2 / (float)DMODEL - mu*mu + 1e-5f);
    }
    __syncthreads();
    const int slot = tick % MM;
    const float mu = ms[0], inv = ms[1];
    for (int j = tid; j < DMODEL; j += 256)
        g_trace[((size_t)(b*DMODEL + j)) * MP + slot] = (gbuf[j] - mu) * inv * ln_g[j] + ln_b[j];
}

__global__ __launch_bounds__(256) void nlm_kernel(const float* __restrict__ nw1,
                                                  const float* __restrict__ nb1,
                                                  const float* __restrict__ nw2,
                                                  const float* __restrict__ nb2, int tick)
{
    __shared__ float w1s[3200], b1s[128], w2s[128], sAct[256];
    const int cta = blockIdx.x, tid = threadIdx.x;
    const int d0 = cta * 16;
    const int b = tid & 63, dsub = tid >> 6;
    const int o = (tick + 1) % MM;

    for (int p = 0; p < 4; p++){
        const int dbase = d0 + p * 4;
        __syncthreads();
        for (int i = tid; i < 3200; i += 256) w1s[i] = nw1[(size_t)dbase*800 + i];
        if (tid < 128){ b1s[tid] = nb1[dbase*32 + tid]; w2s[tid] = nw2[dbase*32 + tid]; }
        __syncthreads();

        const int d = dbase + dsub;
        float tr[MM];
        const float* tp = &g_trace[((size_t)(b*DMODEL + d)) * MP];
#pragma unroll
        for (int m = 0; m < MM; m++){ int s = o + m; if (s >= MM) s -= MM; tr[m] = tp[s]; }

        const float* w1p = w1s + dsub * 800;
        float ov = 0.f;
#pragma unroll
        for (int h = 0; h < 32; h += 4){
            float4 s4 = *reinterpret_cast<const float4*>(&b1s[dsub*32 + h]);
#pragma unroll
            for (int m = 0; m < MM; m++){
                const float4 w = *reinterpret_cast<const float4*>(&w1p[m*32 + h]);
                s4.x += tr[m]*w.x; s4.y += tr[m]*w.y; s4.z += tr[m]*w.z; s4.w += tr[m]*w.w;
            }
            const float4 w2v = *reinterpret_cast<const float4*>(&w2s[dsub*32 + h]);
            ov += gelu_f(s4.x)*w2v.x + gelu_f(s4.y)*w2v.y + gelu_f(s4.z)*w2v.z + gelu_f(s4.w)*w2v.w;
        }
        const float a = ov + nb2[d];
        g_act[b*DMODEL + d] = a;
        sAct[dsub*64 + b] = a;
        __syncthreads();
        if (tid < 128){
            const int pi = tid >> 6, bb = tid & 63;
            const float v0 = sAct[(2*pi)*64 + bb], v1 = sAct[(2*pi+1)*64 + bb];
            uint32_t hi, lo; split2(v0, v1, hi, lo);
            const int kp = (DATTN + dbase + 2*pi) >> 1;
            g_pA_h[bb*(DPRE/2) + kp] = hi; g_pA_l[bb*(DPRE/2) + kp] = lo;
        }
    }
}

// ---------- tails ----------
__global__ __launch_bounds__(256) void tail_syncO(const float* __restrict__ decay_o,
                                                  const int* __restrict__ idx_lo,
                                                  const int* __restrict__ idx_ro)
{
    __shared__ float sAct[DMODEL];
    dev_syncO(blockIdx.x, threadIdx.x, sAct, decay_o, idx_lo, idx_ro);
}
__global__ __launch_bounds__(256) void predtail_kernel()
{
    __shared__ __align__(16) uint32_t smem[6928];
    dev_pred((int)blockIdx.x, (int)blockIdx.y, smem);
}
__global__ __launch_bounds__(256) void fin_kernel(const float* __restrict__ bout,
                                                  float* __restrict__ out)
{
    __shared__ float SM[1024];
    const int blk = blockIdx.x, tid = threadIdx.x;
    if (blk < 64){ dev_entropy(blk, tid, SM, bout, out, TT - 1); return; }
    const int i = (blk - 64) * 256 + tid;
    out[SYO_OFF + i] = g_syO[i];
}

// ---------- launch ----------
extern "C" void kernel_launch(void* const* d_in, const int* in_sizes, int n_in,
                              void* d_out, int out_size)
{
    const float* x   = (const float*)d_in[0];
    const float* Wf  = (const float*)d_in[1];
    const float* bf  = (const float*)d_in[2];
    const float* start_trace = (const float*)d_in[3];
    const float* start_state = (const float*)d_in[4];
    const float* decay_a = (const float*)d_in[5];
    const float* decay_o = (const float*)d_in[6];
    const float* Wqp = (const float*)d_in[7];
    const float* bqp = (const float*)d_in[8];
    const float* Wq  = (const float*)d_in[9];
    const float* bq  = (const float*)d_in[10];
    const float* Wk  = (const float*)d_in[11];
    const float* bk  = (const float*)d_in[12];
    const float* Wv  = (const float*)d_in[13];
    const float* bv  = (const float*)d_in[14];
    const float* Wo  = (const float*)d_in[15];
    const float* bo  = (const float*)d_in[16];
    const float* Ws1 = (const float*)d_in[17];
    const float* bs1 = (const float*)d_in[18];
    const float* ln_g = (const float*)d_in[19];
    const float* ln_b = (const float*)d_in[20];
    const float* nw1 = (const float*)d_in[21];
    const float* nb1 = (const float*)d_in[22];
    const float* nw2 = (const float*)d_in[23];
    const float* nb2 = (const float*)d_in[24];
    const float* Wout = (const float*)d_in[25];
    const float* bout = (const float*)d_in[26];
    const int* idx_la = (const int*)d_in[27];
    const int* idx_ra = (const int*)d_in[28];
    const int* idx_lo = (const int*)d_in[29];
    const int* idx_ro = (const int*)d_in[30];
    float* out = (float*)d_out;

    setup_a<<<13376, 256>>>(x, Wf, Wk, Wv, Wq, Wqp, Wo, Ws1, Wout,
                            bqp, bq, bo, bs1, start_trace, start_state, idx_lo, idx_ro);
    setup_g1<<<1088, 256>>>(bf);
    setup_b<<<21504, 256>>>(bk, bv, Ws1);

    for (int t = 0; t < TT; t++){
        k1_kernel<<<192, 256>>>(decay_a, idx_la, idx_ra, decay_o, idx_lo, idx_ro, t);
        k2_kernel<<<192, 256>>>(t);
        glu_ent_kernel<<<128, 256>>>(ln_g, ln_b, bout, out, t);
        nlm_kernel<<<128, 256>>>(nw1, nb1, nw2, nb2, t);
    }
    tail_syncO<<<64, 256>>>(decay_o, idx_lo, idx_ro);
    predtail_kernel<<<dim3(16, 4), 256>>>();
    fin_kernel<<<192, 256>>>(bout, out);
    (void)in_sizes; (void)n_in; (void)out_size;
}

// round 14
// speedup vs baseline: 1.0228x; 1.0022x over previous
#include <cuda_runtime.h>
#include <cuda_bf16.h>
#include <cstdint>

#define BB 64
#define SS 64
#define DIN 512
#define DATTN 512
#define DMODEL 2048
#define MM 25
#define MP 32
#define HEADS 8
#define HD 64
#define NSYNC 512
#define OUT_N 1000
#define OUT_P 1024
#define TT 50
#define DPRE 2560
#define D2 4096
#define KSPLIT 4

#define PRED_SZ (BB*OUT_N*TT)
#define CERT_OFF (PRED_SZ)
#define SYO_OFF (PRED_SZ + BB*2*TT)

// ---------- scratch ----------
__device__ float g_kv[BB*SS*DATTN];
__device__ float g_Kt[BB*HEADS*HD*SS];
__device__ float g_V [BB*HEADS*SS*HD];
__device__ float g_Wqpq[NSYNC*DATTN];
__device__ float g_WbigTop[DATTN*D2];
__device__ float g_bq2[DATTN];
__device__ float g_bs1c[D2];
__device__ float g_act[BB*DMODEL];
__device__ float g_trace[BB*DMODEL*MP];
__device__ float g_aA[2][BB*NSYNC];
__device__ float g_aO[BB*NSYNC], g_syO[BB*NSYNC];
__device__ float g_rA[NSYNC], g_rO[NSYNC];
__device__ float g_cA[TT*NSYNC], g_cO[TT*NSYNC];
__device__ float g_hpart[KSPLIT*BB*D2];
__device__ float g_ppart[4*BB*OUT_P];
// packed bf16 hi/lo
__device__ uint32_t g_xp_h[(BB*SS)*(DIN/2)],  g_xp_l[(BB*SS)*(DIN/2)];
__device__ uint32_t g_Wf_h[(DIN/2)*DATTN],  g_Wf_l[(DIN/2)*DATTN];
__device__ uint32_t g_Wk_h[(DATTN/2)*DATTN], g_Wk_l[(DATTN/2)*DATTN];
__device__ uint32_t g_Wv_h[(DATTN/2)*DATTN], g_Wv_l[(DATTN/2)*DATTN];
__device__ uint32_t g_Wq_h[(DATTN/2)*DATTN], g_Wq_l[(DATTN/2)*DATTN];
__device__ uint32_t g_WqpA_h[NSYNC*(DATTN/2)], g_WqpA_l[NSYNC*(DATTN/2)];
__device__ uint32_t g_WoA_h[DATTN*(DATTN/2)], g_WoA_l[DATTN*(DATTN/2)];
__device__ uint32_t g_Ws1t_h[(DATTN/2)*D2], g_Ws1t_l[(DATTN/2)*D2];
__device__ uint32_t g_Wbig_h[(DPRE/2)*D2], g_Wbig_l[(DPRE/2)*D2];
__device__ uint32_t g_WoutP_h[(NSYNC/2)*OUT_P], g_WoutP_l[(NSYNC/2)*OUT_P];
__device__ uint32_t g_pA_h[BB*(DPRE/2)], g_pA_l[BB*(DPRE/2)];
__device__ uint32_t g_syO_h[BB*(NSYNC/2)], g_syO_l[BB*(NSYNC/2)];

// ---------- helpers ----------
__device__ __forceinline__ uint32_t bfpair(float a, float b){
    __nv_bfloat162 t = __floats2bfloat162_rn(a, b);
    return *reinterpret_cast<uint32_t*>(&t);
}
__device__ __forceinline__ void split2(float v0, float v1, uint32_t& hi, uint32_t& lo){
    float h0 = __bfloat162float(__float2bfloat16(v0));
    float h1 = __bfloat162float(__float2bfloat16(v1));
    hi = bfpair(h0, h1);
    lo = bfpair(v0 - h0, v1 - h1);
}
__device__ __forceinline__ void mma16816(float* c, uint32_t a0, uint32_t a1,
                                         uint32_t a2, uint32_t a3, uint32_t b0, uint32_t b1){
    asm volatile("mma.sync.aligned.m16n8k16.row.col.f32.bf16.bf16.f32 "
        "{%0,%1,%2,%3},{%4,%5,%6,%7},{%8,%9},{%0,%1,%2,%3};"
        : "+f"(c[0]), "+f"(c[1]), "+f"(c[2]), "+f"(c[3])
        : "r"(a0), "r"(a1), "r"(a2), "r"(a3), "r"(b0), "r"(b1));
}
__device__ __forceinline__ float gelu_f(float x){
    float z = 0.7978845608028654f * (x + 0.044715f * x*x*x);
    float ee = __expf(-2.f * fabsf(z));
    float th = copysignf((1.f - ee) / (1.f + ee), z);
    return 0.5f * x * (1.f + th);
}
__device__ __forceinline__ void packA_elem(const float* __restrict__ src,
                                           uint32_t* __restrict__ h, uint32_t* __restrict__ l,
                                           int idx, int K){
    const int Kh = K >> 1;
    const int m = idx / Kh, kp = idx - m * Kh;
    split2(src[(size_t)m*K + 2*kp], src[(size_t)m*K + 2*kp + 1], h[idx], l[idx]);
}
__device__ __forceinline__ void packW_elem(const float* __restrict__ src,
                                           uint32_t* __restrict__ h, uint32_t* __restrict__ l,
                                           int idx, int N){
    const int kp = idx / N, n = idx - kp * N;
    split2(src[(size_t)(2*kp)*N + n], src[(size_t)(2*kp+1)*N + n], h[idx], l[idx]);
}
__device__ __forceinline__ void packWpad_elem(const float* __restrict__ src,
                                              uint32_t* __restrict__ h, uint32_t* __restrict__ l,
                                              int idx, int Ns, int Nd){
    const int kp = idx / Nd, n = idx - kp * Nd;
    const float v0 = (n < Ns) ? src[(size_t)(2*kp)*Ns + n] : 0.f;
    const float v1 = (n < Ns) ? src[(size_t)(2*kp+1)*Ns + n] : 0.f;
    split2(v0, v1, h[idx], l[idx]);
}

// ---------- setup GEMM core ----------
__device__ void gemm_dev(const uint32_t* __restrict__ Ah, const uint32_t* __restrict__ Al,
                         const uint32_t* __restrict__ Wh, const uint32_t* __restrict__ Wl,
                         float* __restrict__ C, const float* __restrict__ bias,
                         int N, int K, int epi, int bx, int by, uint32_t* smem, const float* Af32)
{
    uint32_t* sAh = smem;
    uint32_t* sAl = sAh + 2304;
    uint32_t* sBh = sAl + 2304;
    uint32_t* sBl = sBh + 1152;
    const int tid = threadIdx.x;
    const int nBase = bx * 64, rowBase = by * 64;
    const int Kh = K >> 1;
    const int warp = tid >> 5, lane = tid & 31;
    const int wm = (warp & 3) * 16, wn = (warp >> 2) * 32;
    const int g = lane >> 2, tg = lane & 3;
    float acc[4][4];
#pragma unroll
    for (int t = 0; t < 4; t++){ acc[t][0]=acc[t][1]=acc[t][2]=acc[t][3]=0.f; }

    for (int kk = 0; kk < K; kk += 32){
        const int kpg = kk >> 1;
#pragma unroll
        for (int i = 0; i < 4; i++){
            int idx = tid + i * 256;
            int m = idx >> 4, kp = idx & 15;
            if (Af32){
                const float2 av = *reinterpret_cast<const float2*>(
                    &Af32[(size_t)(rowBase + m) * K + (kpg + kp) * 2]);
                split2(av.x, av.y, sAh[m*36+kp], sAl[m*36+kp]);
            } else {
                sAh[m*36+kp] = Ah[(size_t)(rowBase + m) * Kh + kpg + kp];
                sAl[m*36+kp] = Al[(size_t)(rowBase + m) * Kh + kpg + kp];
            }
            int kb = idx >> 6, n = idx & 63;
            sBh[kb*72+n] = Wh[(size_t)(kpg + kb) * N + nBase + n];
            sBl[kb*72+n] = Wl[(size_t)(kpg + kb) * N + nBase + n];
        }
        __syncthreads();
#pragma unroll
        for (int s = 0; s < 2; s++){
            const int kb = s * 8;
            uint32_t ah0 = sAh[(wm+g)*36+kb+tg],   ah1 = sAh[(wm+8+g)*36+kb+tg];
            uint32_t ah2 = sAh[(wm+g)*36+kb+4+tg], ah3 = sAh[(wm+8+g)*36+kb+4+tg];
            uint32_t al0 = sAl[(wm+g)*36+kb+tg],   al1 = sAl[(wm+8+g)*36+kb+tg];
            uint32_t al2 = sAl[(wm+g)*36+kb+4+tg], al3 = sAl[(wm+8+g)*36+kb+4+tg];
#pragma unroll
            for (int t = 0; t < 4; t++){
                const int n = wn + t * 8 + g;
                uint32_t bh0 = sBh[(kb+tg)*72+n], bh1 = sBh[(kb+4+tg)*72+n];
                uint32_t bl0 = sBl[(kb+tg)*72+n], bl1 = sBl[(kb+4+tg)*72+n];
                mma16816(acc[t], ah0, ah1, ah2, ah3, bh0, bh1);
                mma16816(acc[t], ah0, ah1, ah2, ah3, bl0, bl1);
                mma16816(acc[t], al0, al1, al2, al3, bh0, bh1);
            }
        }
        __syncthreads();
    }
    const int r0 = rowBase + wm + g;
#pragma unroll
    for (int t = 0; t < 4; t++){
        const int c = nBase + wn + t * 8 + tg * 2;
#pragma unroll
        for (int hr = 0; hr < 2; hr++){
            const int r = r0 + hr * 8;
            const float v0 = acc[t][hr*2+0], v1 = acc[t][hr*2+1];
            if (epi == 0){
                C[(size_t)r*N + c]   = v0 + (bias ? bias[c]   : 0.f);
                C[(size_t)r*N + c+1] = v1 + (bias ? bias[c+1] : 0.f);
            } else if (epi == 1){
                const int b = r >> 6, srow = r & 63, h = c >> 6, d = c & 63;
                C[((b*HEADS+h)*HD + d  )*SS + srow] = v0 + bias[c];
                C[((b*HEADS+h)*HD + d+1)*SS + srow] = v1 + bias[c+1];
            } else {
                const int b = r >> 6, srow = r & 63, h = c >> 6, d = c & 63;
                C[((b*HEADS+h)*SS + srow)*HD + d  ] = v0 + bias[c];
                C[((b*HEADS+h)*SS + srow)*HD + d+1] = v1 + bias[c+1];
            }
        }
    }
}

// ---------- setup kernels ----------
__global__ void setup_a(const float* __restrict__ x,  const float* __restrict__ Wf,
                        const float* __restrict__ Wk, const float* __restrict__ Wv,
                        const float* __restrict__ Wq, const float* __restrict__ Wqp,
                        const float* __restrict__ Wo, const float* __restrict__ Ws1,
                        const float* __restrict__ Wout,
                        const float* __restrict__ bqp, const float* __restrict__ bq,
                        const float* __restrict__ bo,  const float* __restrict__ bs1,
                        const float* __restrict__ start_trace, const float* __restrict__ start_state,
                        const int* __restrict__ idx_lo, const int* __restrict__ idx_ro,
                        const float* __restrict__ decay_a, const float* __restrict__ decay_o)
{
    int blk = blockIdx.x;
    const int tid = threadIdx.x;
    if (blk < 2){   // decay tables: 512 sync units over 2 blocks
        const int i = blk*256 + tid;
        const float ra = __expf(-fminf(fmaxf(decay_a[i], 0.f), 15.f));
        const float ro = __expf(-fminf(fmaxf(decay_o[i], 0.f), 15.f));
        g_rA[i] = ra; g_rO[i] = ro;
        float bA = 0.f, bO = 1.f;
        for (int t = 0; t < TT; t++){
            bA = ra * bA + 1.f;
            bO = ro * bO + 1.f;
            g_cA[t*NSYNC + i] = rsqrtf(bA);
            g_cO[t*NSYNC + i] = rsqrtf(bO);
        }
        return;
    }
    blk -= 2;
    if (blk < 64){
        const int col = blk*8 + (tid >> 5), lane = tid & 31;
        float acc = 0.f;
#pragma unroll 16
        for (int i = 0; i < 16; i++){
            const int k = lane + i*32;
            acc += bqp[k] * Wq[(size_t)k*DATTN + col];
        }
#pragma unroll
        for (int off = 16; off; off >>= 1) acc += __shfl_xor_sync(0xffffffffu, acc, off);
        if (lane == 0) g_bq2[col] = acc + bq[col];
        return;
    }
    blk -= 64;
    if (blk < 512){
        const int col = blk*8 + (tid >> 5), lane = tid & 31;
        float acc = 0.f;
#pragma unroll 16
        for (int i = 0; i < 16; i++){
            const int k = lane + i*32;
            acc += bo[k] * Ws1[(size_t)k*D2 + col];
        }
#pragma unroll
        for (int off = 16; off; off >>= 1) acc += __shfl_xor_sync(0xffffffffu, acc, off);
        if (lane == 0) g_bs1c[col] = acc + bs1[col];
        return;
    }
    blk -= 512;
    if (blk < 512){
        const int idx = blk*256 + tid;
        const int b = idx / DMODEL, d = idx - b * DMODEL;
        const float s0 = start_state[d];
        g_act[idx] = s0;
        if (!(d & 1)){
            uint32_t h, l; split2(s0, start_state[d+1], h, l);
            const int kp = (DATTN + d) >> 1;
            g_pA_h[b*(DPRE/2) + kp] = h; g_pA_l[b*(DPRE/2) + kp] = l;
        }
#pragma unroll
        for (int m = 0; m < MP; m++)
            g_trace[(size_t)idx * MP + m] = (m < MM) ? start_trace[d*MM + m] : 0.f;
        if (d < NSYNC){
            g_aA[0][b*NSYNC + d] = 0.f;
            g_aO[b*NSYNC + d] = start_state[idx_lo[d]] * start_state[idx_ro[d]];
        }
        return;
    }
    blk -= 512;
    if (blk < 4096){ packA_elem(x, g_xp_h, g_xp_l, blk*256 + tid, DIN); return; }
    blk -= 4096;
    if (blk < 512){ packW_elem(Wf, g_Wf_h, g_Wf_l, blk*256 + tid, DATTN); return; }
    blk -= 512;
    if (blk < 512){ packW_elem(Wk, g_Wk_h, g_Wk_l, blk*256 + tid, DATTN); return; }
    blk -= 512;
    if (blk < 512){ packW_elem(Wv, g_Wv_h, g_Wv_l, blk*256 + tid, DATTN); return; }
    blk -= 512;
    if (blk < 512){ packW_elem(Wq, g_Wq_h, g_Wq_l, blk*256 + tid, DATTN); return; }
    blk -= 512;
    if (blk < 512){ packA_elem(Wqp, g_WqpA_h, g_WqpA_l, blk*256 + tid, DATTN); return; }
    blk -= 512;
    if (blk < 512){ packA_elem(Wo, g_WoA_h, g_WoA_l, blk*256 + tid, DATTN); return; }
    blk -= 512;
    if (blk < 4096){ packW_elem(Ws1, g_Ws1t_h, g_Ws1t_l, blk*256 + tid, D2); return; }
    blk -= 4096;
    packWpad_elem(Wout, g_WoutP_h, g_WoutP_l, blk*256 + tid, OUT_N, OUT_P);
}
__global__ __launch_bounds__(256) void setup_g1(const float* __restrict__ bf)
{
    __shared__ uint32_t smem[6912];
    const int c = blockIdx.x;
    if (c < 512)      gemm_dev(g_xp_h, g_xp_l, g_Wf_h, g_Wf_l, g_kv, bf, DATTN, DIN, 0, c & 7, c >> 3, smem, (const float*)0);
    else if (c < 576){ const int c2 = c - 512;
                      gemm_dev(g_WqpA_h, g_WqpA_l, g_Wq_h, g_Wq_l, g_Wqpq, (const float*)0, DATTN, DATTN, 0, c2 & 7, c2 >> 3, smem, (const float*)0); }
    else             { const int c2 = c - 576;
                      gemm_dev(g_WoA_h, g_WoA_l, g_Ws1t_h, g_Ws1t_l, g_WbigTop, (const float*)0, D2, DATTN, 0, c2 & 63, c2 >> 6, smem, (const float*)0); }
}
__global__ __launch_bounds__(256) void setup_b(const float* __restrict__ bk,
                                               const float* __restrict__ bv,
                                               const float* __restrict__ Ws1)
{
    __shared__ uint32_t smem[6912];
    int c = blockIdx.x;
    if (c < 512){ gemm_dev((const uint32_t*)0, (const uint32_t*)0, g_Wk_h, g_Wk_l, g_Kt, bk, DATTN, DATTN, 1, c & 7, c >> 3, smem, g_kv); return; }
    c -= 512;
    if (c < 512){ gemm_dev((const uint32_t*)0, (const uint32_t*)0, g_Wv_h, g_Wv_l, g_V, bv, DATTN, DATTN, 2, c & 7, c >> 3, smem, g_kv); return; }
    c -= 512;
    {   const int idx = c*256 + threadIdx.x;
        const int kp = idx / D2, n = idx - kp*D2;
        float v0, v1;
        if (kp < DATTN/2){ v0 = g_WbigTop[(size_t)(2*kp)*D2 + n]; v1 = g_WbigTop[(size_t)(2*kp+1)*D2 + n]; }
        else             { v0 = Ws1[(size_t)(2*kp)*D2 + n];       v1 = Ws1[(size_t)(2*kp+1)*D2 + n]; }
        split2(v0, v1, g_Wbig_h[idx], g_Wbig_l[idx]); }
}

// ---------- entropy ----------
__device__ void dev_entropy(int b, int tid, float* sm, const float* __restrict__ bout,
                            float* __restrict__ out, int tw)
{
    float* pbuf = sm;
    float* r0 = pbuf + 1000;
    float* r1 = r0 + 8;
    float* bc = r1 + 8;
    float mx = -1e30f;
    for (int o = tid; o < OUT_N; o += 256){
        float p = bout[o];
#pragma unroll
        for (int z = 0; z < 4; z++) p += g_ppart[(z*BB + b)*OUT_P + o];
        pbuf[o] = p;
        out[((size_t)(b*OUT_N + o))*TT + tw] = p;
        mx = fmaxf(mx, p);
    }
#pragma unroll
    for (int off = 16; off; off >>= 1) mx = fmaxf(mx, __shfl_xor_sync(0xffffffffu, mx, off));
    if ((tid & 31) == 0) r0[tid >> 5] = mx;
    __syncthreads();
    if (tid == 0){
        float m = r0[0];
        for (int w = 1; w < 8; w++) m = fmaxf(m, r0[w]);
        bc[0] = m;
    }
    __syncthreads();
    mx = bc[0];
    float s0 = 0.f, s1 = 0.f;
    for (int o = tid; o < OUT_N; o += 256){
        const float u = pbuf[o] - mx;
        const float e = __expf(u);
        s0 += e; s1 += u * e;
    }
#pragma unroll
    for (int off = 16; off; off >>= 1){
        s0 += __shfl_xor_sync(0xffffffffu, s0, off);
        s1 += __shfl_xor_sync(0xffffffffu, s1, off);
    }
    if ((tid & 31) == 0){ r0[tid>>5] = s0; r1[tid>>5] = s1; }
    __syncthreads();
    if (tid == 0){
        float t0 = 0.f, t1 = 0.f;
        for (int w = 0; w < 8; w++){ t0 += r0[w]; t1 += r1[w]; }
        const float ne = -(t1 / t0 - logf(t0)) / logf((float)OUT_N);
        out[CERT_OFF + (size_t)(b*2 + 0)*TT + tw] = ne;
        out[CERT_OFF + (size_t)(b*2 + 1)*TT + tw] = 1.f - ne;
    }
}

// ---------- syncO for one batch (256 threads), tick tw ----------
__device__ void dev_syncO(int b, int tid, float* sAct, int tw,
                          const int* __restrict__ idx_lo, const int* __restrict__ idx_ro)
{
#pragma unroll
    for (int k = 0; k < 8; k++) sAct[tid + k*256] = g_act[b*DMODEL + tid + k*256];
    __syncthreads();
    const int i0 = tid * 2;
    float v[2];
#pragma unroll
    for (int j = 0; j < 2; j++){
        const int i = i0 + j;
        const float pairing = sAct[idx_lo[i]] * sAct[idx_ro[i]];
        const float a = g_rO[i] * g_aO[b*NSYNC+i] + pairing;
        g_aO[b*NSYNC+i] = a;
        v[j] = a * g_cO[tw*NSYNC + i];
        g_syO[b*NSYNC+i] = v[j];
    }
    uint32_t h, l; split2(v[0], v[1], h, l);
    g_syO_h[b*(NSYNC/2) + tid] = h;
    g_syO_l[b*(NSYNC/2) + tid] = l;
}

// ---------- pred (split-K MMA over syO) ----------
__device__ void dev_pred(int nx, int z, uint32_t* smem)
{
    uint32_t* sAh = smem;
    uint32_t* sAl = sAh + 2304;
    uint32_t* sBh = sAl + 2304;
    uint32_t* sBl = sBh + 1152;
    const int tid = threadIdx.x;
    const int nBase = nx * 64;
    const int warp = tid >> 5, lane = tid & 31;
    const int wm = (warp & 3) * 16, wn = (warp >> 2) * 32;
    const int g = lane >> 2, tg = lane & 3;
    float acc[4][4];
#pragma unroll
    for (int t = 0; t < 4; t++){ acc[t][0]=acc[t][1]=acc[t][2]=acc[t][3]=0.f; }

    for (int kk = 0; kk < 128; kk += 32){
        const int kpg = z * 64 + (kk >> 1);
#pragma unroll
        for (int i = 0; i < 4; i++){
            int idx = tid + i * 256;
            int m = idx >> 4, kp = idx & 15;
            sAh[m*36+kp] = g_syO_h[m*(NSYNC/2) + kpg + kp];
            sAl[m*36+kp] = g_syO_l[m*(NSYNC/2) + kpg + kp];
            int kb = idx >> 6, n = idx & 63;
            sBh[kb*72+n] = g_WoutP_h[(size_t)(kpg + kb) * OUT_P + nBase + n];
            sBl[kb*72+n] = g_WoutP_l[(size_t)(kpg + kb) * OUT_P + nBase + n];
        }
        __syncthreads();
#pragma unroll
        for (int s = 0; s < 2; s++){
            const int kb = s * 8;
            uint32_t ah0 = sAh[(wm+g)*36+kb+tg],   ah1 = sAh[(wm+8+g)*36+kb+tg];
            uint32_t ah2 = sAh[(wm+g)*36+kb+4+tg], ah3 = sAh[(wm+8+g)*36+kb+4+tg];
            uint32_t al0 = sAl[(wm+g)*36+kb+tg],   al1 = sAl[(wm+8+g)*36+kb+tg];
            uint32_t al2 = sAl[(wm+g)*36+kb+4+tg], al3 = sAl[(wm+8+g)*36+kb+4+tg];
#pragma unroll
            for (int t = 0; t < 4; t++){
                const int n = wn + t * 8 + g;
                uint32_t bh0 = sBh[(kb+tg)*72+n], bh1 = sBh[(kb+4+tg)*72+n];
                uint32_t bl0 = sBl[(kb+tg)*72+n], bl1 = sBl[(kb+4+tg)*72+n];
                mma16816(acc[t], ah0, ah1, ah2, ah3, bh0, bh1);
                mma16816(acc[t], ah0, ah1, ah2, ah3, bl0, bl1);
                mma16816(acc[t], al0, al1, al2, al3, bh0, bh1);
            }
        }
        __syncthreads();
    }
    const int r0 = wm + g;
#pragma unroll
    for (int t = 0; t < 4; t++){
        const int c = nBase + wn + t * 8 + tg * 2;
#pragma unroll
        for (int hr = 0; hr < 2; hr++){
            const int r = r0 + hr * 8;
            float* p = &g_ppart[((size_t)(z*BB + r)) * OUT_P + c];
            p[0] = acc[t][hr*2+0]; p[1] = acc[t][hr*2+1];
        }
    }
}

// ---------- big GEMM slice ----------
__device__ void dev_big(int nx, int zout, int kp0, int nst, uint32_t* sm)
{
    uint32_t* sAh = sm;
    uint32_t* sAl = sAh + 1280;
    uint32_t* sBh = sAl + 1280;
    uint32_t* sBl = sBh + 2112;
    const int tid = threadIdx.x;
    const int nBase = nx * 128;
    const int warp = tid >> 5, lane = tid & 31;
    const int wm = (warp & 3) * 16, wn = (warp >> 2) * 64;
    const int g = lane >> 2, tg = lane & 3;
    const int arow = tid >> 2, apg = (tid & 3) << 2;
    const int brow = tid >> 5, bc = lane << 2;

    float acc[8][4];
#pragma unroll
    for (int t = 0; t < 8; t++){ acc[t][0]=acc[t][1]=acc[t][2]=acc[t][3]=0.f; }

    uint4 pAh, pAl, pBh0, pBl0, pBh1, pBl1;
    {
        const int kpg = kp0;
        pAh = *reinterpret_cast<const uint4*>(&g_pA_h[arow*(DPRE/2) + kpg + apg]);
        pAl = *reinterpret_cast<const uint4*>(&g_pA_l[arow*(DPRE/2) + kpg + apg]);
        pBh0 = __ldcg(reinterpret_cast<const uint4*>(&g_Wbig_h[(size_t)(kpg+brow  )*D2 + nBase + bc]));
        pBl0 = __ldcg(reinterpret_cast<const uint4*>(&g_Wbig_l[(size_t)(kpg+brow  )*D2 + nBase + bc]));
        pBh1 = __ldcg(reinterpret_cast<const uint4*>(&g_Wbig_h[(size_t)(kpg+brow+8)*D2 + nBase + bc]));
        pBl1 = __ldcg(reinterpret_cast<const uint4*>(&g_Wbig_l[(size_t)(kpg+brow+8)*D2 + nBase + bc]));
    }
    *reinterpret_cast<uint4*>(&sAh[arow*20 + apg]) = pAh;
    *reinterpret_cast<uint4*>(&sAl[arow*20 + apg]) = pAl;
    *reinterpret_cast<uint4*>(&sBh[brow*132 + bc]) = pBh0;
    *reinterpret_cast<uint4*>(&sBl[brow*132 + bc]) = pBl0;
    *reinterpret_cast<uint4*>(&sBh[(brow+8)*132 + bc]) = pBh1;
    *reinterpret_cast<uint4*>(&sBl[(brow+8)*132 + bc]) = pBl1;
    __syncthreads();

    for (int st = 0; st < nst; st++){
        if (st + 1 < nst){
            const int kpg = kp0 + (st+1) * 16;
            pAh = *reinterpret_cast<const uint4*>(&g_pA_h[arow*(DPRE/2) + kpg + apg]);
            pAl = *reinterpret_cast<const uint4*>(&g_pA_l[arow*(DPRE/2) + kpg + apg]);
            pBh0 = __ldcg(reinterpret_cast<const uint4*>(&g_Wbig_h[(size_t)(kpg+brow  )*D2 + nBase + bc]));
            pBl0 = __ldcg(reinterpret_cast<const uint4*>(&g_Wbig_l[(size_t)(kpg+brow  )*D2 + nBase + bc]));
            pBh1 = __ldcg(reinterpret_cast<const uint4*>(&g_Wbig_h[(size_t)(kpg+brow+8)*D2 + nBase + bc]));
            pBl1 = __ldcg(reinterpret_cast<const uint4*>(&g_Wbig_l[(size_t)(kpg+brow+8)*D2 + nBase + bc]));
        }
#pragma unroll
        for (int s = 0; s < 2; s++){
            const int kb = s * 8;
            const uint32_t ah0 = sAh[(wm+g)*20 + kb+tg],   ah1 = sAh[(wm+8+g)*20 + kb+tg];
            const uint32_t ah2 = sAh[(wm+g)*20 + kb+4+tg], ah3 = sAh[(wm+8+g)*20 + kb+4+tg];
            const uint32_t al0 = sAl[(wm+g)*20 + kb+tg],   al1 = sAl[(wm+8+g)*20 + kb+tg];
            const uint32_t al2 = sAl[(wm+g)*20 + kb+4+tg], al3 = sAl[(wm+8+g)*20 + kb+4+tg];
#pragma unroll
            for (int t = 0; t < 8; t++){
                const int n = wn + t * 8 + g;
                const uint32_t bh0 = sBh[(kb+tg)*132 + n], bh1 = sBh[(kb+4+tg)*132 + n];
                const uint32_t bl0 = sBl[(kb+tg)*132 + n], bl1 = sBl[(kb+4+tg)*132 + n];
                mma16816(acc[t], ah0, ah1, ah2, ah3, bh0, bh1);
                mma16816(acc[t], ah0, ah1, ah2, ah3, bl0, bl1);
                mma16816(acc[t], al0, al1, al2, al3, bh0, bh1);
            }
        }
        if (st + 1 < nst){
            __syncthreads();
            *reinterpret_cast<uint4*>(&sAh[arow*20 + apg]) = pAh;
            *reinterpret_cast<uint4*>(&sAl[arow*20 + apg]) = pAl;
            *reinterpret_cast<uint4*>(&sBh[brow*132 + bc]) = pBh0;
            *reinterpret_cast<uint4*>(&sBl[brow*132 + bc]) = pBl0;
            *reinterpret_cast<uint4*>(&sBh[(brow+8)*132 + bc]) = pBh1;
            *reinterpret_cast<uint4*>(&sBl[(brow+8)*132 + bc]) = pBl1;
            __syncthreads();
        }
    }
    const int r0 = wm + g;
#pragma unroll
    for (int t = 0; t < 8; t++){
        const int c = nBase + wn + t * 8 + tg * 2;
#pragma unroll
        for (int hr = 0; hr < 2; hr++){
            const int r = r0 + hr * 8;
            float* p = &g_hpart[((size_t)(zout*64 + r)) * D2 + c];
            p[0] = acc[t][hr*2+0]; p[1] = acc[t][hr*2+1];
        }
    }
}

// ---------- K1: attnq(t) with in-block syncA | syncO(t-1) ----------
__global__ __launch_bounds__(256) void k1_kernel(const int* __restrict__ idx_la,
                                                 const int* __restrict__ idx_ra,
                                                 const int* __restrict__ idx_lo,
                                                 const int* __restrict__ idx_ro,
                                                 int tick)
{
    __shared__ __align__(16) uint32_t SMu[6928];
    const int tid = threadIdx.x;
    if (blockIdx.x >= 128){
        if (tick > 0) dev_syncO(blockIdx.x - 128, tid, (float*)SMu, tick - 1, idx_lo, idx_ro);
        return;
    }
    float* SM = (float*)SMu;
    float* sA  = SM;              // 4 x 512
    float* sW  = SM + 2048;       // 64 x 68 transposed
    float* qs  = SM + 6400;
    float* ws  = qs + 256;
    float* red = ws + 256;
    const int h = blockIdx.x >> 4, bg = blockIdx.x & 15;
    const int grp = tid >> 6, t = tid & 63;
    const int b = bg * 4 + grp;
    const int buf = tick & 1, nbuf = buf ^ 1;
    const float* cA = g_cA + tick * NSYNC;

    // in-block syncA using precomputed r/c tables
#pragma unroll
    for (int i = 0; i < 8; i++){
        const int idx = tid + i * 256;
        const int bb = bg*4 + (idx >> 9), ii = idx & 511;
        const float pairing = g_act[bb*DMODEL + idx_la[ii]] * g_act[bb*DMODEL + idx_ra[ii]];
        const float a = g_rA[ii] * g_aA[buf][bb*NSYNC+ii] + pairing;
        sA[idx] = a * cA[ii];
        if (h == 0) g_aA[nbuf][bb*NSYNC+ii] = a;
    }

    const int col = h * HD + t;
    float a0 = 0.f, a1 = 0.f, a2 = 0.f, a3 = 0.f;
    for (int ch = 0; ch < 8; ch++){
        const int k0 = ch * 64;
        __syncthreads();
        // float4 weight staging: 1024 float4 per chunk, 4 per thread
#pragma unroll
        for (int i = 0; i < 4; i++){
            const int idx = tid + i * 256;
            const int r = idx >> 4, c4 = (idx & 15) << 2;
            const float4 w = *reinterpret_cast<const float4*>(
                &g_Wqpq[(size_t)(k0 + r) * DATTN + h * HD + c4]);
            sW[(c4+0)*68 + r] = w.x;
            sW[(c4+1)*68 + r] = w.y;
            sW[(c4+2)*68 + r] = w.z;
            sW[(c4+3)*68 + r] = w.w;
        }
        __syncthreads();
        const float* ap = sA + grp * 512 + k0;
        const float4* wp = reinterpret_cast<const float4*>(sW + t * 68);
#pragma unroll
        for (int k = 0; k < 64; k += 4){
            const float4 w = wp[k >> 2];
            a0 += ap[k+0] * w.x;
            a1 += ap[k+1] * w.y;
            a2 += ap[k+2] * w.z;
            a3 += ap[k+3] * w.w;
        }
    }
    __syncthreads();
    qs[grp*64 + t] = (a0 + a1) + (a2 + a3) + g_bq2[col];
    __syncthreads();

    const float* ktp = &g_Kt[((b*HEADS + h)*HD) * SS + t];
    float sc = 0.f;
#pragma unroll
    for (int d = 0; d < HD; d++) sc += qs[grp*64 + d] * ktp[d*SS];
    sc *= 0.125f;

    float mx = sc;
#pragma unroll
    for (int off = 16; off; off >>= 1) mx = fmaxf(mx, __shfl_xor_sync(0xffffffffu, mx, off));
    if ((t & 31) == 0) red[grp*4 + (t >> 5)] = mx;
    __syncthreads();
    mx = fmaxf(red[grp*4 + 0], red[grp*4 + 1]);
    const float e = __expf(sc - mx);
    float smv = e;
#pragma unroll
    for (int off = 16; off; off >>= 1) smv += __shfl_xor_sync(0xffffffffu, smv, off);
    if ((t & 31) == 0) red[grp*4 + 2 + (t >> 5)] = smv;
    __syncthreads();
    smv = red[grp*4 + 2] + red[grp*4 + 3];
    ws[grp*64 + t] = e / smv;
    __syncthreads();

    const float* vp = &g_V[((b*HEADS + h)*SS) * HD + t];
    float ao = 0.f;
#pragma unroll
    for (int s = 0; s < SS; s++) ao += ws[grp*64 + s] * vp[s*HD];

    const float an = __shfl_down_sync(0xffffffffu, ao, 1);
    if (!(t & 1)){
        uint32_t hi, lo; split2(ao, an, hi, lo);
        const int kp = (h*HD + t) >> 1;
        g_pA_h[b*(DPRE/2) + kp] = hi; g_pA_l[b*(DPRE/2) + kp] = lo;
    }
}

// ---------- K2: big(t) | pred(t-1) ----------
__global__ __launch_bounds__(256) void k2_kernel(int tick)
{
    __shared__ __align__(16) uint32_t sm[6928];
    if (blockIdx.x >= 128){
        if (tick > 0){
            const int r = blockIdx.x - 128;
            dev_pred(r & 15, r >> 4, sm);
        }
        return;
    }
    const int nx = blockIdx.x & 31, z = blockIdx.x >> 5;
    dev_big(nx, z, z * 320, 20, sm);
}

// ---------- K3: glu(t) | entropy(t-1) ----------
__global__ __launch_bounds__(256) void glu_ent_kernel(const float* __restrict__ ln_g,
                                                      const float* __restrict__ ln_b,
                                                      const float* __restrict__ bout,
                                                      float* __restrict__ out, int tick)
{
    __shared__ float SM[2080];
    const int tid = threadIdx.x;
    if (blockIdx.x >= 64){
        if (tick > 0) dev_entropy(blockIdx.x - 64, tid, SM, bout, out, tick - 1);
        return;
    }
    float* gbuf = SM;
    float* rs   = SM + DMODEL;
    float* ms   = rs + 16;
    const int b = blockIdx.x;
    float s = 0.f, s2 = 0.f;
    for (int j = tid; j < DMODEL; j += 256){
        float h1 = g_bs1c[j], h2 = g_bs1c[j + DMODEL];
#pragma unroll
        for (int z = 0; z < KSPLIT; z++){
            h1 += g_hpart[(size_t)(z*64 + b)*D2 + j];
            h2 += g_hpart[(size_t)(z*64 + b)*D2 + j + DMODEL];
        }
        const float gv = h1 / (1.f + __expf(-h2));
        gbuf[j] = gv; s += gv; s2 += gv*gv;
    }
#pragma unroll
    for (int off = 16; off; off >>= 1){
        s  += __shfl_xor_sync(0xffffffffu, s,  off);
        s2 += __shfl_xor_sync(0xffffffffu, s2, off);
    }
    if ((tid & 31) == 0){ rs[tid>>5] = s; rs[8 + (tid>>5)] = s2; }
    __syncthreads();
    if (tid == 0){
        float ts = 0.f, ts2 = 0.f;
        for (int w = 0; w < 8; w++){ ts += rs[w]; ts2 += rs[8+w]; }
        const float mu = ts / (float)DMODEL;
        ms[0] = mu; ms[1] = rsqrtf(ts2 / (float)DMODEL - mu*mu + 1e-5f);
    }
    __syncthreads();
    const int slot = tick % MM;
    const float mu = ms[0], inv = ms[1];
    for (int j = tid; j < DMODEL; j += 256)
        g_trace[((size_t)(b*DMODEL + j)) * MP + slot] = (gbuf[j] - mu) * inv * ln_g[j] + ln_b[j];
}

// ---------- K4: nlm ----------
__global__ __launch_bounds__(256) void nlm_kernel(const float* __restrict__ nw1,
                                                  const float* __restrict__ nb1,
                                                  const float* __restrict__ nw2,
                                                  const float* __restrict__ nb2, int tick)
{
    __shared__ float w1s[3200], b1s[128], w2s[128], sAct[256];
    const int cta = blockIdx.x, tid = threadIdx.x;
    const int d0 = cta * 16;
    const int b = tid & 63, dsub = tid >> 6;
    const int o = (tick + 1) % MM;

    for (int p = 0; p < 4; p++){
        const int dbase = d0 + p * 4;
        __syncthreads();
        {
            float4* dst = reinterpret_cast<float4*>(w1s);
            const float4* src = reinterpret_cast<const float4*>(nw1 + (size_t)dbase*800);
            for (int i = tid; i < 800; i += 256) dst[i] = src[i];
        }
        if (tid < 128){ b1s[tid] = nb1[dbase*32 + tid]; w2s[tid] = nw2[dbase*32 + tid]; }
        __syncthreads();

        const int d = dbase + dsub;
        float tr[MM];
        const float* tp = &g_trace[((size_t)(b*DMODEL + d)) * MP];
#pragma unroll
        for (int m = 0; m < MM; m++){ int s = o + m; if (s >= MM) s -= MM; tr[m] = tp[s]; }

        const float* w1p = w1s + dsub * 800;
        float ov = 0.f;
#pragma unroll
        for (int h = 0; h < 32; h += 4){
            float4 s4 = *reinterpret_cast<const float4*>(&b1s[dsub*32 + h]);
#pragma unroll
            for (int m = 0; m < MM; m++){
                const float4 w = *reinterpret_cast<const float4*>(&w1p[m*32 + h]);
                s4.x += tr[m]*w.x; s4.y += tr[m]*w.y; s4.z += tr[m]*w.z; s4.w += tr[m]*w.w;
            }
            const float4 w2v = *reinterpret_cast<const float4*>(&w2s[dsub*32 + h]);
            ov += gelu_f(s4.x)*w2v.x + gelu_f(s4.y)*w2v.y + gelu_f(s4.z)*w2v.z + gelu_f(s4.w)*w2v.w;
        }
        const float a = ov + nb2[d];
        g_act[b*DMODEL + d] = a;
        sAct[dsub*64 + b] = a;
        __syncthreads();
        if (tid < 128){
            const int pi = tid >> 6, bb = tid & 63;
            const float v0 = sAct[(2*pi)*64 + bb], v1 = sAct[(2*pi+1)*64 + bb];
            uint32_t hi, lo; split2(v0, v1, hi, lo);
            const int kp = (DATTN + dbase + 2*pi) >> 1;
            g_pA_h[bb*(DPRE/2) + kp] = hi; g_pA_l[bb*(DPRE/2) + kp] = lo;
        }
    }
}

// ---------- tails ----------
__global__ __launch_bounds__(256) void tail_syncO(const int* __restrict__ idx_lo,
                                                  const int* __restrict__ idx_ro)
{
    __shared__ float sAct[DMODEL];
    dev_syncO(blockIdx.x, threadIdx.x, sAct, TT - 1, idx_lo, idx_ro);
}
__global__ __launch_bounds__(256) void predtail_kernel()
{
    __shared__ __align__(16) uint32_t smem[6928];
    dev_pred((int)blockIdx.x, (int)blockIdx.y, smem);
}
__global__ __launch_bounds__(256) void fin_kernel(const float* __restrict__ bout,
                                                  float* __restrict__ out)
{
    __shared__ float SM[1024];
    const int blk = blockIdx.x, tid = threadIdx.x;
    if (blk < 64){ dev_entropy(blk, tid, SM, bout, out, TT - 1); return; }
    const int i = (blk - 64) * 256 + tid;
    out[SYO_OFF + i] = g_syO[i];
}

// ---------- launch ----------
extern "C" void kernel_launch(void* const* d_in, const int* in_sizes, int n_in,
                              void* d_out, int out_size)
{
    const float* x   = (const float*)d_in[0];
    const float* Wf  = (const float*)d_in[1];
    const float* bf  = (const float*)d_in[2];
    const float* start_trace = (const float*)d_in[3];
    const float* start_state = (const float*)d_in[4];
    const float* decay_a = (const float*)d_in[5];
    const float* decay_o = (const float*)d_in[6];
    const float* Wqp = (const float*)d_in[7];
    const float* bqp = (const float*)d_in[8];
    const float* Wq  = (const float*)d_in[9];
    const float* bq  = (const float*)d_in[10];
    const float* Wk  = (const float*)d_in[11];
    const float* bk  = (const float*)d_in[12];
    const float* Wv  = (const float*)d_in[13];
    const float* bv  = (const float*)d_in[14];
    const float* Wo  = (const float*)d_in[15];
    const float* bo  = (const float*)d_in[16];
    const float* Ws1 = (const float*)d_in[17];
    const float* bs1 = (const float*)d_in[18];
    const float* ln_g = (const float*)d_in[19];
    const float* ln_b = (const float*)d_in[20];
    const float* nw1 = (const float*)d_in[21];
    const float* nb1 = (const float*)d_in[22];
    const float* nw2 = (const float*)d_in[23];
    const float* nb2 = (const float*)d_in[24];
    const float* Wout = (const float*)d_in[25];
    const float* bout = (const float*)d_in[26];
    const int* idx_la = (const int*)d_in[27];
    const int* idx_ra = (const int*)d_in[28];
    const int* idx_lo = (const int*)d_in[29];
    const int* idx_ro = (const int*)d_in[30];
    float* out = (float*)d_out;

    setup_a<<<13378, 256>>>(x, Wf, Wk, Wv, Wq, Wqp, Wo, Ws1, Wout,
                            bqp, bq, bo, bs1, start_trace, start_state, idx_lo, idx_ro,
                            decay_a, decay_o);
    setup_g1<<<1088, 256>>>(bf);
    setup_b<<<21504, 256>>>(bk, bv, Ws1);

    for (int t = 0; t < TT; t++){
        k1_kernel<<<192, 256>>>(idx_la, idx_ra, idx_lo, idx_ro, t);
        k2_kernel<<<192, 256>>>(t);
        glu_ent_kernel<<<128, 256>>>(ln_g, ln_b, bout, out, t);
        nlm_kernel<<<128, 256>>>(nw1, nb1, nw2, nb2, t);
    }
    tail_syncO<<<64, 256>>>(idx_lo, idx_ro);
    predtail_kernel<<<dim3(16, 4), 256>>>();
    fin_kernel<<<192, 256>>>(bout, out);
    (void)in_sizes; (void)n_in; (void)out_size;
}

// round 15
// speedup vs baseline: 1.0450x; 1.0216x over previous
#include <cuda_runtime.h>
#include <cuda_bf16.h>
#include <cstdint>

#define BB 64
#define SS 64
#define DIN 512
#define DATTN 512
#define DMODEL 2048
#define MM 25
#define MP 32
#define HEADS 8
#define HD 64
#define NSYNC 512
#define OUT_N 1000
#define OUT_P 1024
#define TT 50
#define DPRE 2560
#define D2 4096
#define HSPLIT 3
#define PSPLIT 2

#define PRED_SZ (BB*OUT_N*TT)
#define CERT_OFF (PRED_SZ)
#define SYO_OFF (PRED_SZ + BB*2*TT)

// ---------- scratch ----------
__device__ float g_kv[BB*SS*DATTN];
__device__ float g_Kt[BB*HEADS*HD*SS];
__device__ float g_V [BB*HEADS*SS*HD];
__device__ float g_Wqpq[NSYNC*DATTN];
__device__ float g_WbigTop[DATTN*D2];
__device__ float g_bq2[DATTN];
__device__ float g_bs1c[D2];
__device__ float g_act[BB*DMODEL];
__device__ float g_trace[BB*DMODEL*MP];
__device__ float g_aA[2][BB*NSYNC];
__device__ float g_aO[BB*NSYNC], g_syO[BB*NSYNC];
__device__ float g_rA[NSYNC], g_rO[NSYNC];
__device__ float g_cA[TT*NSYNC], g_cO[TT*NSYNC];
__device__ float g_hpart[HSPLIT*BB*D2];
__device__ float g_ppart[PSPLIT*BB*OUT_P];
// packed bf16 hi/lo
__device__ uint32_t g_xp_h[(BB*SS)*(DIN/2)],  g_xp_l[(BB*SS)*(DIN/2)];
__device__ uint32_t g_Wf_h[(DIN/2)*DATTN],  g_Wf_l[(DIN/2)*DATTN];
__device__ uint32_t g_Wk_h[(DATTN/2)*DATTN], g_Wk_l[(DATTN/2)*DATTN];
__device__ uint32_t g_Wv_h[(DATTN/2)*DATTN], g_Wv_l[(DATTN/2)*DATTN];
__device__ uint32_t g_Wq_h[(DATTN/2)*DATTN], g_Wq_l[(DATTN/2)*DATTN];
__device__ uint32_t g_WqpA_h[NSYNC*(DATTN/2)], g_WqpA_l[NSYNC*(DATTN/2)];
__device__ uint32_t g_WoA_h[DATTN*(DATTN/2)], g_WoA_l[DATTN*(DATTN/2)];
__device__ uint32_t g_Ws1t_h[(DATTN/2)*D2], g_Ws1t_l[(DATTN/2)*D2];
__device__ uint32_t g_Wbig_h[(DPRE/2)*D2], g_Wbig_l[(DPRE/2)*D2];
__device__ uint32_t g_WoutP_h[(NSYNC/2)*OUT_P], g_WoutP_l[(NSYNC/2)*OUT_P];
__device__ uint32_t g_pA_h[BB*(DPRE/2)], g_pA_l[BB*(DPRE/2)];
__device__ uint32_t g_syO_h[BB*(NSYNC/2)], g_syO_l[BB*(NSYNC/2)];

// ---------- helpers ----------
__device__ __forceinline__ uint32_t bfpair(float a, float b){
    __nv_bfloat162 t = __floats2bfloat162_rn(a, b);
    return *reinterpret_cast<uint32_t*>(&t);
}
__device__ __forceinline__ void split2(float v0, float v1, uint32_t& hi, uint32_t& lo){
    float h0 = __bfloat162float(__float2bfloat16(v0));
    float h1 = __bfloat162float(__float2bfloat16(v1));
    hi = bfpair(h0, h1);
    lo = bfpair(v0 - h0, v1 - h1);
}
__device__ __forceinline__ void mma16816(float* c, uint32_t a0, uint32_t a1,
                                         uint32_t a2, uint32_t a3, uint32_t b0, uint32_t b1){
    asm volatile("mma.sync.aligned.m16n8k16.row.col.f32.bf16.bf16.f32 "
        "{%0,%1,%2,%3},{%4,%5,%6,%7},{%8,%9},{%0,%1,%2,%3};"
        : "+f"(c[0]), "+f"(c[1]), "+f"(c[2]), "+f"(c[3])
        : "r"(a0), "r"(a1), "r"(a2), "r"(a3), "r"(b0), "r"(b1));
}
__device__ __forceinline__ float gelu_f(float x){
    float z = 0.7978845608028654f * (x + 0.044715f * x*x*x);
    float ee = __expf(-2.f * fabsf(z));
    float th = copysignf((1.f - ee) / (1.f + ee), z);
    return 0.5f * x * (1.f + th);
}
__device__ __forceinline__ void packA_elem(const float* __restrict__ src,
                                           uint32_t* __restrict__ h, uint32_t* __restrict__ l,
                                           int idx, int K){
    const int Kh = K >> 1;
    const int m = idx / Kh, kp = idx - m * Kh;
    split2(src[(size_t)m*K + 2*kp], src[(size_t)m*K + 2*kp + 1], h[idx], l[idx]);
}
__device__ __forceinline__ void packW_elem(const float* __restrict__ src,
                                           uint32_t* __restrict__ h, uint32_t* __restrict__ l,
                                           int idx, int N){
    const int kp = idx / N, n = idx - kp * N;
    split2(src[(size_t)(2*kp)*N + n], src[(size_t)(2*kp+1)*N + n], h[idx], l[idx]);
}
__device__ __forceinline__ void packWpad_elem(const float* __restrict__ src,
                                              uint32_t* __restrict__ h, uint32_t* __restrict__ l,
                                              int idx, int Ns, int Nd){
    const int kp = idx / Nd, n = idx - kp * Nd;
    const float v0 = (n < Ns) ? src[(size_t)(2*kp)*Ns + n] : 0.f;
    const float v1 = (n < Ns) ? src[(size_t)(2*kp+1)*Ns + n] : 0.f;
    split2(v0, v1, h[idx], l[idx]);
}

// ---------- setup GEMM core ----------
__device__ void gemm_dev(const uint32_t* __restrict__ Ah, const uint32_t* __restrict__ Al,
                         const uint32_t* __restrict__ Wh, const uint32_t* __restrict__ Wl,
                         float* __restrict__ C, const float* __restrict__ bias,
                         int N, int K, int epi, int bx, int by, uint32_t* smem, const float* Af32)
{
    uint32_t* sAh = smem;
    uint32_t* sAl = sAh + 2304;
    uint32_t* sBh = sAl + 2304;
    uint32_t* sBl = sBh + 1152;
    const int tid = threadIdx.x;
    const int nBase = bx * 64, rowBase = by * 64;
    const int Kh = K >> 1;
    const int warp = tid >> 5, lane = tid & 31;
    const int wm = (warp & 3) * 16, wn = (warp >> 2) * 32;
    const int g = lane >> 2, tg = lane & 3;
    float acc[4][4];
#pragma unroll
    for (int t = 0; t < 4; t++){ acc[t][0]=acc[t][1]=acc[t][2]=acc[t][3]=0.f; }

    for (int kk = 0; kk < K; kk += 32){
        const int kpg = kk >> 1;
#pragma unroll
        for (int i = 0; i < 4; i++){
            int idx = tid + i * 256;
            int m = idx >> 4, kp = idx & 15;
            if (Af32){
                const float2 av = *reinterpret_cast<const float2*>(
                    &Af32[(size_t)(rowBase + m) * K + (kpg + kp) * 2]);
                split2(av.x, av.y, sAh[m*36+kp], sAl[m*36+kp]);
            } else {
                sAh[m*36+kp] = Ah[(size_t)(rowBase + m) * Kh + kpg + kp];
                sAl[m*36+kp] = Al[(size_t)(rowBase + m) * Kh + kpg + kp];
            }
            int kb = idx >> 6, n = idx & 63;
            sBh[kb*72+n] = Wh[(size_t)(kpg + kb) * N + nBase + n];
            sBl[kb*72+n] = Wl[(size_t)(kpg + kb) * N + nBase + n];
        }
        __syncthreads();
#pragma unroll
        for (int s = 0; s < 2; s++){
            const int kb = s * 8;
            uint32_t ah0 = sAh[(wm+g)*36+kb+tg],   ah1 = sAh[(wm+8+g)*36+kb+tg];
            uint32_t ah2 = sAh[(wm+g)*36+kb+4+tg], ah3 = sAh[(wm+8+g)*36+kb+4+tg];
            uint32_t al0 = sAl[(wm+g)*36+kb+tg],   al1 = sAl[(wm+8+g)*36+kb+tg];
            uint32_t al2 = sAl[(wm+g)*36+kb+4+tg], al3 = sAl[(wm+8+g)*36+kb+4+tg];
#pragma unroll
            for (int t = 0; t < 4; t++){
                const int n = wn + t * 8 + g;
                uint32_t bh0 = sBh[(kb+tg)*72+n], bh1 = sBh[(kb+4+tg)*72+n];
                uint32_t bl0 = sBl[(kb+tg)*72+n], bl1 = sBl[(kb+4+tg)*72+n];
                mma16816(acc[t], ah0, ah1, ah2, ah3, bh0, bh1);
                mma16816(acc[t], ah0, ah1, ah2, ah3, bl0, bl1);
                mma16816(acc[t], al0, al1, al2, al3, bh0, bh1);
            }
        }
        __syncthreads();
    }
    const int r0 = rowBase + wm + g;
#pragma unroll
    for (int t = 0; t < 4; t++){
        const int c = nBase + wn + t * 8 + tg * 2;
#pragma unroll
        for (int hr = 0; hr < 2; hr++){
            const int r = r0 + hr * 8;
            const float v0 = acc[t][hr*2+0], v1 = acc[t][hr*2+1];
            if (epi == 0){
                C[(size_t)r*N + c]   = v0 + (bias ? bias[c]   : 0.f);
                C[(size_t)r*N + c+1] = v1 + (bias ? bias[c+1] : 0.f);
            } else if (epi == 1){
                const int b = r >> 6, srow = r & 63, h = c >> 6, d = c & 63;
                C[((b*HEADS+h)*HD + d  )*SS + srow] = v0 + bias[c];
                C[((b*HEADS+h)*HD + d+1)*SS + srow] = v1 + bias[c+1];
            } else {
                const int b = r >> 6, srow = r & 63, h = c >> 6, d = c & 63;
                C[((b*HEADS+h)*SS + srow)*HD + d  ] = v0 + bias[c];
                C[((b*HEADS+h)*SS + srow)*HD + d+1] = v1 + bias[c+1];
            }
        }
    }
}

// ---------- setup kernels ----------
__global__ void setup_a(const float* __restrict__ x,  const float* __restrict__ Wf,
                        const float* __restrict__ Wk, const float* __restrict__ Wv,
                        const float* __restrict__ Wq, const float* __restrict__ Wqp,
                        const float* __restrict__ Wo, const float* __restrict__ Ws1,
                        const float* __restrict__ Wout,
                        const float* __restrict__ bqp, const float* __restrict__ bq,
                        const float* __restrict__ bo,  const float* __restrict__ bs1,
                        const float* __restrict__ start_trace, const float* __restrict__ start_state,
                        const int* __restrict__ idx_lo, const int* __restrict__ idx_ro,
                        const float* __restrict__ decay_a, const float* __restrict__ decay_o)
{
    int blk = blockIdx.x;
    const int tid = threadIdx.x;
    if (blk < 2){
        const int i = blk*256 + tid;
        const float ra = __expf(-fminf(fmaxf(decay_a[i], 0.f), 15.f));
        const float ro = __expf(-fminf(fmaxf(decay_o[i], 0.f), 15.f));
        g_rA[i] = ra; g_rO[i] = ro;
        float bA = 0.f, bO = 1.f;
        for (int t = 0; t < TT; t++){
            bA = ra * bA + 1.f;
            bO = ro * bO + 1.f;
            g_cA[t*NSYNC + i] = rsqrtf(bA);
            g_cO[t*NSYNC + i] = rsqrtf(bO);
        }
        return;
    }
    blk -= 2;
    if (blk < 64){
        const int col = blk*8 + (tid >> 5), lane = tid & 31;
        float acc = 0.f;
#pragma unroll 16
        for (int i = 0; i < 16; i++){
            const int k = lane + i*32;
            acc += bqp[k] * Wq[(size_t)k*DATTN + col];
        }
#pragma unroll
        for (int off = 16; off; off >>= 1) acc += __shfl_xor_sync(0xffffffffu, acc, off);
        if (lane == 0) g_bq2[col] = acc + bq[col];
        return;
    }
    blk -= 64;
    if (blk < 512){
        const int col = blk*8 + (tid >> 5), lane = tid & 31;
        float acc = 0.f;
#pragma unroll 16
        for (int i = 0; i < 16; i++){
            const int k = lane + i*32;
            acc += bo[k] * Ws1[(size_t)k*D2 + col];
        }
#pragma unroll
        for (int off = 16; off; off >>= 1) acc += __shfl_xor_sync(0xffffffffu, acc, off);
        if (lane == 0) g_bs1c[col] = acc + bs1[col];
        return;
    }
    blk -= 512;
    if (blk < 512){
        const int idx = blk*256 + tid;
        const int b = idx / DMODEL, d = idx - b * DMODEL;
        const float s0 = start_state[d];
        g_act[idx] = s0;
        if (!(d & 1)){
            uint32_t h, l; split2(s0, start_state[d+1], h, l);
            const int kp = (DATTN + d) >> 1;
            g_pA_h[b*(DPRE/2) + kp] = h; g_pA_l[b*(DPRE/2) + kp] = l;
        }
#pragma unroll
        for (int m = 0; m < MP; m++)
            g_trace[(size_t)idx * MP + m] = (m < MM) ? start_trace[d*MM + m] : 0.f;
        if (d < NSYNC){
            g_aA[0][b*NSYNC + d] = 0.f;
            g_aO[b*NSYNC + d] = start_state[idx_lo[d]] * start_state[idx_ro[d]];
        }
        return;
    }
    blk -= 512;
    if (blk < 4096){ packA_elem(x, g_xp_h, g_xp_l, blk*256 + tid, DIN); return; }
    blk -= 4096;
    if (blk < 512){ packW_elem(Wf, g_Wf_h, g_Wf_l, blk*256 + tid, DATTN); return; }
    blk -= 512;
    if (blk < 512){ packW_elem(Wk, g_Wk_h, g_Wk_l, blk*256 + tid, DATTN); return; }
    blk -= 512;
    if (blk < 512){ packW_elem(Wv, g_Wv_h, g_Wv_l, blk*256 + tid, DATTN); return; }
    blk -= 512;
    if (blk < 512){ packW_elem(Wq, g_Wq_h, g_Wq_l, blk*256 + tid, DATTN); return; }
    blk -= 512;
    if (blk < 512){ packA_elem(Wqp, g_WqpA_h, g_WqpA_l, blk*256 + tid, DATTN); return; }
    blk -= 512;
    if (blk < 512){ packA_elem(Wo, g_WoA_h, g_WoA_l, blk*256 + tid, DATTN); return; }
    blk -= 512;
    if (blk < 4096){ packW_elem(Ws1, g_Ws1t_h, g_Ws1t_l, blk*256 + tid, D2); return; }
    blk -= 4096;
    packWpad_elem(Wout, g_WoutP_h, g_WoutP_l, blk*256 + tid, OUT_N, OUT_P);
}
__global__ __launch_bounds__(256) void setup_g1(const float* __restrict__ bf)
{
    __shared__ uint32_t smem[6912];
    const int c = blockIdx.x;
    if (c < 512)      gemm_dev(g_xp_h, g_xp_l, g_Wf_h, g_Wf_l, g_kv, bf, DATTN, DIN, 0, c & 7, c >> 3, smem, (const float*)0);
    else if (c < 576){ const int c2 = c - 512;
                      gemm_dev(g_WqpA_h, g_WqpA_l, g_Wq_h, g_Wq_l, g_Wqpq, (const float*)0, DATTN, DATTN, 0, c2 & 7, c2 >> 3, smem, (const float*)0); }
    else             { const int c2 = c - 576;
                      gemm_dev(g_WoA_h, g_WoA_l, g_Ws1t_h, g_Ws1t_l, g_WbigTop, (const float*)0, D2, DATTN, 0, c2 & 63, c2 >> 6, smem, (const float*)0); }
}
__global__ __launch_bounds__(256) void setup_b(const float* __restrict__ bk,
                                               const float* __restrict__ bv,
                                               const float* __restrict__ Ws1)
{
    __shared__ uint32_t smem[6912];
    int c = blockIdx.x;
    if (c < 512){ gemm_dev((const uint32_t*)0, (const uint32_t*)0, g_Wk_h, g_Wk_l, g_Kt, bk, DATTN, DATTN, 1, c & 7, c >> 3, smem, g_kv); return; }
    c -= 512;
    if (c < 512){ gemm_dev((const uint32_t*)0, (const uint32_t*)0, g_Wv_h, g_Wv_l, g_V, bv, DATTN, DATTN, 2, c & 7, c >> 3, smem, g_kv); return; }
    c -= 512;
    {   const int idx = c*256 + threadIdx.x;
        const int kp = idx / D2, n = idx - kp*D2;
        float v0, v1;
        if (kp < DATTN/2){ v0 = g_WbigTop[(size_t)(2*kp)*D2 + n]; v1 = g_WbigTop[(size_t)(2*kp+1)*D2 + n]; }
        else             { v0 = Ws1[(size_t)(2*kp)*D2 + n];       v1 = Ws1[(size_t)(2*kp+1)*D2 + n]; }
        split2(v0, v1, g_Wbig_h[idx], g_Wbig_l[idx]); }
}

// ---------- entropy (sums PSPLIT ppart slices) ----------
__device__ void dev_entropy(int b, int tid, float* sm, const float* __restrict__ bout,
                            float* __restrict__ out, int tw)
{
    float* pbuf = sm;
    float* r0 = pbuf + 1000;
    float* r1 = r0 + 8;
    float* bc = r1 + 8;
    float mx = -1e30f;
    for (int o = tid; o < OUT_N; o += 256){
        float p = bout[o];
#pragma unroll
        for (int z = 0; z < PSPLIT; z++) p += g_ppart[(z*BB + b)*OUT_P + o];
        pbuf[o] = p;
        out[((size_t)(b*OUT_N + o))*TT + tw] = p;
        mx = fmaxf(mx, p);
    }
#pragma unroll
    for (int off = 16; off; off >>= 1) mx = fmaxf(mx, __shfl_xor_sync(0xffffffffu, mx, off));
    if ((tid & 31) == 0) r0[tid >> 5] = mx;
    __syncthreads();
    if (tid == 0){
        float m = r0[0];
        for (int w = 1; w < 8; w++) m = fmaxf(m, r0[w]);
        bc[0] = m;
    }
    __syncthreads();
    mx = bc[0];
    float s0 = 0.f, s1 = 0.f;
    for (int o = tid; o < OUT_N; o += 256){
        const float u = pbuf[o] - mx;
        const float e = __expf(u);
        s0 += e; s1 += u * e;
    }
#pragma unroll
    for (int off = 16; off; off >>= 1){
        s0 += __shfl_xor_sync(0xffffffffu, s0, off);
        s1 += __shfl_xor_sync(0xffffffffu, s1, off);
    }
    if ((tid & 31) == 0){ r0[tid>>5] = s0; r1[tid>>5] = s1; }
    __syncthreads();
    if (tid == 0){
        float t0 = 0.f, t1 = 0.f;
        for (int w = 0; w < 8; w++){ t0 += r0[w]; t1 += r1[w]; }
        const float ne = -(t1 / t0 - logf(t0)) / logf((float)OUT_N);
        out[CERT_OFF + (size_t)(b*2 + 0)*TT + tw] = ne;
        out[CERT_OFF + (size_t)(b*2 + 1)*TT + tw] = 1.f - ne;
    }
}

// ---------- syncO for one batch (256 threads), tick tw ----------
__device__ void dev_syncO(int b, int tid, float* sAct, int tw,
                          const int* __restrict__ idx_lo, const int* __restrict__ idx_ro)
{
#pragma unroll
    for (int k = 0; k < 8; k++) sAct[tid + k*256] = g_act[b*DMODEL + tid + k*256];
    __syncthreads();
    const int i0 = tid * 2;
    float v[2];
#pragma unroll
    for (int j = 0; j < 2; j++){
        const int i = i0 + j;
        const float pairing = sAct[idx_lo[i]] * sAct[idx_ro[i]];
        const float a = g_rO[i] * g_aO[b*NSYNC+i] + pairing;
        g_aO[b*NSYNC+i] = a;
        v[j] = a * g_cO[tw*NSYNC + i];
        g_syO[b*NSYNC+i] = v[j];
    }
    uint32_t h, l; split2(v[0], v[1], h, l);
    g_syO_h[b*(NSYNC/2) + tid] = h;
    g_syO_l[b*(NSYNC/2) + tid] = l;
}

// ---------- pred: split-K MMA, z in {0,1}, 128 pairs each ----------
__device__ void dev_pred(int nx, int z, uint32_t* smem)
{
    uint32_t* sAh = smem;
    uint32_t* sAl = sAh + 2304;
    uint32_t* sBh = sAl + 2304;
    uint32_t* sBl = sBh + 1152;
    const int tid = threadIdx.x;
    const int nBase = nx * 64;
    const int warp = tid >> 5, lane = tid & 31;
    const int wm = (warp & 3) * 16, wn = (warp >> 2) * 32;
    const int g = lane >> 2, tg = lane & 3;
    float acc[4][4];
#pragma unroll
    for (int t = 0; t < 4; t++){ acc[t][0]=acc[t][1]=acc[t][2]=acc[t][3]=0.f; }

    for (int kk = 0; kk < 256; kk += 32){
        const int kpg = z * 128 + (kk >> 1);
#pragma unroll
        for (int i = 0; i < 4; i++){
            int idx = tid + i * 256;
            int m = idx >> 4, kp = idx & 15;
            sAh[m*36+kp] = g_syO_h[m*(NSYNC/2) + kpg + kp];
            sAl[m*36+kp] = g_syO_l[m*(NSYNC/2) + kpg + kp];
            int kb = idx >> 6, n = idx & 63;
            sBh[kb*72+n] = g_WoutP_h[(size_t)(kpg + kb) * OUT_P + nBase + n];
            sBl[kb*72+n] = g_WoutP_l[(size_t)(kpg + kb) * OUT_P + nBase + n];
        }
        __syncthreads();
#pragma unroll
        for (int s = 0; s < 2; s++){
            const int kb = s * 8;
            uint32_t ah0 = sAh[(wm+g)*36+kb+tg],   ah1 = sAh[(wm+8+g)*36+kb+tg];
            uint32_t ah2 = sAh[(wm+g)*36+kb+4+tg], ah3 = sAh[(wm+8+g)*36+kb+4+tg];
            uint32_t al0 = sAl[(wm+g)*36+kb+tg],   al1 = sAl[(wm+8+g)*36+kb+tg];
            uint32_t al2 = sAl[(wm+g)*36+kb+4+tg], al3 = sAl[(wm+8+g)*36+kb+4+tg];
#pragma unroll
            for (int t = 0; t < 4; t++){
                const int n = wn + t * 8 + g;
                uint32_t bh0 = sBh[(kb+tg)*72+n], bh1 = sBh[(kb+4+tg)*72+n];
                uint32_t bl0 = sBl[(kb+tg)*72+n], bl1 = sBl[(kb+4+tg)*72+n];
                mma16816(acc[t], ah0, ah1, ah2, ah3, bh0, bh1);
                mma16816(acc[t], ah0, ah1, ah2, ah3, bl0, bl1);
                mma16816(acc[t], al0, al1, al2, al3, bh0, bh1);
            }
        }
        __syncthreads();
    }
    const int r0 = wm + g;
#pragma unroll
    for (int t = 0; t < 4; t++){
        const int c = nBase + wn + t * 8 + tg * 2;
#pragma unroll
        for (int hr = 0; hr < 2; hr++){
            const int r = r0 + hr * 8;
            float* p = &g_ppart[((size_t)(z*BB + r)) * OUT_P + c];
            p[0] = acc[t][hr*2+0]; p[1] = acc[t][hr*2+1];
        }
    }
}

// ---------- big GEMM slice ----------
__device__ void dev_big(int nx, int zout, int kp0, int nst, uint32_t* sm)
{
    uint32_t* sAh = sm;
    uint32_t* sAl = sAh + 1280;
    uint32_t* sBh = sAl + 1280;
    uint32_t* sBl = sBh + 2112;
    const int tid = threadIdx.x;
    const int nBase = nx * 128;
    const int warp = tid >> 5, lane = tid & 31;
    const int wm = (warp & 3) * 16, wn = (warp >> 2) * 64;
    const int g = lane >> 2, tg = lane & 3;
    const int arow = tid >> 2, apg = (tid & 3) << 2;
    const int brow = tid >> 5, bc = lane << 2;

    float acc[8][4];
#pragma unroll
    for (int t = 0; t < 8; t++){ acc[t][0]=acc[t][1]=acc[t][2]=acc[t][3]=0.f; }

    uint4 pAh, pAl, pBh0, pBl0, pBh1, pBl1;
    {
        const int kpg = kp0;
        pAh = *reinterpret_cast<const uint4*>(&g_pA_h[arow*(DPRE/2) + kpg + apg]);
        pAl = *reinterpret_cast<const uint4*>(&g_pA_l[arow*(DPRE/2) + kpg + apg]);
        pBh0 = __ldcg(reinterpret_cast<const uint4*>(&g_Wbig_h[(size_t)(kpg+brow  )*D2 + nBase + bc]));
        pBl0 = __ldcg(reinterpret_cast<const uint4*>(&g_Wbig_l[(size_t)(kpg+brow  )*D2 + nBase + bc]));
        pBh1 = __ldcg(reinterpret_cast<const uint4*>(&g_Wbig_h[(size_t)(kpg+brow+8)*D2 + nBase + bc]));
        pBl1 = __ldcg(reinterpret_cast<const uint4*>(&g_Wbig_l[(size_t)(kpg+brow+8)*D2 + nBase + bc]));
    }
    *reinterpret_cast<uint4*>(&sAh[arow*20 + apg]) = pAh;
    *reinterpret_cast<uint4*>(&sAl[arow*20 + apg]) = pAl;
    *reinterpret_cast<uint4*>(&sBh[brow*132 + bc]) = pBh0;
    *reinterpret_cast<uint4*>(&sBl[brow*132 + bc]) = pBl0;
    *reinterpret_cast<uint4*>(&sBh[(brow+8)*132 + bc]) = pBh1;
    *reinterpret_cast<uint4*>(&sBl[(brow+8)*132 + bc]) = pBl1;
    __syncthreads();

    for (int st = 0; st < nst; st++){
        if (st + 1 < nst){
            const int kpg = kp0 + (st+1) * 16;
            pAh = *reinterpret_cast<const uint4*>(&g_pA_h[arow*(DPRE/2) + kpg + apg]);
            pAl = *reinterpret_cast<const uint4*>(&g_pA_l[arow*(DPRE/2) + kpg + apg]);
            pBh0 = __ldcg(reinterpret_cast<const uint4*>(&g_Wbig_h[(size_t)(kpg+brow  )*D2 + nBase + bc]));
            pBl0 = __ldcg(reinterpret_cast<const uint4*>(&g_Wbig_l[(size_t)(kpg+brow  )*D2 + nBase + bc]));
            pBh1 = __ldcg(reinterpret_cast<const uint4*>(&g_Wbig_h[(size_t)(kpg+brow+8)*D2 + nBase + bc]));
            pBl1 = __ldcg(reinterpret_cast<const uint4*>(&g_Wbig_l[(size_t)(kpg+brow+8)*D2 + nBase + bc]));
        }
#pragma unroll
        for (int s = 0; s < 2; s++){
            const int kb = s * 8;
            const uint32_t ah0 = sAh[(wm+g)*20 + kb+tg],   ah1 = sAh[(wm+8+g)*20 + kb+tg];
            const uint32_t ah2 = sAh[(wm+g)*20 + kb+4+tg], ah3 = sAh[(wm+8+g)*20 + kb+4+tg];
            const uint32_t al0 = sAl[(wm+g)*20 + kb+tg],   al1 = sAl[(wm+8+g)*20 + kb+tg];
            const uint32_t al2 = sAl[(wm+g)*20 + kb+4+tg], al3 = sAl[(wm+8+g)*20 + kb+4+tg];
#pragma unroll
            for (int t = 0; t < 8; t++){
                const int n = wn + t * 8 + g;
                const uint32_t bh0 = sBh[(kb+tg)*132 + n], bh1 = sBh[(kb+4+tg)*132 + n];
                const uint32_t bl0 = sBl[(kb+tg)*132 + n], bl1 = sBl[(kb+4+tg)*132 + n];
                mma16816(acc[t], ah0, ah1, ah2, ah3, bh0, bh1);
                mma16816(acc[t], ah0, ah1, ah2, ah3, bl0, bl1);
                mma16816(acc[t], al0, al1, al2, al3, bh0, bh1);
            }
        }
        if (st + 1 < nst){
            __syncthreads();
            *reinterpret_cast<uint4*>(&sAh[arow*20 + apg]) = pAh;
            *reinterpret_cast<uint4*>(&sAl[arow*20 + apg]) = pAl;
            *reinterpret_cast<uint4*>(&sBh[brow*132 + bc]) = pBh0;
            *reinterpret_cast<uint4*>(&sBl[brow*132 + bc]) = pBl0;
            *reinterpret_cast<uint4*>(&sBh[(brow+8)*132 + bc]) = pBh1;
            *reinterpret_cast<uint4*>(&sBl[(brow+8)*132 + bc]) = pBl1;
            __syncthreads();
        }
    }
    const int r0 = wm + g;
#pragma unroll
    for (int t = 0; t < 8; t++){
        const int c = nBase + wn + t * 8 + tg * 2;
#pragma unroll
        for (int hr = 0; hr < 2; hr++){
            const int r = r0 + hr * 8;
            float* p = &g_hpart[((size_t)(zout*64 + r)) * D2 + c];
            p[0] = acc[t][hr*2+0]; p[1] = acc[t][hr*2+1];
        }
    }
}

// ---------- K1: 128 blocks, single wave.
// block = attnq(h=blk>>4, bg=blk&15); even blocks prepend syncO(t-1) for b=blk>>1.
__global__ __launch_bounds__(256) void k1_kernel(const int* __restrict__ idx_la,
                                                 const int* __restrict__ idx_ra,
                                                 const int* __restrict__ idx_lo,
                                                 const int* __restrict__ idx_ro,
                                                 int tick)
{
    __shared__ __align__(16) uint32_t SMu[6928];
    const int tid = threadIdx.x;
    float* SM = (float*)SMu;
    float* sA  = SM;              // 4 x 512
    float* sW  = SM + 2048;       // 64 x 68 transposed (also syncO scratch: 2048 <= 4352)
    float* qs  = SM + 6400;
    float* ws  = qs + 256;
    float* red = ws + 256;

    // even blocks: syncO(t-1) for batch blk>>1 (uses sW region as scratch)
    if (tick > 0 && !(blockIdx.x & 1)){
        dev_syncO(blockIdx.x >> 1, tid, sW, tick - 1, idx_lo, idx_ro);
        __syncthreads();
    }

    const int h = blockIdx.x >> 4, bg = blockIdx.x & 15;
    const int grp = tid >> 6, t = tid & 63;
    const int b = bg * 4 + grp;
    const int buf = tick & 1, nbuf = buf ^ 1;
    const float* cA = g_cA + tick * NSYNC;

    // in-block syncA using precomputed tables
#pragma unroll
    for (int i = 0; i < 8; i++){
        const int idx = tid + i * 256;
        const int bb = bg*4 + (idx >> 9), ii = idx & 511;
        const float pairing = g_act[bb*DMODEL + idx_la[ii]] * g_act[bb*DMODEL + idx_ra[ii]];
        const float a = g_rA[ii] * g_aA[buf][bb*NSYNC+ii] + pairing;
        sA[idx] = a * cA[ii];
        if (h == 0) g_aA[nbuf][bb*NSYNC+ii] = a;
    }

    const int col = h * HD + t;
    float a0 = 0.f, a1 = 0.f, a2 = 0.f, a3 = 0.f;
    for (int ch = 0; ch < 8; ch++){
        const int k0 = ch * 64;
        __syncthreads();
#pragma unroll
        for (int i = 0; i < 4; i++){
            const int idx = tid + i * 256;
            const int r = idx >> 4, c4 = (idx & 15) << 2;
            const float4 w = *reinterpret_cast<const float4*>(
                &g_Wqpq[(size_t)(k0 + r) * DATTN + h * HD + c4]);
            sW[(c4+0)*68 + r] = w.x;
            sW[(c4+1)*68 + r] = w.y;
            sW[(c4+2)*68 + r] = w.z;
            sW[(c4+3)*68 + r] = w.w;
        }
        __syncthreads();
        const float* ap = sA + grp * 512 + k0;
        const float4* wp = reinterpret_cast<const float4*>(sW + t * 68);
#pragma unroll
        for (int k = 0; k < 64; k += 4){
            const float4 w = wp[k >> 2];
            a0 += ap[k+0] * w.x;
            a1 += ap[k+1] * w.y;
            a2 += ap[k+2] * w.z;
            a3 += ap[k+3] * w.w;
        }
    }
    __syncthreads();
    qs[grp*64 + t] = (a0 + a1) + (a2 + a3) + g_bq2[col];
    __syncthreads();

    const float* ktp = &g_Kt[((b*HEADS + h)*HD) * SS + t];
    float sc = 0.f;
#pragma unroll
    for (int d = 0; d < HD; d++) sc += qs[grp*64 + d] * ktp[d*SS];
    sc *= 0.125f;

    float mx = sc;
#pragma unroll
    for (int off = 16; off; off >>= 1) mx = fmaxf(mx, __shfl_xor_sync(0xffffffffu, mx, off));
    if ((t & 31) == 0) red[grp*4 + (t >> 5)] = mx;
    __syncthreads();
    mx = fmaxf(red[grp*4 + 0], red[grp*4 + 1]);
    const float e = __expf(sc - mx);
    float smv = e;
#pragma unroll
    for (int off = 16; off; off >>= 1) smv += __shfl_xor_sync(0xffffffffu, smv, off);
    if ((t & 31) == 0) red[grp*4 + 2 + (t >> 5)] = smv;
    __syncthreads();
    smv = red[grp*4 + 2] + red[grp*4 + 3];
    ws[grp*64 + t] = e / smv;
    __syncthreads();

    const float* vp = &g_V[((b*HEADS + h)*SS) * HD + t];
    float ao = 0.f;
#pragma unroll
    for (int s = 0; s < SS; s++) ao += ws[grp*64 + s] * vp[s*HD];

    const float an = __shfl_down_sync(0xffffffffu, ao, 1);
    if (!(t & 1)){
        uint32_t hi, lo; split2(ao, an, hi, lo);
        const int kp = (h*HD + t) >> 1;
        g_pA_h[b*(DPRE/2) + kp] = hi; g_pA_l[b*(DPRE/2) + kp] = lo;
    }
}

// ---------- K2: 128 blocks single wave. [0,96): big (nx=blk%32, z=blk/32), [96,128): pred (t-1)
__global__ __launch_bounds__(256) void k2_kernel(int tick)
{
    __shared__ __align__(16) uint32_t sm[6928];
    if (blockIdx.x >= 96){
        if (tick > 0){
            const int r = blockIdx.x - 96;
            dev_pred(r & 15, r >> 4, sm);
        }
        return;
    }
    const int nx = blockIdx.x & 31, z = blockIdx.x >> 5;
    const int kp0 = (z == 0) ? 0 : (z == 1 ? 432 : 864);
    const int nst = (z == 2) ? 26 : 27;
    dev_big(nx, z, kp0, nst, sm);
}

// ---------- K3: glu(t) | entropy(t-1) ----------
__global__ __launch_bounds__(256) void glu_ent_kernel(const float* __restrict__ ln_g,
                                                      const float* __restrict__ ln_b,
                                                      const float* __restrict__ bout,
                                                      float* __restrict__ out, int tick)
{
    __shared__ float SM[2080];
    const int tid = threadIdx.x;
    if (blockIdx.x >= 64){
        if (tick > 0) dev_entropy(blockIdx.x - 64, tid, SM, bout, out, tick - 1);
        return;
    }
    float* gbuf = SM;
    float* rs   = SM + DMODEL;
    float* ms   = rs + 16;
    const int b = blockIdx.x;
    float s = 0.f, s2 = 0.f;
    for (int j = tid; j < DMODEL; j += 256){
        float h1 = g_bs1c[j], h2 = g_bs1c[j + DMODEL];
#pragma unroll
        for (int z = 0; z < HSPLIT; z++){
            h1 += g_hpart[(size_t)(z*64 + b)*D2 + j];
            h2 += g_hpart[(size_t)(z*64 + b)*D2 + j + DMODEL];
        }
        const float gv = h1 / (1.f + __expf(-h2));
        gbuf[j] = gv; s += gv; s2 += gv*gv;
    }
#pragma unroll
    for (int off = 16; off; off >>= 1){
        s  += __shfl_xor_sync(0xffffffffu, s,  off);
        s2 += __shfl_xor_sync(0xffffffffu, s2, off);
    }
    if ((tid & 31) == 0){ rs[tid>>5] = s; rs[8 + (tid>>5)] = s2; }
    __syncthreads();
    if (tid == 0){
        float ts = 0.f, ts2 = 0.f;
        for (int w = 0; w < 8; w++){ ts += rs[w]; ts2 += rs[8+w]; }
        const float mu = ts / (float)DMODEL;
        ms[0] = mu; ms[1] = rsqrtf(ts2 / (float)DMODEL - mu*mu + 1e-5f);
    }
    __syncthreads();
    const int slot = tick % MM;
    const float mu = ms[0], inv = ms[1];
    for (int j = tid; j < DMODEL; j += 256)
        g_trace[((size_t)(b*DMODEL + j)) * MP + slot] = (gbuf[j] - mu) * inv * ln_g[j] + ln_b[j];
}

// ---------- K4: nlm ----------
__global__ __launch_bounds__(256) void nlm_kernel(const float* __restrict__ nw1,
                                                  const float* __restrict__ nb1,
                                                  const float* __restrict__ nw2,
                                                  const float* __restrict__ nb2, int tick)
{
    __shared__ float w1s[3200], b1s[128], w2s[128], sAct[256];
    const int cta = blockIdx.x, tid = threadIdx.x;
    const int d0 = cta * 16;
    const int b = tid & 63, dsub = tid >> 6;
    const int o = (tick + 1) % MM;

    for (int p = 0; p < 4; p++){
        const int dbase = d0 + p * 4;
        __syncthreads();
        {
            float4* dst = reinterpret_cast<float4*>(w1s);
            const float4* src = reinterpret_cast<const float4*>(nw1 + (size_t)dbase*800);
            for (int i = tid; i < 800; i += 256) dst[i] = src[i];
        }
        if (tid < 128){ b1s[tid] = nb1[dbase*32 + tid]; w2s[tid] = nw2[dbase*32 + tid]; }
        __syncthreads();

        const int d = dbase + dsub;
        float tr[MM];
        const float* tp = &g_trace[((size_t)(b*DMODEL + d)) * MP];
#pragma unroll
        for (int m = 0; m < MM; m++){ int s = o + m; if (s >= MM) s -= MM; tr[m] = tp[s]; }

        const float* w1p = w1s + dsub * 800;
        float ov = 0.f;
#pragma unroll
        for (int h = 0; h < 32; h += 4){
            float4 s4 = *reinterpret_cast<const float4*>(&b1s[dsub*32 + h]);
#pragma unroll
            for (int m = 0; m < MM; m++){
                const float4 w = *reinterpret_cast<const float4*>(&w1p[m*32 + h]);
                s4.x += tr[m]*w.x; s4.y += tr[m]*w.y; s4.z += tr[m]*w.z; s4.w += tr[m]*w.w;
            }
            const float4 w2v = *reinterpret_cast<const float4*>(&w2s[dsub*32 + h]);
            ov += gelu_f(s4.x)*w2v.x + gelu_f(s4.y)*w2v.y + gelu_f(s4.z)*w2v.z + gelu_f(s4.w)*w2v.w;
        }
        const float a = ov + nb2[d];
        g_act[b*DMODEL + d] = a;
        sAct[dsub*64 + b] = a;
        __syncthreads();
        if (tid < 128){
            const int pi = tid >> 6, bb = tid & 63;
            const float v0 = sAct[(2*pi)*64 + bb], v1 = sAct[(2*pi+1)*64 + bb];
            uint32_t hi, lo; split2(v0, v1, hi, lo);
            const int kp = (DATTN + dbase + 2*pi) >> 1;
            g_pA_h[bb*(DPRE/2) + kp] = hi; g_pA_l[bb*(DPRE/2) + kp] = lo;
        }
    }
}

// ---------- tails ----------
__global__ __launch_bounds__(256) void tail_syncO(const int* __restrict__ idx_lo,
                                                  const int* __restrict__ idx_ro)
{
    __shared__ float sAct[DMODEL];
    dev_syncO(blockIdx.x, threadIdx.x, sAct, TT - 1, idx_lo, idx_ro);
}
__global__ __launch_bounds__(256) void predtail_kernel()
{
    __shared__ __align__(16) uint32_t smem[6928];
    dev_pred((int)blockIdx.x, (int)blockIdx.y, smem);
}
__global__ __launch_bounds__(256) void fin_kernel(const float* __restrict__ bout,
                                                  float* __restrict__ out)
{
    __shared__ float SM[1024];
    const int blk = blockIdx.x, tid = threadIdx.x;
    if (blk < 64){ dev_entropy(blk, tid, SM, bout, out, TT - 1); return; }
    const int i = (blk - 64) * 256 + tid;
    out[SYO_OFF + i] = g_syO[i];
}

// ---------- launch ----------
extern "C" void kernel_launch(void* const* d_in, const int* in_sizes, int n_in,
                              void* d_out, int out_size)
{
    const float* x   = (const float*)d_in[0];
    const float* Wf  = (const float*)d_in[1];
    const float* bf  = (const float*)d_in[2];
    const float* start_trace = (const float*)d_in[3];
    const float* start_state = (const float*)d_in[4];
    const float* decay_a = (const float*)d_in[5];
    const float* decay_o = (const float*)d_in[6];
    const float* Wqp = (const float*)d_in[7];
    const float* bqp = (const float*)d_in[8];
    const float* Wq  = (const float*)d_in[9];
    const float* bq  = (const float*)d_in[10];
    const float* Wk  = (const float*)d_in[11];
    const float* bk  = (const float*)d_in[12];
    const float* Wv  = (const float*)d_in[13];
    const float* bv  = (const float*)d_in[14];
    const float* Wo  = (const float*)d_in[15];
    const float* bo  = (const float*)d_in[16];
    const float* Ws1 = (const float*)d_in[17];
    const float* bs1 = (const float*)d_in[18];
    const float* ln_g = (const float*)d_in[19];
    const float* ln_b = (const float*)d_in[20];
    const float* nw1 = (const float*)d_in[21];
    const float* nb1 = (const float*)d_in[22];
    const float* nw2 = (const float*)d_in[23];
    const float* nb2 = (const float*)d_in[24];
    const float* Wout = (const float*)d_in[25];
    const float* bout = (const float*)d_in[26];
    const int* idx_la = (const int*)d_in[27];
    const int* idx_ra = (const int*)d_in[28];
    const int* idx_lo = (const int*)d_in[29];
    const int* idx_ro = (const int*)d_in[30];
    float* out = (float*)d_out;

    setup_a<<<13378, 256>>>(x, Wf, Wk, Wv, Wq, Wqp, Wo, Ws1, Wout,
                            bqp, bq, bo, bs1, start_trace, start_state, idx_lo, idx_ro,
                            decay_a, decay_o);
    setup_g1<<<1088, 256>>>(bf);
    setup_b<<<21504, 256>>>(bk, bv, Ws1);

    for (int t = 0; t < TT; t++){
        k1_kernel<<<128, 256>>>(idx_la, idx_ra, idx_lo, idx_ro, t);
        k2_kernel<<<128, 256>>>(t);
        glu_ent_kernel<<<128, 256>>>(ln_g, ln_b, bout, out, t);
        nlm_kernel<<<128, 256>>>(nw1, nb1, nw2, nb2, t);
    }
    tail_syncO<<<64, 256>>>(idx_lo, idx_ro);
    predtail_kernel<<<dim3(16, 2), 256>>>();
    fin_kernel<<<192, 256>>>(bout, out);
    (void)in_sizes; (void)n_in; (void)out_size;
}

// round 16
// speedup vs baseline: 1.1617x; 1.1117x over previous
#include <cuda_runtime.h>
#include <cuda_bf16.h>
#include <cstdint>

#define BB 64
#define SS 64
#define DIN 512
#define DATTN 512
#define DMODEL 2048
#define MM 25
#define MP 32
#define HEADS 8
#define HD 64
#define NSYNC 512
#define OUT_N 1000
#define OUT_P 1024
#define TT 50
#define DPRE 2560
#define D2 4096
#define HSPLIT 3
#define PSPLIT 2

#define PRED_SZ (BB*OUT_N*TT)
#define CERT_OFF (PRED_SZ)
#define SYO_OFF (PRED_SZ + BB*2*TT)

// ---------- scratch ----------
__device__ float g_kv[BB*SS*DATTN];
__device__ float g_Kt[BB*HEADS*HD*SS];
__device__ float g_V [BB*HEADS*SS*HD];
__device__ float g_Wqpq[NSYNC*DATTN];
__device__ float g_WbigTop[DATTN*D2];
__device__ float g_bq2[DATTN];
__device__ float g_bs1c[D2];
__device__ float g_act[BB*DMODEL];
__device__ float g_trace[BB*DMODEL*MP];
__device__ float g_aA[2][BB*NSYNC];
__device__ float g_aO[BB*NSYNC], g_syO[BB*NSYNC];
__device__ float g_rA[NSYNC], g_rO[NSYNC];
__device__ float g_cA[TT*NSYNC], g_cO[TT*NSYNC];
__device__ float g_hpart[HSPLIT*BB*D2];
__device__ float g_ppart[PSPLIT*BB*OUT_P];
// packed bf16 hi/lo
__device__ uint32_t g_xp_h[(BB*SS)*(DIN/2)],  g_xp_l[(BB*SS)*(DIN/2)];
__device__ uint32_t g_Wf_h[(DIN/2)*DATTN],  g_Wf_l[(DIN/2)*DATTN];
__device__ uint32_t g_Wk_h[(DATTN/2)*DATTN], g_Wk_l[(DATTN/2)*DATTN];
__device__ uint32_t g_Wv_h[(DATTN/2)*DATTN], g_Wv_l[(DATTN/2)*DATTN];
__device__ uint32_t g_Wq_h[(DATTN/2)*DATTN], g_Wq_l[(DATTN/2)*DATTN];
__device__ uint32_t g_WqpA_h[NSYNC*(DATTN/2)], g_WqpA_l[NSYNC*(DATTN/2)];
__device__ uint32_t g_WoA_h[DATTN*(DATTN/2)], g_WoA_l[DATTN*(DATTN/2)];
__device__ uint32_t g_Ws1t_h[(DATTN/2)*D2], g_Ws1t_l[(DATTN/2)*D2];
__device__ uint32_t g_Wbig_h[(DPRE/2)*D2], g_Wbig_l[(DPRE/2)*D2];
__device__ uint32_t g_WoutP_h[(NSYNC/2)*OUT_P], g_WoutP_l[(NSYNC/2)*OUT_P];
__device__ uint32_t g_pA_h[BB*(DPRE/2)], g_pA_l[BB*(DPRE/2)];
__device__ uint32_t g_syO_h[BB*(NSYNC/2)], g_syO_l[BB*(NSYNC/2)];

// ---------- helpers ----------
__device__ __forceinline__ uint32_t bfpair(float a, float b){
    __nv_bfloat162 t = __floats2bfloat162_rn(a, b);
    return *reinterpret_cast<uint32_t*>(&t);
}
__device__ __forceinline__ void split2(float v0, float v1, uint32_t& hi, uint32_t& lo){
    float h0 = __bfloat162float(__float2bfloat16(v0));
    float h1 = __bfloat162float(__float2bfloat16(v1));
    hi = bfpair(h0, h1);
    lo = bfpair(v0 - h0, v1 - h1);
}
__device__ __forceinline__ void mma16816(float* c, uint32_t a0, uint32_t a1,
                                         uint32_t a2, uint32_t a3, uint32_t b0, uint32_t b1){
    asm volatile("mma.sync.aligned.m16n8k16.row.col.f32.bf16.bf16.f32 "
        "{%0,%1,%2,%3},{%4,%5,%6,%7},{%8,%9},{%0,%1,%2,%3};"
        : "+f"(c[0]), "+f"(c[1]), "+f"(c[2]), "+f"(c[3])
        : "r"(a0), "r"(a1), "r"(a2), "r"(a3), "r"(b0), "r"(b1));
}
__device__ __forceinline__ float gelu_f(float x){
    float z = 0.7978845608028654f * (x + 0.044715f * x*x*x);
    float ee = __expf(-2.f * fabsf(z));
    float th = copysignf((1.f - ee) / (1.f + ee), z);
    return 0.5f * x * (1.f + th);
}
__device__ __forceinline__ void packA_elem(const float* __restrict__ src,
                                           uint32_t* __restrict__ h, uint32_t* __restrict__ l,
                                           int idx, int K){
    const int Kh = K >> 1;
    const int m = idx / Kh, kp = idx - m * Kh;
    split2(src[(size_t)m*K + 2*kp], src[(size_t)m*K + 2*kp + 1], h[idx], l[idx]);
}
__device__ __forceinline__ void packW_elem(const float* __restrict__ src,
                                           uint32_t* __restrict__ h, uint32_t* __restrict__ l,
                                           int idx, int N){
    const int kp = idx / N, n = idx - kp * N;
    split2(src[(size_t)(2*kp)*N + n], src[(size_t)(2*kp+1)*N + n], h[idx], l[idx]);
}
__device__ __forceinline__ void packWpad_elem(const float* __restrict__ src,
                                              uint32_t* __restrict__ h, uint32_t* __restrict__ l,
                                              int idx, int Ns, int Nd){
    const int kp = idx / Nd, n = idx - kp * Nd;
    const float v0 = (n < Ns) ? src[(size_t)(2*kp)*Ns + n] : 0.f;
    const float v1 = (n < Ns) ? src[(size_t)(2*kp+1)*Ns + n] : 0.f;
    split2(v0, v1, h[idx], l[idx]);
}

// ---------- setup GEMM core ----------
__device__ void gemm_dev(const uint32_t* __restrict__ Ah, const uint32_t* __restrict__ Al,
                         const uint32_t* __restrict__ Wh, const uint32_t* __restrict__ Wl,
                         float* __restrict__ C, const float* __restrict__ bias,
                         int N, int K, int epi, int bx, int by, uint32_t* smem, const float* Af32)
{
    uint32_t* sAh = smem;
    uint32_t* sAl = sAh + 2304;
    uint32_t* sBh = sAl + 2304;
    uint32_t* sBl = sBh + 1152;
    const int tid = threadIdx.x;
    const int nBase = bx * 64, rowBase = by * 64;
    const int Kh = K >> 1;
    const int warp = tid >> 5, lane = tid & 31;
    const int wm = (warp & 3) * 16, wn = (warp >> 2) * 32;
    const int g = lane >> 2, tg = lane & 3;
    float acc[4][4];
#pragma unroll
    for (int t = 0; t < 4; t++){ acc[t][0]=acc[t][1]=acc[t][2]=acc[t][3]=0.f; }

    for (int kk = 0; kk < K; kk += 32){
        const int kpg = kk >> 1;
#pragma unroll
        for (int i = 0; i < 4; i++){
            int idx = tid + i * 256;
            int m = idx >> 4, kp = idx & 15;
            if (Af32){
                const float2 av = *reinterpret_cast<const float2*>(
                    &Af32[(size_t)(rowBase + m) * K + (kpg + kp) * 2]);
                split2(av.x, av.y, sAh[m*36+kp], sAl[m*36+kp]);
            } else {
                sAh[m*36+kp] = Ah[(size_t)(rowBase + m) * Kh + kpg + kp];
                sAl[m*36+kp] = Al[(size_t)(rowBase + m) * Kh + kpg + kp];
            }
            int kb = idx >> 6, n = idx & 63;
            sBh[kb*72+n] = Wh[(size_t)(kpg + kb) * N + nBase + n];
            sBl[kb*72+n] = Wl[(size_t)(kpg + kb) * N + nBase + n];
        }
        __syncthreads();
#pragma unroll
        for (int s = 0; s < 2; s++){
            const int kb = s * 8;
            uint32_t ah0 = sAh[(wm+g)*36+kb+tg],   ah1 = sAh[(wm+8+g)*36+kb+tg];
            uint32_t ah2 = sAh[(wm+g)*36+kb+4+tg], ah3 = sAh[(wm+8+g)*36+kb+4+tg];
            uint32_t al0 = sAl[(wm+g)*36+kb+tg],   al1 = sAl[(wm+8+g)*36+kb+tg];
            uint32_t al2 = sAl[(wm+g)*36+kb+4+tg], al3 = sAl[(wm+8+g)*36+kb+4+tg];
#pragma unroll
            for (int t = 0; t < 4; t++){
                const int n = wn + t * 8 + g;
                uint32_t bh0 = sBh[(kb+tg)*72+n], bh1 = sBh[(kb+4+tg)*72+n];
                uint32_t bl0 = sBl[(kb+tg)*72+n], bl1 = sBl[(kb+4+tg)*72+n];
                mma16816(acc[t], ah0, ah1, ah2, ah3, bh0, bh1);
                mma16816(acc[t], ah0, ah1, ah2, ah3, bl0, bl1);
                mma16816(acc[t], al0, al1, al2, al3, bh0, bh1);
            }
        }
        __syncthreads();
    }
    const int r0 = rowBase + wm + g;
#pragma unroll
    for (int t = 0; t < 4; t++){
        const int c = nBase + wn + t * 8 + tg * 2;
#pragma unroll
        for (int hr = 0; hr < 2; hr++){
            const int r = r0 + hr * 8;
            const float v0 = acc[t][hr*2+0], v1 = acc[t][hr*2+1];
            if (epi == 0){
                C[(size_t)r*N + c]   = v0 + (bias ? bias[c]   : 0.f);
                C[(size_t)r*N + c+1] = v1 + (bias ? bias[c+1] : 0.f);
            } else if (epi == 1){
                const int b = r >> 6, srow = r & 63, h = c >> 6, d = c & 63;
                C[((b*HEADS+h)*HD + d  )*SS + srow] = v0 + bias[c];
                C[((b*HEADS+h)*HD + d+1)*SS + srow] = v1 + bias[c+1];
            } else {
                const int b = r >> 6, srow = r & 63, h = c >> 6, d = c & 63;
                C[((b*HEADS+h)*SS + srow)*HD + d  ] = v0 + bias[c];
                C[((b*HEADS+h)*SS + srow)*HD + d+1] = v1 + bias[c+1];
            }
        }
    }
}

// ---------- setup kernels ----------
__global__ void setup_a(const float* __restrict__ x,  const float* __restrict__ Wf,
                        const float* __restrict__ Wk, const float* __restrict__ Wv,
                        const float* __restrict__ Wq, const float* __restrict__ Wqp,
                        const float* __restrict__ Wo, const float* __restrict__ Ws1,
                        const float* __restrict__ Wout,
                        const float* __restrict__ bqp, const float* __restrict__ bq,
                        const float* __restrict__ bo,  const float* __restrict__ bs1,
                        const float* __restrict__ start_trace, const float* __restrict__ start_state,
                        const int* __restrict__ idx_lo, const int* __restrict__ idx_ro,
                        const float* __restrict__ decay_a, const float* __restrict__ decay_o)
{
    int blk = blockIdx.x;
    const int tid = threadIdx.x;
    if (blk < 2){
        const int i = blk*256 + tid;
        const float ra = __expf(-fminf(fmaxf(decay_a[i], 0.f), 15.f));
        const float ro = __expf(-fminf(fmaxf(decay_o[i], 0.f), 15.f));
        g_rA[i] = ra; g_rO[i] = ro;
        float bA = 0.f, bO = 1.f;
        for (int t = 0; t < TT; t++){
            bA = ra * bA + 1.f;
            bO = ro * bO + 1.f;
            g_cA[t*NSYNC + i] = rsqrtf(bA);
            g_cO[t*NSYNC + i] = rsqrtf(bO);
        }
        return;
    }
    blk -= 2;
    if (blk < 64){
        const int col = blk*8 + (tid >> 5), lane = tid & 31;
        float acc = 0.f;
#pragma unroll 16
        for (int i = 0; i < 16; i++){
            const int k = lane + i*32;
            acc += bqp[k] * Wq[(size_t)k*DATTN + col];
        }
#pragma unroll
        for (int off = 16; off; off >>= 1) acc += __shfl_xor_sync(0xffffffffu, acc, off);
        if (lane == 0) g_bq2[col] = acc + bq[col];
        return;
    }
    blk -= 64;
    if (blk < 512){
        const int col = blk*8 + (tid >> 5), lane = tid & 31;
        float acc = 0.f;
#pragma unroll 16
        for (int i = 0; i < 16; i++){
            const int k = lane + i*32;
            acc += bo[k] * Ws1[(size_t)k*D2 + col];
        }
#pragma unroll
        for (int off = 16; off; off >>= 1) acc += __shfl_xor_sync(0xffffffffu, acc, off);
        if (lane == 0) g_bs1c[col] = acc + bs1[col];
        return;
    }
    blk -= 512;
    if (blk < 512){
        const int idx = blk*256 + tid;
        const int b = idx / DMODEL, d = idx - b * DMODEL;
        const float s0 = start_state[d];
        g_act[idx] = s0;
        if (!(d & 1)){
            uint32_t h, l; split2(s0, start_state[d+1], h, l);
            const int kp = (DATTN + d) >> 1;
            g_pA_h[b*(DPRE/2) + kp] = h; g_pA_l[b*(DPRE/2) + kp] = l;
        }
#pragma unroll
        for (int m = 0; m < MP; m++)
            g_trace[(size_t)idx * MP + m] = (m < MM) ? start_trace[d*MM + m] : 0.f;
        if (d < NSYNC){
            g_aA[0][b*NSYNC + d] = 0.f;
            g_aO[b*NSYNC + d] = start_state[idx_lo[d]] * start_state[idx_ro[d]];
        }
        return;
    }
    blk -= 512;
    if (blk < 4096){ packA_elem(x, g_xp_h, g_xp_l, blk*256 + tid, DIN); return; }
    blk -= 4096;
    if (blk < 512){ packW_elem(Wf, g_Wf_h, g_Wf_l, blk*256 + tid, DATTN); return; }
    blk -= 512;
    if (blk < 512){ packW_elem(Wk, g_Wk_h, g_Wk_l, blk*256 + tid, DATTN); return; }
    blk -= 512;
    if (blk < 512){ packW_elem(Wv, g_Wv_h, g_Wv_l, blk*256 + tid, DATTN); return; }
    blk -= 512;
    if (blk < 512){ packW_elem(Wq, g_Wq_h, g_Wq_l, blk*256 + tid, DATTN); return; }
    blk -= 512;
    if (blk < 512){ packA_elem(Wqp, g_WqpA_h, g_WqpA_l, blk*256 + tid, DATTN); return; }
    blk -= 512;
    if (blk < 512){ packA_elem(Wo, g_WoA_h, g_WoA_l, blk*256 + tid, DATTN); return; }
    blk -= 512;
    if (blk < 4096){ packW_elem(Ws1, g_Ws1t_h, g_Ws1t_l, blk*256 + tid, D2); return; }
    blk -= 4096;
    packWpad_elem(Wout, g_WoutP_h, g_WoutP_l, blk*256 + tid, OUT_N, OUT_P);
}
__global__ __launch_bounds__(256) void setup_g1(const float* __restrict__ bf)
{
    __shared__ uint32_t smem[6912];
    const int c = blockIdx.x;
    if (c < 512)      gemm_dev(g_xp_h, g_xp_l, g_Wf_h, g_Wf_l, g_kv, bf, DATTN, DIN, 0, c & 7, c >> 3, smem, (const float*)0);
    else if (c < 576){ const int c2 = c - 512;
                      gemm_dev(g_WqpA_h, g_WqpA_l, g_Wq_h, g_Wq_l, g_Wqpq, (const float*)0, DATTN, DATTN, 0, c2 & 7, c2 >> 3, smem, (const float*)0); }
    else             { const int c2 = c - 576;
                      gemm_dev(g_WoA_h, g_WoA_l, g_Ws1t_h, g_Ws1t_l, g_WbigTop, (const float*)0, D2, DATTN, 0, c2 & 63, c2 >> 6, smem, (const float*)0); }
}
__global__ __launch_bounds__(256) void setup_b(const float* __restrict__ bk,
                                               const float* __restrict__ bv,
                                               const float* __restrict__ Ws1)
{
    __shared__ uint32_t smem[6912];
    int c = blockIdx.x;
    if (c < 512){ gemm_dev((const uint32_t*)0, (const uint32_t*)0, g_Wk_h, g_Wk_l, g_Kt, bk, DATTN, DATTN, 1, c & 7, c >> 3, smem, g_kv); return; }
    c -= 512;
    if (c < 512){ gemm_dev((const uint32_t*)0, (const uint32_t*)0, g_Wv_h, g_Wv_l, g_V, bv, DATTN, DATTN, 2, c & 7, c >> 3, smem, g_kv); return; }
    c -= 512;
    {   const int idx = c*256 + threadIdx.x;
        const int kp = idx / D2, n = idx - kp*D2;
        float v0, v1;
        if (kp < DATTN/2){ v0 = g_WbigTop[(size_t)(2*kp)*D2 + n]; v1 = g_WbigTop[(size_t)(2*kp+1)*D2 + n]; }
        else             { v0 = Ws1[(size_t)(2*kp)*D2 + n];       v1 = Ws1[(size_t)(2*kp+1)*D2 + n]; }
        split2(v0, v1, g_Wbig_h[idx], g_Wbig_l[idx]); }
}

// ---------- entropy ----------
__device__ void dev_entropy(int b, int tid, float* sm, const float* __restrict__ bout,
                            float* __restrict__ out, int tw)
{
    float* pbuf = sm;
    float* r0 = pbuf + 1000;
    float* r1 = r0 + 8;
    float* bc = r1 + 8;
    float mx = -1e30f;
    for (int o = tid; o < OUT_N; o += 256){
        float p = bout[o];
#pragma unroll
        for (int z = 0; z < PSPLIT; z++) p += g_ppart[(z*BB + b)*OUT_P + o];
        pbuf[o] = p;
        out[((size_t)(b*OUT_N + o))*TT + tw] = p;
        mx = fmaxf(mx, p);
    }
#pragma unroll
    for (int off = 16; off; off >>= 1) mx = fmaxf(mx, __shfl_xor_sync(0xffffffffu, mx, off));
    if ((tid & 31) == 0) r0[tid >> 5] = mx;
    __syncthreads();
    if (tid == 0){
        float m = r0[0];
        for (int w = 1; w < 8; w++) m = fmaxf(m, r0[w]);
        bc[0] = m;
    }
    __syncthreads();
    mx = bc[0];
    float s0 = 0.f, s1 = 0.f;
    for (int o = tid; o < OUT_N; o += 256){
        const float u = pbuf[o] - mx;
        const float e = __expf(u);
        s0 += e; s1 += u * e;
    }
#pragma unroll
    for (int off = 16; off; off >>= 1){
        s0 += __shfl_xor_sync(0xffffffffu, s0, off);
        s1 += __shfl_xor_sync(0xffffffffu, s1, off);
    }
    if ((tid & 31) == 0){ r0[tid>>5] = s0; r1[tid>>5] = s1; }
    __syncthreads();
    if (tid == 0){
        float t0 = 0.f, t1 = 0.f;
        for (int w = 0; w < 8; w++){ t0 += r0[w]; t1 += r1[w]; }
        const float ne = -(t1 / t0 - logf(t0)) / logf((float)OUT_N);
        out[CERT_OFF + (size_t)(b*2 + 0)*TT + tw] = ne;
        out[CERT_OFF + (size_t)(b*2 + 1)*TT + tw] = 1.f - ne;
    }
}

// ---------- syncO for one batch (256 threads), tick tw ----------
__device__ void dev_syncO(int b, int tid, float* sAct, int tw,
                          const int* __restrict__ idx_lo, const int* __restrict__ idx_ro)
{
#pragma unroll
    for (int k = 0; k < 8; k++) sAct[tid + k*256] = g_act[b*DMODEL + tid + k*256];
    __syncthreads();
    const int i0 = tid * 2;
    float v[2];
#pragma unroll
    for (int j = 0; j < 2; j++){
        const int i = i0 + j;
        const float pairing = sAct[idx_lo[i]] * sAct[idx_ro[i]];
        const float a = g_rO[i] * g_aO[b*NSYNC+i] + pairing;
        g_aO[b*NSYNC+i] = a;
        v[j] = a * g_cO[tw*NSYNC + i];
        g_syO[b*NSYNC+i] = v[j];
    }
    uint32_t h, l; split2(v[0], v[1], h, l);
    g_syO_h[b*(NSYNC/2) + tid] = h;
    g_syO_l[b*(NSYNC/2) + tid] = l;
}

// ---------- pred: split-K MMA, z in {0,1}, 128 pairs each ----------
__device__ void dev_pred(int nx, int z, uint32_t* smem)
{
    uint32_t* sAh = smem;
    uint32_t* sAl = sAh + 2304;
    uint32_t* sBh = sAl + 2304;
    uint32_t* sBl = sBh + 1152;
    const int tid = threadIdx.x;
    const int nBase = nx * 64;
    const int warp = tid >> 5, lane = tid & 31;
    const int wm = (warp & 3) * 16, wn = (warp >> 2) * 32;
    const int g = lane >> 2, tg = lane & 3;
    float acc[4][4];
#pragma unroll
    for (int t = 0; t < 4; t++){ acc[t][0]=acc[t][1]=acc[t][2]=acc[t][3]=0.f; }

    for (int kk = 0; kk < 256; kk += 32){
        const int kpg = z * 128 + (kk >> 1);
#pragma unroll
        for (int i = 0; i < 4; i++){
            int idx = tid + i * 256;
            int m = idx >> 4, kp = idx & 15;
            sAh[m*36+kp] = g_syO_h[m*(NSYNC/2) + kpg + kp];
            sAl[m*36+kp] = g_syO_l[m*(NSYNC/2) + kpg + kp];
            int kb = idx >> 6, n = idx & 63;
            sBh[kb*72+n] = g_WoutP_h[(size_t)(kpg + kb) * OUT_P + nBase + n];
            sBl[kb*72+n] = g_WoutP_l[(size_t)(kpg + kb) * OUT_P + nBase + n];
        }
        __syncthreads();
#pragma unroll
        for (int s = 0; s < 2; s++){
            const int kb = s * 8;
            uint32_t ah0 = sAh[(wm+g)*36+kb+tg],   ah1 = sAh[(wm+8+g)*36+kb+tg];
            uint32_t ah2 = sAh[(wm+g)*36+kb+4+tg], ah3 = sAh[(wm+8+g)*36+kb+4+tg];
            uint32_t al0 = sAl[(wm+g)*36+kb+tg],   al1 = sAl[(wm+8+g)*36+kb+tg];
            uint32_t al2 = sAl[(wm+g)*36+kb+4+tg], al3 = sAl[(wm+8+g)*36+kb+4+tg];
#pragma unroll
            for (int t = 0; t < 4; t++){
                const int n = wn + t * 8 + g;
                uint32_t bh0 = sBh[(kb+tg)*72+n], bh1 = sBh[(kb+4+tg)*72+n];
                uint32_t bl0 = sBl[(kb+tg)*72+n], bl1 = sBl[(kb+4+tg)*72+n];
                mma16816(acc[t], ah0, ah1, ah2, ah3, bh0, bh1);
                mma16816(acc[t], ah0, ah1, ah2, ah3, bl0, bl1);
                mma16816(acc[t], al0, al1, al2, al3, bh0, bh1);
            }
        }
        __syncthreads();
    }
    const int r0 = wm + g;
#pragma unroll
    for (int t = 0; t < 4; t++){
        const int c = nBase + wn + t * 8 + tg * 2;
#pragma unroll
        for (int hr = 0; hr < 2; hr++){
            const int r = r0 + hr * 8;
            float* p = &g_ppart[((size_t)(z*BB + r)) * OUT_P + c];
            p[0] = acc[t][hr*2+0]; p[1] = acc[t][hr*2+1];
        }
    }
}

// ---------- big GEMM slice (weights streamed with __ldcs: evict-first) ----------
__device__ void dev_big(int nx, int zout, int kp0, int nst, uint32_t* sm)
{
    uint32_t* sAh = sm;
    uint32_t* sAl = sAh + 1280;
    uint32_t* sBh = sAl + 1280;
    uint32_t* sBl = sBh + 2112;
    const int tid = threadIdx.x;
    const int nBase = nx * 128;
    const int warp = tid >> 5, lane = tid & 31;
    const int wm = (warp & 3) * 16, wn = (warp >> 2) * 64;
    const int g = lane >> 2, tg = lane & 3;
    const int arow = tid >> 2, apg = (tid & 3) << 2;
    const int brow = tid >> 5, bc = lane << 2;

    float acc[8][4];
#pragma unroll
    for (int t = 0; t < 8; t++){ acc[t][0]=acc[t][1]=acc[t][2]=acc[t][3]=0.f; }

    uint4 pAh, pAl, pBh0, pBl0, pBh1, pBl1;
    {
        const int kpg = kp0;
        pAh = *reinterpret_cast<const uint4*>(&g_pA_h[arow*(DPRE/2) + kpg + apg]);
        pAl = *reinterpret_cast<const uint4*>(&g_pA_l[arow*(DPRE/2) + kpg + apg]);
        pBh0 = __ldcs(reinterpret_cast<const uint4*>(&g_Wbig_h[(size_t)(kpg+brow  )*D2 + nBase + bc]));
        pBl0 = __ldcs(reinterpret_cast<const uint4*>(&g_Wbig_l[(size_t)(kpg+brow  )*D2 + nBase + bc]));
        pBh1 = __ldcs(reinterpret_cast<const uint4*>(&g_Wbig_h[(size_t)(kpg+brow+8)*D2 + nBase + bc]));
        pBl1 = __ldcs(reinterpret_cast<const uint4*>(&g_Wbig_l[(size_t)(kpg+brow+8)*D2 + nBase + bc]));
    }
    *reinterpret_cast<uint4*>(&sAh[arow*20 + apg]) = pAh;
    *reinterpret_cast<uint4*>(&sAl[arow*20 + apg]) = pAl;
    *reinterpret_cast<uint4*>(&sBh[brow*132 + bc]) = pBh0;
    *reinterpret_cast<uint4*>(&sBl[brow*132 + bc]) = pBl0;
    *reinterpret_cast<uint4*>(&sBh[(brow+8)*132 + bc]) = pBh1;
    *reinterpret_cast<uint4*>(&sBl[(brow+8)*132 + bc]) = pBl1;
    __syncthreads();

    for (int st = 0; st < nst; st++){
        if (st + 1 < nst){
            const int kpg = kp0 + (st+1) * 16;
            pAh = *reinterpret_cast<const uint4*>(&g_pA_h[arow*(DPRE/2) + kpg + apg]);
            pAl = *reinterpret_cast<const uint4*>(&g_pA_l[arow*(DPRE/2) + kpg + apg]);
            pBh0 = __ldcs(reinterpret_cast<const uint4*>(&g_Wbig_h[(size_t)(kpg+brow  )*D2 + nBase + bc]));
            pBl0 = __ldcs(reinterpret_cast<const uint4*>(&g_Wbig_l[(size_t)(kpg+brow  )*D2 + nBase + bc]));
            pBh1 = __ldcs(reinterpret_cast<const uint4*>(&g_Wbig_h[(size_t)(kpg+brow+8)*D2 + nBase + bc]));
            pBl1 = __ldcs(reinterpret_cast<const uint4*>(&g_Wbig_l[(size_t)(kpg+brow+8)*D2 + nBase + bc]));
        }
#pragma unroll
        for (int s = 0; s < 2; s++){
            const int kb = s * 8;
            const uint32_t ah0 = sAh[(wm+g)*20 + kb+tg],   ah1 = sAh[(wm+8+g)*20 + kb+tg];
            const uint32_t ah2 = sAh[(wm+g)*20 + kb+4+tg], ah3 = sAh[(wm+8+g)*20 + kb+4+tg];
            const uint32_t al0 = sAl[(wm+g)*20 + kb+tg],   al1 = sAl[(wm+8+g)*20 + kb+tg];
            const uint32_t al2 = sAl[(wm+g)*20 + kb+4+tg], al3 = sAl[(wm+8+g)*20 + kb+4+tg];
#pragma unroll
            for (int t = 0; t < 8; t++){
                const int n = wn + t * 8 + g;
                const uint32_t bh0 = sBh[(kb+tg)*132 + n], bh1 = sBh[(kb+4+tg)*132 + n];
                const uint32_t bl0 = sBl[(kb+tg)*132 + n], bl1 = sBl[(kb+4+tg)*132 + n];
                mma16816(acc[t], ah0, ah1, ah2, ah3, bh0, bh1);
                mma16816(acc[t], ah0, ah1, ah2, ah3, bl0, bl1);
                mma16816(acc[t], al0, al1, al2, al3, bh0, bh1);
            }
        }
        if (st + 1 < nst){
            __syncthreads();
            *reinterpret_cast<uint4*>(&sAh[arow*20 + apg]) = pAh;
            *reinterpret_cast<uint4*>(&sAl[arow*20 + apg]) = pAl;
            *reinterpret_cast<uint4*>(&sBh[brow*132 + bc]) = pBh0;
            *reinterpret_cast<uint4*>(&sBl[brow*132 + bc]) = pBl0;
            *reinterpret_cast<uint4*>(&sBh[(brow+8)*132 + bc]) = pBh1;
            *reinterpret_cast<uint4*>(&sBl[(brow+8)*132 + bc]) = pBl1;
            __syncthreads();
        }
    }
    const int r0 = wm + g;
#pragma unroll
    for (int t = 0; t < 8; t++){
        const int c = nBase + wn + t * 8 + tg * 2;
#pragma unroll
        for (int hr = 0; hr < 2; hr++){
            const int r = r0 + hr * 8;
            float* p = &g_hpart[((size_t)(zout*64 + r)) * D2 + c];
            p[0] = acc[t][hr*2+0]; p[1] = acc[t][hr*2+1];
        }
    }
}

// ---------- K1: 128 blocks, single wave.
// block = attnq(h=blk>>4, bg=blk&15); even blocks prepend syncO(t-1) for b=blk>>1.
__global__ __launch_bounds__(256) void k1_kernel(const int* __restrict__ idx_la,
                                                 const int* __restrict__ idx_ra,
                                                 const int* __restrict__ idx_lo,
                                                 const int* __restrict__ idx_ro,
                                                 int tick)
{
    __shared__ __align__(16) uint32_t SMu[6928];
    const int tid = threadIdx.x;
    float* SM = (float*)SMu;
    float* sA  = SM;              // 4 x 512
    float* sW  = SM + 2048;       // 64 x 68 transposed (also syncO scratch)
    float* qs  = SM + 6400;
    float* ws  = qs + 256;
    float* red = ws + 256;

    if (tick > 0 && !(blockIdx.x & 1)){
        dev_syncO(blockIdx.x >> 1, tid, sW, tick - 1, idx_lo, idx_ro);
        __syncthreads();
    }

    const int h = blockIdx.x >> 4, bg = blockIdx.x & 15;
    const int grp = tid >> 6, t = tid & 63;
    const int b = bg * 4 + grp;
    const int buf = tick & 1, nbuf = buf ^ 1;
    const float* cA = g_cA + tick * NSYNC;

#pragma unroll
    for (int i = 0; i < 8; i++){
        const int idx = tid + i * 256;
        const int bb = bg*4 + (idx >> 9), ii = idx & 511;
        const float pairing = g_act[bb*DMODEL + idx_la[ii]] * g_act[bb*DMODEL + idx_ra[ii]];
        const float a = g_rA[ii] * g_aA[buf][bb*NSYNC+ii] + pairing;
        sA[idx] = a * cA[ii];
        if (h == 0) g_aA[nbuf][bb*NSYNC+ii] = a;
    }

    const int col = h * HD + t;
    float a0 = 0.f, a1 = 0.f, a2 = 0.f, a3 = 0.f;
    for (int ch = 0; ch < 8; ch++){
        const int k0 = ch * 64;
        __syncthreads();
#pragma unroll
        for (int i = 0; i < 4; i++){
            const int idx = tid + i * 256;
            const int r = idx >> 4, c4 = (idx & 15) << 2;
            const float4 w = *reinterpret_cast<const float4*>(
                &g_Wqpq[(size_t)(k0 + r) * DATTN + h * HD + c4]);
            sW[(c4+0)*68 + r] = w.x;
            sW[(c4+1)*68 + r] = w.y;
            sW[(c4+2)*68 + r] = w.z;
            sW[(c4+3)*68 + r] = w.w;
        }
        __syncthreads();
        const float* ap = sA + grp * 512 + k0;
        const float4* wp = reinterpret_cast<const float4*>(sW + t * 68);
#pragma unroll
        for (int k = 0; k < 64; k += 4){
            const float4 w = wp[k >> 2];
            a0 += ap[k+0] * w.x;
            a1 += ap[k+1] * w.y;
            a2 += ap[k+2] * w.z;
            a3 += ap[k+3] * w.w;
        }
    }
    __syncthreads();
    qs[grp*64 + t] = (a0 + a1) + (a2 + a3) + g_bq2[col];
    __syncthreads();

    const float* ktp = &g_Kt[((b*HEADS + h)*HD) * SS + t];
    float sc = 0.f;
#pragma unroll
    for (int d = 0; d < HD; d++) sc += qs[grp*64 + d] * ktp[d*SS];
    sc *= 0.125f;

    float mx = sc;
#pragma unroll
    for (int off = 16; off; off >>= 1) mx = fmaxf(mx, __shfl_xor_sync(0xffffffffu, mx, off));
    if ((t & 31) == 0) red[grp*4 + (t >> 5)] = mx;
    __syncthreads();
    mx = fmaxf(red[grp*4 + 0], red[grp*4 + 1]);
    const float e = __expf(sc - mx);
    float smv = e;
#pragma unroll
    for (int off = 16; off; off >>= 1) smv += __shfl_xor_sync(0xffffffffu, smv, off);
    if ((t & 31) == 0) red[grp*4 + 2 + (t >> 5)] = smv;
    __syncthreads();
    smv = red[grp*4 + 2] + red[grp*4 + 3];
    ws[grp*64 + t] = e / smv;
    __syncthreads();

    const float* vp = &g_V[((b*HEADS + h)*SS) * HD + t];
    float ao = 0.f;
#pragma unroll
    for (int s = 0; s < SS; s++) ao += ws[grp*64 + s] * vp[s*HD];

    const float an = __shfl_down_sync(0xffffffffu, ao, 1);
    if (!(t & 1)){
        uint32_t hi, lo; split2(ao, an, hi, lo);
        const int kp = (h*HD + t) >> 1;
        g_pA_h[b*(DPRE/2) + kp] = hi; g_pA_l[b*(DPRE/2) + kp] = lo;
    }
}

// ---------- K2: 128 blocks single wave. [0,96): big, [96,128): pred(t-1)
__global__ __launch_bounds__(256) void k2_kernel(int tick)
{
    __shared__ __align__(16) uint32_t sm[6928];
    if (blockIdx.x >= 96){
        if (tick > 0){
            const int r = blockIdx.x - 96;
            dev_pred(r & 15, r >> 4, sm);
        }
        return;
    }
    const int nx = blockIdx.x & 31, z = blockIdx.x >> 5;
    const int kp0 = (z == 0) ? 0 : (z == 1 ? 432 : 864);
    const int nst = (z == 2) ? 26 : 27;
    dev_big(nx, z, kp0, nst, sm);
}

// ---------- K3: glu(t) | entropy(t-1) ----------
__global__ __launch_bounds__(256) void glu_ent_kernel(const float* __restrict__ ln_g,
                                                      const float* __restrict__ ln_b,
                                                      const float* __restrict__ bout,
                                                      float* __restrict__ out, int tick)
{
    __shared__ float SM[2080];
    const int tid = threadIdx.x;
    if (blockIdx.x >= 64){
        if (tick > 0) dev_entropy(blockIdx.x - 64, tid, SM, bout, out, tick - 1);
        return;
    }
    float* gbuf = SM;
    float* rs   = SM + DMODEL;
    float* ms   = rs + 16;
    const int b = blockIdx.x;
    float s = 0.f, s2 = 0.f;
    for (int j = tid; j < DMODEL; j += 256){
        float h1 = g_bs1c[j], h2 = g_bs1c[j + DMODEL];
#pragma unroll
        for (int z = 0; z < HSPLIT; z++){
            h1 += g_hpart[(size_t)(z*64 + b)*D2 + j];
            h2 += g_hpart[(size_t)(z*64 + b)*D2 + j + DMODEL];
        }
        const float gv = h1 / (1.f + __expf(-h2));
        gbuf[j] = gv; s += gv; s2 += gv*gv;
    }
#pragma unroll
    for (int off = 16; off; off >>= 1){
        s  += __shfl_xor_sync(0xffffffffu, s,  off);
        s2 += __shfl_xor_sync(0xffffffffu, s2, off);
    }
    if ((tid & 31) == 0){ rs[tid>>5] = s; rs[8 + (tid>>5)] = s2; }
    __syncthreads();
    if (tid == 0){
        float ts = 0.f, ts2 = 0.f;
        for (int w = 0; w < 8; w++){ ts += rs[w]; ts2 += rs[8+w]; }
        const float mu = ts / (float)DMODEL;
        ms[0] = mu; ms[1] = rsqrtf(ts2 / (float)DMODEL - mu*mu + 1e-5f);
    }
    __syncthreads();
    const int slot = tick % MM;
    const float mu = ms[0], inv = ms[1];
    for (int j = tid; j < DMODEL; j += 256)
        g_trace[((size_t)(b*DMODEL + j)) * MP + slot] = (gbuf[j] - mu) * inv * ln_g[j] + ln_b[j];
}

// ---------- K4: nlm ----------
__global__ __launch_bounds__(256) void nlm_kernel(const float* __restrict__ nw1,
                                                  const float* __restrict__ nb1,
                                                  const float* __restrict__ nw2,
                                                  const float* __restrict__ nb2, int tick)
{
    __shared__ float w1s[3200], b1s[128], w2s[128], sAct[256];
    const int cta = blockIdx.x, tid = threadIdx.x;
    const int d0 = cta * 16;
    const int b = tid & 63, dsub = tid >> 6;
    const int o = (tick + 1) % MM;

    for (int p = 0; p < 4; p++){
        const int dbase = d0 + p * 4;
        __syncthreads();
        {
            float4* dst = reinterpret_cast<float4*>(w1s);
            const float4* src = reinterpret_cast<const float4*>(nw1 + (size_t)dbase*800);
            for (int i = tid; i < 800; i += 256) dst[i] = src[i];
        }
        if (tid < 128){ b1s[tid] = nb1[dbase*32 + tid]; w2s[tid] = nw2[dbase*32 + tid]; }
        __syncthreads();

        const int d = dbase + dsub;
        float tr[MM];
        const float* tp = &g_trace[((size_t)(b*DMODEL + d)) * MP];
#pragma unroll
        for (int m = 0; m < MM; m++){ int s = o + m; if (s >= MM) s -= MM; tr[m] = tp[s]; }

        const float* w1p = w1s + dsub * 800;
        float ov = 0.f;
#pragma unroll
        for (int h = 0; h < 32; h += 4){
            float4 s4 = *reinterpret_cast<const float4*>(&b1s[dsub*32 + h]);
#pragma unroll
            for (int m = 0; m < MM; m++){
                const float4 w = *reinterpret_cast<const float4*>(&w1p[m*32 + h]);
                s4.x += tr[m]*w.x; s4.y += tr[m]*w.y; s4.z += tr[m]*w.z; s4.w += tr[m]*w.w;
            }
            const float4 w2v = *reinterpret_cast<const float4*>(&w2s[dsub*32 + h]);
            ov += gelu_f(s4.x)*w2v.x + gelu_f(s4.y)*w2v.y + gelu_f(s4.z)*w2v.z + gelu_f(s4.w)*w2v.w;
        }
        const float a = ov + nb2[d];
        g_act[b*DMODEL + d] = a;
        sAct[dsub*64 + b] = a;
        __syncthreads();
        if (tid < 128){
            const int pi = tid >> 6, bb = tid & 63;
            const float v0 = sAct[(2*pi)*64 + bb], v1 = sAct[(2*pi+1)*64 + bb];
            uint32_t hi, lo; split2(v0, v1, hi, lo);
            const int kp = (DATTN + dbase + 2*pi) >> 1;
            g_pA_h[bb*(DPRE/2) + kp] = hi; g_pA_l[bb*(DPRE/2) + kp] = lo;
        }
    }
}

// ---------- tails ----------
__global__ __launch_bounds__(256) void tail_syncO(const int* __restrict__ idx_lo,
                                                  const int* __restrict__ idx_ro)
{
    __shared__ float sAct[DMODEL];
    dev_syncO(blockIdx.x, threadIdx.x, sAct, TT - 1, idx_lo, idx_ro);
}
__global__ __launch_bounds__(256) void predtail_kernel()
{
    __shared__ __align__(16) uint32_t smem[6928];
    dev_pred((int)blockIdx.x, (int)blockIdx.y, smem);
}
__global__ __launch_bounds__(256) void fin_kernel(const float* __restrict__ bout,
                                                  float* __restrict__ out)
{
    __shared__ float SM[1024];
    const int blk = blockIdx.x, tid = threadIdx.x;
    if (blk < 64){ dev_entropy(blk, tid, SM, bout, out, TT - 1); return; }
    const int i = (blk - 64) * 256 + tid;
    out[SYO_OFF + i] = g_syO[i];
}

// ---------- launch ----------
extern "C" void kernel_launch(void* const* d_in, const int* in_sizes, int n_in,
                              void* d_out, int out_size)
{
    const float* x   = (const float*)d_in[0];
    const float* Wf  = (const float*)d_in[1];
    const float* bf  = (const float*)d_in[2];
    const float* start_trace = (const float*)d_in[3];
    const float* start_state = (const float*)d_in[4];
    const float* decay_a = (const float*)d_in[5];
    const float* decay_o = (const float*)d_in[6];
    const float* Wqp = (const float*)d_in[7];
    const float* bqp = (const float*)d_in[8];
    const float* Wq  = (const float*)d_in[9];
    const float* bq  = (const float*)d_in[10];
    const float* Wk  = (const float*)d_in[11];
    const float* bk  = (const float*)d_in[12];
    const float* Wv  = (const float*)d_in[13];
    const float* bv  = (const float*)d_in[14];
    const float* Wo  = (const float*)d_in[15];
    const float* bo  = (const float*)d_in[16];
    const float* Ws1 = (const float*)d_in[17];
    const float* bs1 = (const float*)d_in[18];
    const float* ln_g = (const float*)d_in[19];
    const float* ln_b = (const float*)d_in[20];
    const float* nw1 = (const float*)d_in[21];
    const float* nb1 = (const float*)d_in[22];
    const float* nw2 = (const float*)d_in[23];
    const float* nb2 = (const float*)d_in[24];
    const float* Wout = (const float*)d_in[25];
    const float* bout = (const float*)d_in[26];
    const int* idx_la = (const int*)d_in[27];
    const int* idx_ra = (const int*)d_in[28];
    const int* idx_lo = (const int*)d_in[29];
    const int* idx_ro = (const int*)d_in[30];
    float* out = (float*)d_out;

    setup_a<<<13378, 256>>>(x, Wf, Wk, Wv, Wq, Wqp, Wo, Ws1, Wout,
                            bqp, bq, bo, bs1, start_trace, start_state, idx_lo, idx_ro,
                            decay_a, decay_o);
    setup_g1<<<1088, 256>>>(bf);
    setup_b<<<21504, 256>>>(bk, bv, Ws1);

    for (int t = 0; t < TT; t++){
        k1_kernel<<<128, 256>>>(idx_la, idx_ra, idx_lo, idx_ro, t);
        k2_kernel<<<128, 256>>>(t);
        glu_ent_kernel<<<128, 256>>>(ln_g, ln_b, bout, out, t);
        nlm_kernel<<<128, 256>>>(nw1, nb1, nw2, nb2, t);
    }
    tail_syncO<<<64, 256>>>(idx_lo, idx_ro);
    predtail_kernel<<<dim3(16, 2), 256>>>();
    fin_kernel<<<192, 256>>>(bout, out);
    (void)in_sizes; (void)n_in; (void)out_size;
}